// round 1
// baseline (speedup 1.0000x reference)
#include <cuda_runtime.h>
#include <math.h>

static constexpr int T_   = 2048;
static constexpr int NH   = 32;
static constexpr int MIX  = 8192;   // KEY + KEY + VAL
static constexpr int KEYD = 2048;   // 16 kv-heads * 128
static constexpr int VALD = 4096;   // 32 heads * 128

// ---- scratch (static __device__ arrays; no runtime allocation) ----
__device__ float g_mixed[T_ * MIX];   // qkv projections (pre-conv)
__device__ float g_acts [T_ * MIX];   // after conv + silu
__device__ float g_xa   [T_ * NH];
__device__ float g_xb   [T_ * NH];
__device__ float g_eg   [T_ * NH];    // exp(g)
__device__ float g_bt   [T_ * NH];    // beta
__device__ float g_qn   [T_ * KEYD];  // l2-normed q * DK^-0.5 (16 kv heads)
__device__ float g_kn   [T_ * KEYD];  // l2-normed k
__device__ float g_o    [T_ * VALD];  // scan output
__device__ float g_gate [T_ * VALD];  // h @ Wg
__device__ float g_og   [T_ * VALD];  // normed+gated o

// =====================================================================
// Generic tiled SGEMM: C[M,N] = A[M,K] @ B[K,N]; all row-major.
// 128x128 block tile, BK=16, 256 threads, 8x8 per-thread (split-tile).
// M and K must be multiples of 128/16 (true here); N is guarded.
// =====================================================================
__global__ __launch_bounds__(256) void sgemm128(
    const float* __restrict__ A, const float* __restrict__ B, float* __restrict__ C,
    int M, int N, int K, int lda, int ldb, int ldc)
{
    __shared__ float As[16][132];   // transposed A tile (+pad)
    __shared__ float Bs[16][128];
    const int tid  = threadIdx.x;
    const int row0 = blockIdx.y * 128;
    const int col0 = blockIdx.x * 128;
    const int arow = tid >> 2;          // 0..63
    const int acol = (tid & 3) << 2;    // 0,4,8,12
    const int brow = tid >> 5;          // 0..7
    const int bcol = (tid & 31) << 2;   // 0..124
    const int tx = tid & 15;
    const int ty = tid >> 4;

    float acc[8][8];
#pragma unroll
    for (int i = 0; i < 8; i++)
#pragma unroll
        for (int j = 0; j < 8; j++) acc[i][j] = 0.f;

    for (int k0 = 0; k0 < K; k0 += 16) {
#pragma unroll
        for (int p = 0; p < 2; p++) {
            int r = arow + p * 64;
            float4 v = *(const float4*)(A + (size_t)(row0 + r) * lda + k0 + acol);
            As[acol + 0][r] = v.x;
            As[acol + 1][r] = v.y;
            As[acol + 2][r] = v.z;
            As[acol + 3][r] = v.w;
        }
#pragma unroll
        for (int p = 0; p < 2; p++) {
            int r  = brow + p * 8;
            int gc = col0 + bcol;
            float4 v = make_float4(0.f, 0.f, 0.f, 0.f);
            const float* bp = B + (size_t)(k0 + r) * ldb;
            if (gc + 3 < N) {
                v = *(const float4*)(bp + gc);
            } else {
                if (gc + 0 < N) v.x = bp[gc + 0];
                if (gc + 1 < N) v.y = bp[gc + 1];
                if (gc + 2 < N) v.z = bp[gc + 2];
            }
            *(float4*)&Bs[r][bcol] = v;
        }
        __syncthreads();
#pragma unroll
        for (int k = 0; k < 16; k++) {
            float a[8], b[8];
            *(float4*)&a[0] = *(const float4*)&As[k][ty * 4];
            *(float4*)&a[4] = *(const float4*)&As[k][64 + ty * 4];
            *(float4*)&b[0] = *(const float4*)&Bs[k][tx * 4];
            *(float4*)&b[4] = *(const float4*)&Bs[k][64 + tx * 4];
#pragma unroll
            for (int i = 0; i < 8; i++)
#pragma unroll
                for (int j = 0; j < 8; j++) acc[i][j] = fmaf(a[i], b[j], acc[i][j]);
        }
        __syncthreads();
    }
#pragma unroll
    for (int i = 0; i < 8; i++) {
        int r = row0 + ((i < 4) ? (ty * 4 + i) : (64 + ty * 4 + (i - 4)));
#pragma unroll
        for (int j = 0; j < 8; j++) {
            int c = col0 + ((j < 4) ? (tx * 4 + j) : (64 + tx * 4 + (j - 4)));
            if (c < N) C[(size_t)r * ldc + c] = acc[i][j];
        }
    }
}

// =====================================================================
// Causal depthwise conv (K=4, no kernel flip — XLA correlation) + SiLU
// =====================================================================
__global__ void conv_silu(const float* __restrict__ mixed,
                          const float* __restrict__ cq,
                          const float* __restrict__ ck,
                          const float* __restrict__ cv,
                          float* __restrict__ acts)
{
    int gid = blockIdx.x * blockDim.x + threadIdx.x;   // T_ * MIX/4
    int t = gid >> 11;             // MIX/4 = 2048 groups per row
    int c = (gid & 2047) << 2;
    const float* wp = (c < 2048) ? (cq + c * 4)
                    : (c < 4096) ? (ck + (c - 2048) * 4)
                                 : (cv + (c - 4096) * 4);
    float4 w0 = *(const float4*)(wp + 0);
    float4 w1 = *(const float4*)(wp + 4);
    float4 w2 = *(const float4*)(wp + 8);
    float4 w3 = *(const float4*)(wp + 12);
    const float* xp = mixed + (size_t)t * MIX + c;
    float4 z  = make_float4(0.f, 0.f, 0.f, 0.f);
    float4 x3 = *(const float4*)xp;
    float4 x2 = (t >= 1) ? *(const float4*)(xp - MIX)     : z;
    float4 x1 = (t >= 2) ? *(const float4*)(xp - 2 * MIX) : z;
    float4 x0 = (t >= 3) ? *(const float4*)(xp - 3 * MIX) : z;
    float4 o;
    o.x = w0.x * x0.x + w0.y * x1.x + w0.z * x2.x + w0.w * x3.x;
    o.y = w1.x * x0.y + w1.y * x1.y + w1.z * x2.y + w1.w * x3.y;
    o.z = w2.x * x0.z + w2.y * x1.z + w2.z * x2.z + w2.w * x3.z;
    o.w = w3.x * x0.w + w3.y * x1.w + w3.z * x2.w + w3.w * x3.w;
    o.x = o.x / (1.f + expf(-o.x));
    o.y = o.y / (1.f + expf(-o.y));
    o.z = o.z / (1.f + expf(-o.z));
    o.w = o.w / (1.f + expf(-o.w));
    *(float4*)(acts + (size_t)t * MIX + c) = o;
}

// =====================================================================
// g = exp(-exp(A_log) * softplus(xa + dt_bias)); beta = sigmoid(xb)
// =====================================================================
__global__ void gate_beta(const float* __restrict__ xa, const float* __restrict__ xb,
                          const float* __restrict__ dtb, const float* __restrict__ Alg,
                          float* __restrict__ eg, float* __restrict__ bt)
{
    int i = blockIdx.x * blockDim.x + threadIdx.x;   // T_*NH
    int h = i & 31;
    float x  = xa[i] + dtb[h];
    float sp = (x <= 20.f) ? log1pf(expf(x)) : x;
    eg[i] = expf(-expf(Alg[h]) * sp);
    bt[i] = 1.f / (1.f + expf(-xb[i]));
}

// =====================================================================
// l2norm over head_dim=128 for q (scaled by 128^-0.5) and k. warp/vec.
// =====================================================================
__global__ void qknorm(const float* __restrict__ acts,
                       float* __restrict__ qn, float* __restrict__ kn)
{
    int wid  = (blockIdx.x * blockDim.x + threadIdx.x) >> 5;  // t*32 + hh*2 + which
    int lane = threadIdx.x & 31;
    int t     = wid >> 5;
    int hh    = (wid >> 1) & 15;
    int which = wid & 1;
    const float* src = acts + (size_t)t * MIX + which * 2048 + hh * 128 + lane * 4;
    float4 x = *(const float4*)src;
    float ss = x.x * x.x + x.y * x.y + x.z * x.z + x.w * x.w;
#pragma unroll
    for (int off = 16; off; off >>= 1) ss += __shfl_xor_sync(0xffffffffu, ss, off);
    float s = rsqrtf(ss + 1e-6f);
    if (which == 0) s *= 0.08838834764831845f;   // DK^-0.5
    float* dst = (which == 0 ? qn : kn) + (size_t)t * 2048 + hh * 128 + lane * 4;
    *(float4*)dst = make_float4(x.x * s, x.y * s, x.z * s, x.w * s);
}

// =====================================================================
// Gated delta-rule scan. Grid (8 dv-tiles, 32 heads), 128 threads.
// Warp w owns dv columns [dvt*16 + w*4, +4); lane owns dk {l, l+32, l+64, l+96}.
// o = q.S_new = (q.S_decayed) + (q.k)*dvv  -> single butterfly phase/step.
// =====================================================================
__global__ __launch_bounds__(128) void gdn_scan(
    const float* __restrict__ qn, const float* __restrict__ kn,
    const float* __restrict__ acts, const float* __restrict__ eg,
    const float* __restrict__ bt, float* __restrict__ o)
{
    const int h    = blockIdx.y;
    const int dvt  = blockIdx.x;
    const int hk   = h >> 1;                 // GQA repeat-interleave
    const int tid  = threadIdx.x;
    const int w    = tid >> 5;
    const int lane = tid & 31;
    const int dv0  = dvt * 16 + w * 4;

    __shared__ float sq[32][128];
    __shared__ float sk[32][128];
    __shared__ float sv[32][16];
    __shared__ float se[32];
    __shared__ float sb[32];

    float S[4][4];
#pragma unroll
    for (int i = 0; i < 4; i++)
#pragma unroll
        for (int j = 0; j < 4; j++) S[i][j] = 0.f;

    for (int t0 = 0; t0 < T_; t0 += 32) {
        __syncthreads();
        for (int i = tid; i < 32 * 128; i += 128) {
            int tt = i >> 7, cc = i & 127;
            sq[tt][cc] = qn[(size_t)(t0 + tt) * 2048 + hk * 128 + cc];
            sk[tt][cc] = kn[(size_t)(t0 + tt) * 2048 + hk * 128 + cc];
        }
        for (int i = tid; i < 32 * 16; i += 128) {
            int tt = i >> 4, j = i & 15;
            sv[tt][j] = acts[(size_t)(t0 + tt) * MIX + 4096 + h * 128 + dvt * 16 + j];
        }
        if (tid < 32) {
            se[tid] = eg[(t0 + tid) * 32 + h];
            sb[tid] = bt[(t0 + tid) * 32 + h];
        }
        __syncthreads();
#pragma unroll 1
        for (int tt = 0; tt < 32; tt++) {
            float kk[4], qq[4], vv[4];
#pragma unroll
            for (int i = 0; i < 4; i++) { kk[i] = sk[tt][lane + 32 * i]; qq[i] = sq[tt][lane + 32 * i]; }
#pragma unroll
            for (int j = 0; j < 4; j++) vv[j] = sv[tt][w * 4 + j];
            float e = se[tt], b = sb[tt];
            float kv[4] = {0.f, 0.f, 0.f, 0.f};
            float oq[4] = {0.f, 0.f, 0.f, 0.f};
            float qkr = 0.f;
#pragma unroll
            for (int i = 0; i < 4; i++) {
                qkr = fmaf(qq[i], kk[i], qkr);
#pragma unroll
                for (int j = 0; j < 4; j++) {
                    float s = S[i][j] * e;
                    S[i][j] = s;
                    kv[j] = fmaf(kk[i], s, kv[j]);
                    oq[j] = fmaf(qq[i], s, oq[j]);
                }
            }
#pragma unroll
            for (int off = 16; off; off >>= 1) {
#pragma unroll
                for (int j = 0; j < 4; j++) {
                    kv[j] += __shfl_xor_sync(0xffffffffu, kv[j], off);
                    oq[j] += __shfl_xor_sync(0xffffffffu, oq[j], off);
                }
                qkr += __shfl_xor_sync(0xffffffffu, qkr, off);
            }
            float d[4];
#pragma unroll
            for (int j = 0; j < 4; j++) {
                d[j] = b * (vv[j] - kv[j]);
#pragma unroll
                for (int i = 0; i < 4; i++) S[i][j] = fmaf(kk[i], d[j], S[i][j]);
            }
            float ov = 0.f;
#pragma unroll
            for (int j = 0; j < 4; j++) if (lane == j) ov = fmaf(qkr, d[j], oq[j]);
            if (lane < 4)
                o[(size_t)(t0 + tt) * 4096 + h * 128 + dv0 + lane] = ov;
        }
    }
}

// =====================================================================
// gated RMSNorm: o * rsqrt(mean(o^2)+1e-5) * w * silu(gate). warp/(t,h).
// =====================================================================
__global__ void gate_norm(const float* __restrict__ o, const float* __restrict__ gate,
                          const float* __restrict__ wn, float* __restrict__ og)
{
    int wid  = (blockIdx.x * blockDim.x + threadIdx.x) >> 5;  // T_*NH
    int lane = threadIdx.x & 31;
    int t = wid >> 5;
    int h = wid & 31;
    size_t base = (size_t)t * 4096 + h * 128 + lane * 4;
    float4 x = *(const float4*)(o + base);
    float ss = x.x * x.x + x.y * x.y + x.z * x.z + x.w * x.w;
#pragma unroll
    for (int off = 16; off; off >>= 1) ss += __shfl_xor_sync(0xffffffffu, ss, off);
    float r = rsqrtf(ss * (1.f / 128.f) + 1e-5f);
    float4 g  = *(const float4*)(gate + base);
    float4 wv = *(const float4*)(wn + lane * 4);
    float4 out;
    out.x = x.x * r * wv.x * (g.x / (1.f + expf(-g.x)));
    out.y = x.y * r * wv.y * (g.y / (1.f + expf(-g.y)));
    out.z = x.z * r * wv.z * (g.z / (1.f + expf(-g.z)));
    out.w = x.w * r * wv.w * (g.w / (1.f + expf(-g.w)));
    *(float4*)(og + base) = out;
}

// =====================================================================
extern "C" void kernel_launch(void* const* d_in, const int* in_sizes, int n_in,
                              void* d_out, int out_size)
{
    const float* h   = (const float*)d_in[0];
    const float* Wq  = (const float*)d_in[1];
    const float* Wk  = (const float*)d_in[2];
    const float* Wv  = (const float*)d_in[3];
    const float* Wa  = (const float*)d_in[4];
    const float* Wb  = (const float*)d_in[5];
    const float* Wg  = (const float*)d_in[6];
    const float* cq  = (const float*)d_in[7];
    const float* ck  = (const float*)d_in[8];
    const float* cv  = (const float*)d_in[9];
    const float* dtb = (const float*)d_in[10];
    const float* Alg = (const float*)d_in[11];
    const float* onw = (const float*)d_in[12];
    const float* Wo  = (const float*)d_in[13];
    float* out = (float*)d_out;

    float *mixed, *acts, *xa, *xb, *eg, *bt, *qn, *kn, *o, *gate, *og;
    cudaGetSymbolAddress((void**)&mixed, g_mixed);
    cudaGetSymbolAddress((void**)&acts,  g_acts);
    cudaGetSymbolAddress((void**)&xa,    g_xa);
    cudaGetSymbolAddress((void**)&xb,    g_xb);
    cudaGetSymbolAddress((void**)&eg,    g_eg);
    cudaGetSymbolAddress((void**)&bt,    g_bt);
    cudaGetSymbolAddress((void**)&qn,    g_qn);
    cudaGetSymbolAddress((void**)&kn,    g_kn);
    cudaGetSymbolAddress((void**)&o,     g_o);
    cudaGetSymbolAddress((void**)&gate,  g_gate);
    cudaGetSymbolAddress((void**)&og,    g_og);

    // projections
    sgemm128<<<dim3(16, 16), 256>>>(h, Wq, mixed,        2048, 2048, 2048, 2048, 2048, 8192);
    sgemm128<<<dim3(16, 16), 256>>>(h, Wk, mixed + 2048, 2048, 2048, 2048, 2048, 2048, 8192);
    sgemm128<<<dim3(32, 16), 256>>>(h, Wv, mixed + 4096, 2048, 4096, 2048, 2048, 4096, 8192);
    sgemm128<<<dim3(1, 16),  256>>>(h, Wa, xa,           2048, 32,   2048, 2048, 32,   32);
    sgemm128<<<dim3(1, 16),  256>>>(h, Wb, xb,           2048, 32,   2048, 2048, 32,   32);
    sgemm128<<<dim3(32, 16), 256>>>(h, Wg, gate,         2048, 4096, 2048, 2048, 4096, 4096);

    gate_beta<<<256, 256>>>(xa, xb, dtb, Alg, eg, bt);
    conv_silu<<<16384, 256>>>(mixed, cq, ck, cv, acts);
    qknorm<<<8192, 256>>>(acts, qn, kn);
    gdn_scan<<<dim3(8, 32), 128>>>(qn, kn, acts, eg, bt, o);
    gate_norm<<<8192, 256>>>(o, gate, onw, og);

    // output projection
    sgemm128<<<dim3(16, 16), 256>>>(og, Wo, out, 2048, 2048, 4096, 4096, 2048, 2048);
}

// round 3
// speedup vs baseline: 1.6987x; 1.6987x over previous
#include <cuda_runtime.h>
#include <math.h>
#include <cstdint>

static constexpr int T_   = 2048;
static constexpr int NH   = 32;
static constexpr int MIX  = 8192;   // KEY + KEY + VAL
static constexpr int KEYD = 2048;
static constexpr int VALD = 4096;

// ---- scratch (static __device__ arrays; no runtime allocation) ----
__device__ float g_mixed[T_ * MIX];
__device__ float g_acts [T_ * MIX];
__device__ float g_xab  [T_ * 64];
__device__ float g_eg   [T_ * NH];
__device__ float g_bt   [T_ * NH];
__device__ float g_qn   [T_ * KEYD];
__device__ float g_kn   [T_ * KEYD];
__device__ float g_o    [T_ * VALD];
__device__ float g_gate [T_ * VALD];
__device__ float g_og   [T_ * VALD];
__device__ float g_ab   [2048 * 64];   // packed [K, 64] = [Wa | Wb]

// round f32 -> tf32 (round-to-nearest) as an f32 bit pattern
__device__ __forceinline__ float tf32r(float x) {
    uint32_t u;
    asm("cvt.rna.tf32.f32 %0, %1;" : "=r"(u) : "f"(x));
    return __uint_as_float(u);
}

__device__ __forceinline__ void mma_tf32(float* c, const uint32_t* a, const uint32_t* b) {
    asm volatile("mma.sync.aligned.m16n8k8.row.col.f32.tf32.tf32.f32 "
        "{%0,%1,%2,%3}, {%4,%5,%6,%7}, {%8,%9}, {%0,%1,%2,%3};"
        : "+f"(c[0]), "+f"(c[1]), "+f"(c[2]), "+f"(c[3])
        : "r"(a[0]), "r"(a[1]), "r"(a[2]), "r"(a[3]), "r"(b[0]), "r"(b[1]));
}

// =====================================================================
// tf32 mma.sync GEMM: C[2048, N] = A[2048, K] @ B[K, N]; all row-major.
// Block tile 128x128, BK=32, 256 threads (8 warps, 2x4), warp tile 64x32.
// Smem layout permutes k so fragment loads are float2: element (r, k)
// at r*34 + (k&3)*8 + (k>>2). B staged transposed: (k, n) -> row n.
// =====================================================================
__global__ __launch_bounds__(256) void mma_gemm(
    const float* __restrict__ A, const float* __restrict__ B, float* __restrict__ C,
    int N, int K, int ldc)
{
    __shared__ __align__(16) float As[128 * 34];
    __shared__ __align__(16) float Bs[128 * 34];
    const int tid  = threadIdx.x;
    const int lane = tid & 31;
    const int w    = tid >> 5;
    const int wm   = w >> 2;          // 0..1
    const int wn   = w & 3;           // 0..3
    const int c4   = lane & 3;
    const int g    = lane >> 2;
    const int row0 = blockIdx.y * 128;
    const int col0 = blockIdx.x * 128;

    float acc[4][4][4];
#pragma unroll
    for (int mi = 0; mi < 4; mi++)
#pragma unroll
        for (int ni = 0; ni < 4; ni++)
#pragma unroll
            for (int q = 0; q < 4; q++) acc[mi][ni][q] = 0.f;

    const int nt = K >> 5;
    float4 pa[4], pb[4];

    // gmem tile load into regs
    auto loadg = [&](int k0) {
#pragma unroll
        for (int it = 0; it < 4; it++) {
            int idx = it * 256 + tid;
            int r = idx >> 3, a = idx & 7;
            pa[it] = *(const float4*)(A + (size_t)(row0 + r) * K + k0 + a * 4);
        }
#pragma unroll
        for (int it = 0; it < 4; it++) {
            int idx = it * 256 + tid;
            int kr = idx >> 5, nc = (idx & 31) * 4;
            float4 v = make_float4(0.f, 0.f, 0.f, 0.f);
            if (col0 + nc < N) v = *(const float4*)(B + (size_t)(k0 + kr) * N + col0 + nc);
            pb[it] = v;
        }
    };
    // regs -> smem with tf32 rounding + k-permute
    auto stores = [&]() {
#pragma unroll
        for (int it = 0; it < 4; it++) {
            int idx = it * 256 + tid;
            int r = idx >> 3, a = idx & 7;
            float* ap = As + r * 34 + a;
            ap[0]  = tf32r(pa[it].x);
            ap[8]  = tf32r(pa[it].y);
            ap[16] = tf32r(pa[it].z);
            ap[24] = tf32r(pa[it].w);
        }
#pragma unroll
        for (int it = 0; it < 4; it++) {
            int idx = it * 256 + tid;
            int kr = idx >> 5, nc = (idx & 31) * 4;
            int p = (kr & 3) * 8 + (kr >> 2);
            Bs[(nc + 0) * 34 + p] = tf32r(pb[it].x);
            Bs[(nc + 1) * 34 + p] = tf32r(pb[it].y);
            Bs[(nc + 2) * 34 + p] = tf32r(pb[it].z);
            Bs[(nc + 3) * 34 + p] = tf32r(pb[it].w);
        }
    };

    loadg(0);
    stores();
    __syncthreads();

    for (int t = 0; t < nt; t++) {
        if (t + 1 < nt) loadg((t + 1) << 5);
#pragma unroll
        for (int s = 0; s < 4; s++) {
            uint32_t af[4][4];
            uint32_t bf[4][2];
#pragma unroll
            for (int mi = 0; mi < 4; mi++) {
                int r = wm * 64 + mi * 16 + g;
                float2 lo = *(const float2*)&As[r * 34 + c4 * 8 + 2 * s];
                float2 hi = *(const float2*)&As[(r + 8) * 34 + c4 * 8 + 2 * s];
                af[mi][0] = __float_as_uint(lo.x);   // a0
                af[mi][1] = __float_as_uint(hi.x);   // a1
                af[mi][2] = __float_as_uint(lo.y);   // a2
                af[mi][3] = __float_as_uint(hi.y);   // a3
            }
#pragma unroll
            for (int ni = 0; ni < 4; ni++) {
                int n = wn * 32 + ni * 8 + g;
                float2 b2 = *(const float2*)&Bs[n * 34 + c4 * 8 + 2 * s];
                bf[ni][0] = __float_as_uint(b2.x);
                bf[ni][1] = __float_as_uint(b2.y);
            }
#pragma unroll
            for (int mi = 0; mi < 4; mi++)
#pragma unroll
                for (int ni = 0; ni < 4; ni++)
                    mma_tf32(acc[mi][ni], af[mi], bf[ni]);
        }
        __syncthreads();
        if (t + 1 < nt) {
            stores();
            __syncthreads();
        }
    }

#pragma unroll
    for (int mi = 0; mi < 4; mi++) {
        int r0 = row0 + wm * 64 + mi * 16 + g;
#pragma unroll
        for (int ni = 0; ni < 4; ni++) {
            int cc = col0 + wn * 32 + ni * 8 + 2 * c4;
            if (cc < N) {
                *(float2*)(C + (size_t)r0 * ldc + cc) =
                    make_float2(acc[mi][ni][0], acc[mi][ni][1]);
                *(float2*)(C + (size_t)(r0 + 8) * ldc + cc) =
                    make_float2(acc[mi][ni][2], acc[mi][ni][3]);
            }
        }
    }
}

// =====================================================================
// Pack Wa, Wb [2048, 32] each into one [2048, 64] B matrix
// =====================================================================
__global__ void pack_ab(const float* __restrict__ Wa, const float* __restrict__ Wb,
                        float* __restrict__ P)
{
    int i = blockIdx.x * blockDim.x + threadIdx.x;  // 2048*32
    int k = i >> 5, n = i & 31;
    P[k * 64 + n]      = Wa[i];
    P[k * 64 + 32 + n] = Wb[i];
}

// =====================================================================
// Causal depthwise conv (K=4) + SiLU
// =====================================================================
__global__ void conv_silu(const float* __restrict__ mixed,
                          const float* __restrict__ cq,
                          const float* __restrict__ ck,
                          const float* __restrict__ cv,
                          float* __restrict__ acts)
{
    int gid = blockIdx.x * blockDim.x + threadIdx.x;
    int t = gid >> 11;
    int c = (gid & 2047) << 2;
    const float* wp = (c < 2048) ? (cq + c * 4)
                    : (c < 4096) ? (ck + (c - 2048) * 4)
                                 : (cv + (c - 4096) * 4);
    float4 w0 = *(const float4*)(wp + 0);
    float4 w1 = *(const float4*)(wp + 4);
    float4 w2 = *(const float4*)(wp + 8);
    float4 w3 = *(const float4*)(wp + 12);
    const float* xp = mixed + (size_t)t * MIX + c;
    float4 z  = make_float4(0.f, 0.f, 0.f, 0.f);
    float4 x3 = *(const float4*)xp;
    float4 x2 = (t >= 1) ? *(const float4*)(xp - MIX)     : z;
    float4 x1 = (t >= 2) ? *(const float4*)(xp - 2 * MIX) : z;
    float4 x0 = (t >= 3) ? *(const float4*)(xp - 3 * MIX) : z;
    float4 o;
    o.x = w0.x * x0.x + w0.y * x1.x + w0.z * x2.x + w0.w * x3.x;
    o.y = w1.x * x0.y + w1.y * x1.y + w1.z * x2.y + w1.w * x3.y;
    o.z = w2.x * x0.z + w2.y * x1.z + w2.z * x2.z + w2.w * x3.z;
    o.w = w3.x * x0.w + w3.y * x1.w + w3.z * x2.w + w3.w * x3.w;
    o.x = o.x / (1.f + expf(-o.x));
    o.y = o.y / (1.f + expf(-o.y));
    o.z = o.z / (1.f + expf(-o.z));
    o.w = o.w / (1.f + expf(-o.w));
    *(float4*)(acts + (size_t)t * MIX + c) = o;
}

// =====================================================================
__global__ void gate_beta(const float* __restrict__ xab,
                          const float* __restrict__ dtb, const float* __restrict__ Alg,
                          float* __restrict__ eg, float* __restrict__ bt)
{
    int i = blockIdx.x * blockDim.x + threadIdx.x;   // T_*NH
    int t = i >> 5, h = i & 31;
    float x  = xab[t * 64 + h] + dtb[h];
    float sp = (x <= 20.f) ? log1pf(expf(x)) : x;
    eg[i] = expf(-expf(Alg[h]) * sp);
    float xb = xab[t * 64 + 32 + h];
    bt[i] = 1.f / (1.f + expf(-xb));
}

// =====================================================================
__global__ void qknorm(const float* __restrict__ acts,
                       float* __restrict__ qn, float* __restrict__ kn)
{
    int wid  = (blockIdx.x * blockDim.x + threadIdx.x) >> 5;
    int lane = threadIdx.x & 31;
    int t     = wid >> 5;
    int hh    = (wid >> 1) & 15;
    int which = wid & 1;
    const float* src = acts + (size_t)t * MIX + which * 2048 + hh * 128 + lane * 4;
    float4 x = *(const float4*)src;
    float ss = x.x * x.x + x.y * x.y + x.z * x.z + x.w * x.w;
#pragma unroll
    for (int off = 16; off; off >>= 1) ss += __shfl_xor_sync(0xffffffffu, ss, off);
    float s = rsqrtf(ss + 1e-6f);
    if (which == 0) s *= 0.08838834764831845f;
    float* dst = (which == 0 ? qn : kn) + (size_t)t * 2048 + hh * 128 + lane * 4;
    *(float4*)dst = make_float4(x.x * s, x.y * s, x.z * s, x.w * s);
}

// =====================================================================
// Gated delta-rule scan. Grid (8 dv-tiles, 32 heads), 128 threads.
// =====================================================================
__global__ __launch_bounds__(128) void gdn_scan(
    const float* __restrict__ qn, const float* __restrict__ kn,
    const float* __restrict__ acts, const float* __restrict__ eg,
    const float* __restrict__ bt, float* __restrict__ o)
{
    const int h    = blockIdx.y;
    const int dvt  = blockIdx.x;
    const int hk   = h >> 1;
    const int tid  = threadIdx.x;
    const int w    = tid >> 5;
    const int lane = tid & 31;
    const int dv0  = dvt * 16 + w * 4;

    __shared__ float sq[32][128];
    __shared__ float sk[32][128];
    __shared__ float sv[32][16];
    __shared__ float se[32];
    __shared__ float sb[32];

    float S[4][4];
#pragma unroll
    for (int i = 0; i < 4; i++)
#pragma unroll
        for (int j = 0; j < 4; j++) S[i][j] = 0.f;

    for (int t0 = 0; t0 < T_; t0 += 32) {
        __syncthreads();
        for (int i = tid; i < 32 * 128; i += 128) {
            int tt = i >> 7, cc = i & 127;
            sq[tt][cc] = qn[(size_t)(t0 + tt) * 2048 + hk * 128 + cc];
            sk[tt][cc] = kn[(size_t)(t0 + tt) * 2048 + hk * 128 + cc];
        }
        for (int i = tid; i < 32 * 16; i += 128) {
            int tt = i >> 4, j = i & 15;
            sv[tt][j] = acts[(size_t)(t0 + tt) * MIX + 4096 + h * 128 + dvt * 16 + j];
        }
        if (tid < 32) {
            se[tid] = eg[(t0 + tid) * 32 + h];
            sb[tid] = bt[(t0 + tid) * 32 + h];
        }
        __syncthreads();
#pragma unroll 1
        for (int tt = 0; tt < 32; tt++) {
            float kk[4], qq[4], vv[4];
#pragma unroll
            for (int i = 0; i < 4; i++) { kk[i] = sk[tt][lane + 32 * i]; qq[i] = sq[tt][lane + 32 * i]; }
#pragma unroll
            for (int j = 0; j < 4; j++) vv[j] = sv[tt][w * 4 + j];
            float e = se[tt], b = sb[tt];
            float kv[4] = {0.f, 0.f, 0.f, 0.f};
            float oq[4] = {0.f, 0.f, 0.f, 0.f};
            float qkr = 0.f;
#pragma unroll
            for (int i = 0; i < 4; i++) {
                qkr = fmaf(qq[i], kk[i], qkr);
#pragma unroll
                for (int j = 0; j < 4; j++) {
                    float s = S[i][j] * e;
                    S[i][j] = s;
                    kv[j] = fmaf(kk[i], s, kv[j]);
                    oq[j] = fmaf(qq[i], s, oq[j]);
                }
            }
#pragma unroll
            for (int off = 16; off; off >>= 1) {
#pragma unroll
                for (int j = 0; j < 4; j++) {
                    kv[j] += __shfl_xor_sync(0xffffffffu, kv[j], off);
                    oq[j] += __shfl_xor_sync(0xffffffffu, oq[j], off);
                }
                qkr += __shfl_xor_sync(0xffffffffu, qkr, off);
            }
            float d[4];
#pragma unroll
            for (int j = 0; j < 4; j++) {
                d[j] = b * (vv[j] - kv[j]);
#pragma unroll
                for (int i = 0; i < 4; i++) S[i][j] = fmaf(kk[i], d[j], S[i][j]);
            }
            float ov = 0.f;
#pragma unroll
            for (int j = 0; j < 4; j++) if (lane == j) ov = fmaf(qkr, d[j], oq[j]);
            if (lane < 4)
                o[(size_t)(t0 + tt) * 4096 + h * 128 + dv0 + lane] = ov;
        }
    }
}

// =====================================================================
__global__ void gate_norm(const float* __restrict__ o, const float* __restrict__ gate,
                          const float* __restrict__ wn, float* __restrict__ og)
{
    int wid  = (blockIdx.x * blockDim.x + threadIdx.x) >> 5;
    int lane = threadIdx.x & 31;
    int t = wid >> 5;
    int h = wid & 31;
    size_t base = (size_t)t * 4096 + h * 128 + lane * 4;
    float4 x = *(const float4*)(o + base);
    float ss = x.x * x.x + x.y * x.y + x.z * x.z + x.w * x.w;
#pragma unroll
    for (int off = 16; off; off >>= 1) ss += __shfl_xor_sync(0xffffffffu, ss, off);
    float r = rsqrtf(ss * (1.f / 128.f) + 1e-5f);
    float4 g  = *(const float4*)(gate + base);
    float4 wv = *(const float4*)(wn + lane * 4);
    float4 out;
    out.x = x.x * r * wv.x * (g.x / (1.f + expf(-g.x)));
    out.y = x.y * r * wv.y * (g.y / (1.f + expf(-g.y)));
    out.z = x.z * r * wv.z * (g.z / (1.f + expf(-g.z)));
    out.w = x.w * r * wv.w * (g.w / (1.f + expf(-g.w)));
    *(float4*)(og + base) = out;
}

// =====================================================================
extern "C" void kernel_launch(void* const* d_in, const int* in_sizes, int n_in,
                              void* d_out, int out_size)
{
    const float* h   = (const float*)d_in[0];
    const float* Wq  = (const float*)d_in[1];
    const float* Wk  = (const float*)d_in[2];
    const float* Wv  = (const float*)d_in[3];
    const float* Wa  = (const float*)d_in[4];
    const float* Wb  = (const float*)d_in[5];
    const float* Wg  = (const float*)d_in[6];
    const float* cq  = (const float*)d_in[7];
    const float* ck  = (const float*)d_in[8];
    const float* cv  = (const float*)d_in[9];
    const float* dtb = (const float*)d_in[10];
    const float* Alg = (const float*)d_in[11];
    const float* onw = (const float*)d_in[12];
    const float* Wo  = (const float*)d_in[13];
    float* out = (float*)d_out;

    float *mixed, *acts, *xab, *eg, *bt, *qn, *kn, *o, *gate, *og, *ab;
    cudaGetSymbolAddress((void**)&mixed, g_mixed);
    cudaGetSymbolAddress((void**)&acts,  g_acts);
    cudaGetSymbolAddress((void**)&xab,   g_xab);
    cudaGetSymbolAddress((void**)&eg,    g_eg);
    cudaGetSymbolAddress((void**)&bt,    g_bt);
    cudaGetSymbolAddress((void**)&qn,    g_qn);
    cudaGetSymbolAddress((void**)&kn,    g_kn);
    cudaGetSymbolAddress((void**)&o,     g_o);
    cudaGetSymbolAddress((void**)&gate,  g_gate);
    cudaGetSymbolAddress((void**)&og,    g_og);
    cudaGetSymbolAddress((void**)&ab,    g_ab);

    pack_ab<<<256, 256>>>(Wa, Wb, ab);

    // projections (tf32 mma.sync tensor cores); B used as [K, N] row-major directly
    mma_gemm<<<dim3(16, 16), 256>>>(h, Wq, mixed,        2048, 2048, 8192);
    mma_gemm<<<dim3(16, 16), 256>>>(h, Wk, mixed + 2048, 2048, 2048, 8192);
    mma_gemm<<<dim3(32, 16), 256>>>(h, Wv, mixed + 4096, 4096, 2048, 8192);
    mma_gemm<<<dim3(32, 16), 256>>>(h, Wg, gate,         4096, 2048, 4096);
    mma_gemm<<<dim3(1, 16),  256>>>(h, ab, xab,          64,   2048, 64);

    gate_beta<<<256, 256>>>(xab, dtb, Alg, eg, bt);
    conv_silu<<<16384, 256>>>(mixed, cq, ck, cv, acts);
    qknorm<<<8192, 256>>>(acts, qn, kn);
    gdn_scan<<<dim3(8, 32), 128>>>(qn, kn, acts, eg, bt, o);
    gate_norm<<<8192, 256>>>(o, gate, onw, og);

    // output projection
    mma_gemm<<<dim3(16, 16), 256>>>(og, Wo, out, 2048, 4096, 2048);
}

// round 4
// speedup vs baseline: 2.7058x; 1.5928x over previous
#include <cuda_runtime.h>
#include <math.h>
#include <cstdint>

static constexpr int T_   = 2048;
static constexpr int NH   = 32;
static constexpr int NPACK = 12544;   // q(2048) k(2048) v(4096) g(4096) a(32) b(32) pad(192)
static constexpr int OFF_K = 2048;
static constexpr int OFF_V = 4096;
static constexpr int OFF_G = 8192;
static constexpr int OFF_A = 12288;
static constexpr int OFF_B2 = 12320;
static constexpr int OFF_END = 12352;

// ---- scratch (static __device__ arrays; no runtime allocation) ----
__device__ float g_big [T_ * NPACK];   // fused projection output (q|k|v|gate|xa|xb)
__device__ float g_Wp  [2048 * NPACK]; // packed + tf32-rounded weights
__device__ float g_hr  [T_ * 2048];    // tf32-rounded h
__device__ float g_WoR [4096 * 2048];  // tf32-rounded Wo
__device__ float g_acts[T_ * 8192];    // conv+silu output (q|k|v), stride 8192
__device__ float g_eg  [T_ * NH];
__device__ float g_bt  [T_ * NH];
__device__ float g_qn  [T_ * 2048];
__device__ float g_kn  [T_ * 2048];
__device__ float g_o   [T_ * 4096];
__device__ float g_og  [T_ * 4096];    // normed+gated, tf32-rounded

// round f32 -> tf32 (round-to-nearest) as an f32 bit pattern
__device__ __forceinline__ float tf32r(float x) {
    uint32_t u;
    asm("cvt.rna.tf32.f32 %0, %1;" : "=r"(u) : "f"(x));
    return __uint_as_float(u);
}

__device__ __forceinline__ uint32_t smem_u32(const void* p) {
    uint32_t a;
    asm("{ .reg .u64 t; cvta.to.shared.u64 t, %1; cvt.u32.u64 %0, t; }" : "=r"(a) : "l"(p));
    return a;
}
__device__ __forceinline__ void cp16(uint32_t dst, const void* src) {
    asm volatile("cp.async.cg.shared.global [%0], [%1], 16;" :: "r"(dst), "l"(src));
}
#define CP_COMMIT() asm volatile("cp.async.commit_group;" ::: "memory")
#define CP_WAIT(n)  asm volatile("cp.async.wait_group %0;" :: "n"(n) : "memory")

__device__ __forceinline__ uint32_t lds32(uint32_t a) {
    uint32_t v;
    asm volatile("ld.shared.b32 %0, [%1];" : "=r"(v) : "r"(a));
    return v;
}

__device__ __forceinline__ void mma_tf32(float* c, const uint32_t* a, const uint32_t* b) {
    asm volatile("mma.sync.aligned.m16n8k8.row.col.f32.tf32.tf32.f32 "
        "{%0,%1,%2,%3}, {%4,%5,%6,%7}, {%8,%9}, {%0,%1,%2,%3};"
        : "+f"(c[0]), "+f"(c[1]), "+f"(c[2]), "+f"(c[3])
        : "r"(a[0]), "r"(a[1]), "r"(a[2]), "r"(a[3]), "r"(b[0]), "r"(b[1]));
}

// =====================================================================
// tf32 mma.sync GEMM v2: C[2048, N] = A[2048, K] @ B[K, N], row-major,
// A and B pre-rounded to tf32. CTA tile 128x256, BK=32, 8 warps (2x4),
// warp tile 64x64. 3-stage cp.async pipeline. XOR-16B smem swizzles.
// Stage layout: A 128 rows x 128B (16KB), B 32 rows x 1024B (32KB).
// =====================================================================
static constexpr uint32_t STAGE = 49152;           // 16KB A + 32KB B
static constexpr uint32_t GEMM_SMEM = 3 * STAGE;   // 144KB

__global__ __launch_bounds__(256) void mma_gemm(
    const float* __restrict__ A, const float* __restrict__ B, float* __restrict__ C,
    int K, int ldb, int ldc)
{
    extern __shared__ char smem[];
    const uint32_t sbase = smem_u32(smem);
    const int tid  = threadIdx.x;
    const int lane = tid & 31;
    const int w    = tid >> 5;
    const int wm   = w >> 2;          // 0..1
    const int wn   = w & 3;           // 0..3
    const int c4   = lane & 3;
    const int g    = lane >> 2;
    const int row0 = blockIdx.y * 128;
    const int col0 = blockIdx.x * 256;

    float acc[4][8][4];
#pragma unroll
    for (int mi = 0; mi < 4; mi++)
#pragma unroll
        for (int ni = 0; ni < 8; ni++)
#pragma unroll
            for (int q = 0; q < 4; q++) acc[mi][ni][q] = 0.f;

    const int nt = K >> 5;

    auto issue = [&](int t, int st) {
        const int k0 = t << 5;
        const uint32_t sA = sbase + st * STAGE;
        const uint32_t sB = sA + 16384;
#pragma unroll
        for (int it = 0; it < 4; it++) {
            int idx = it * 256 + tid;          // 0..1023
            int r = idx >> 3, f = idx & 7;
            cp16(sA + r * 128 + ((f ^ (r & 7)) << 4),
                 A + (size_t)(row0 + r) * K + k0 + f * 4);
        }
#pragma unroll
        for (int it = 0; it < 8; it++) {
            int idx = it * 256 + tid;          // 0..2047
            int k = idx >> 6, c = idx & 63;
            cp16(sB + k * 1024 + ((c ^ ((k & 3) << 1)) << 4),
                 B + (size_t)(k0 + k) * ldb + col0 + c * 4);
        }
    };

    auto compute = [&](int st) {
        const uint32_t sA = sbase + st * STAGE;
        const uint32_t sB = sA + 16384;
#pragma unroll
        for (int s = 0; s < 4; s++) {
            uint32_t af[4][4];
            uint32_t bf[8][2];
            const int f0 = 2 * s, f1 = 2 * s + 1;
#pragma unroll
            for (int mi = 0; mi < 4; mi++) {
                const int r = wm * 64 + mi * 16 + g;   // r&7 == g
                const uint32_t base = sA + r * 128 + c4 * 4;
                af[mi][0] = lds32(base + ((f0 ^ g) << 4));
                af[mi][1] = lds32(base + 8 * 128 + ((f0 ^ g) << 4));
                af[mi][2] = lds32(base + ((f1 ^ g) << 4));
                af[mi][3] = lds32(base + 8 * 128 + ((f1 ^ g) << 4));
            }
            const int kk = 8 * s + c4;
#pragma unroll
            for (int ni = 0; ni < 8; ni++) {
                const int n = wn * 64 + ni * 8 + g;
                const int c = n >> 2;
                const uint32_t boff = ((c ^ (c4 << 1)) << 4) + (n & 3) * 4;
                bf[ni][0] = lds32(sB + kk * 1024 + boff);
                bf[ni][1] = lds32(sB + (kk + 4) * 1024 + boff);
            }
#pragma unroll
            for (int mi = 0; mi < 4; mi++)
#pragma unroll
                for (int ni = 0; ni < 8; ni++)
                    mma_tf32(acc[mi][ni], af[mi], bf[ni]);
        }
    };

    issue(0, 0); CP_COMMIT();
    issue(1, 1); CP_COMMIT();
    int st = 0;
    for (int t = 0; t < nt; t++) {
        if (t + 2 < nt) {
            CP_WAIT(1);
            __syncthreads();
            issue(t + 2, (st + 2) % 3);
            CP_COMMIT();
        } else {
            CP_WAIT(0);
            __syncthreads();
        }
        compute(st);
        st = (st + 1) % 3;
        if (st == 0) st = 0;   // keep st in [0,3)
    }

#pragma unroll
    for (int mi = 0; mi < 4; mi++) {
        const int r0 = row0 + wm * 64 + mi * 16 + g;
#pragma unroll
        for (int ni = 0; ni < 8; ni++) {
            const int cc = col0 + wn * 64 + ni * 8 + 2 * c4;
            *(float2*)(C + (size_t)r0 * ldc + cc) =
                make_float2(acc[mi][ni][0], acc[mi][ni][1]);
            *(float2*)(C + (size_t)(r0 + 8) * ldc + cc) =
                make_float2(acc[mi][ni][2], acc[mi][ni][3]);
        }
    }
}

// =====================================================================
// Pack + tf32-round all projection weights into Wp[2048, 12544]
// =====================================================================
__global__ void pack_w(const float* __restrict__ Wq, const float* __restrict__ Wk,
                       const float* __restrict__ Wv, const float* __restrict__ Wg,
                       const float* __restrict__ Wa, const float* __restrict__ Wb,
                       float* __restrict__ P)
{
    int idx = blockIdx.x * 256 + threadIdx.x;   // 2048 * 3136
    int k = idx / 3136;
    int n = (idx - k * 3136) * 4;
    float4 v = make_float4(0.f, 0.f, 0.f, 0.f);
    if      (n < OFF_K)   v = *(const float4*)(Wq + (size_t)k * 2048 + n);
    else if (n < OFF_V)   v = *(const float4*)(Wk + (size_t)k * 2048 + n - OFF_K);
    else if (n < OFF_G)   v = *(const float4*)(Wv + (size_t)k * 4096 + n - OFF_V);
    else if (n < OFF_A)   v = *(const float4*)(Wg + (size_t)k * 4096 + n - OFF_G);
    else if (n < OFF_B2)  v = *(const float4*)(Wa + (size_t)k * 32 + n - OFF_A);
    else if (n < OFF_END) v = *(const float4*)(Wb + (size_t)k * 32 + n - OFF_B2);
    v.x = tf32r(v.x); v.y = tf32r(v.y); v.z = tf32r(v.z); v.w = tf32r(v.w);
    *(float4*)(P + (size_t)k * NPACK + n) = v;
}

// tf32-round copy
__global__ void round_copy(const float* __restrict__ src, float* __restrict__ dst)
{
    int i = (blockIdx.x * 256 + threadIdx.x) * 4;
    float4 v = *(const float4*)(src + i);
    v.x = tf32r(v.x); v.y = tf32r(v.y); v.z = tf32r(v.z); v.w = tf32r(v.w);
    *(float4*)(dst + i) = v;
}

// =====================================================================
// Causal depthwise conv (K=4) + SiLU; input stride NPACK, output 8192
// =====================================================================
__global__ void conv_silu(const float* __restrict__ big,
                          const float* __restrict__ cq,
                          const float* __restrict__ ck,
                          const float* __restrict__ cv,
                          float* __restrict__ acts)
{
    int gid = blockIdx.x * blockDim.x + threadIdx.x;
    int t = gid >> 11;
    int c = (gid & 2047) << 2;
    const float* wp = (c < 2048) ? (cq + c * 4)
                    : (c < 4096) ? (ck + (c - 2048) * 4)
                                 : (cv + (c - 4096) * 4);
    float4 w0 = *(const float4*)(wp + 0);
    float4 w1 = *(const float4*)(wp + 4);
    float4 w2 = *(const float4*)(wp + 8);
    float4 w3 = *(const float4*)(wp + 12);
    const float* xp = big + (size_t)t * NPACK + c;
    float4 z  = make_float4(0.f, 0.f, 0.f, 0.f);
    float4 x3 = *(const float4*)xp;
    float4 x2 = (t >= 1) ? *(const float4*)(xp - NPACK)     : z;
    float4 x1 = (t >= 2) ? *(const float4*)(xp - 2 * NPACK) : z;
    float4 x0 = (t >= 3) ? *(const float4*)(xp - 3 * NPACK) : z;
    float4 o;
    o.x = w0.x * x0.x + w0.y * x1.x + w0.z * x2.x + w0.w * x3.x;
    o.y = w1.x * x0.y + w1.y * x1.y + w1.z * x2.y + w1.w * x3.y;
    o.z = w2.x * x0.z + w2.y * x1.z + w2.z * x2.z + w2.w * x3.z;
    o.w = w3.x * x0.w + w3.y * x1.w + w3.z * x2.w + w3.w * x3.w;
    o.x = o.x / (1.f + expf(-o.x));
    o.y = o.y / (1.f + expf(-o.y));
    o.z = o.z / (1.f + expf(-o.z));
    o.w = o.w / (1.f + expf(-o.w));
    *(float4*)(acts + (size_t)t * 8192 + c) = o;
}

// =====================================================================
__global__ void gate_beta(const float* __restrict__ big,
                          const float* __restrict__ dtb, const float* __restrict__ Alg,
                          float* __restrict__ eg, float* __restrict__ bt)
{
    int i = blockIdx.x * blockDim.x + threadIdx.x;   // T_*NH
    int t = i >> 5, h = i & 31;
    float x  = big[(size_t)t * NPACK + OFF_A + h] + dtb[h];
    float sp = (x <= 20.f) ? log1pf(expf(x)) : x;
    eg[i] = expf(-expf(Alg[h]) * sp);
    float xb = big[(size_t)t * NPACK + OFF_B2 + h];
    bt[i] = 1.f / (1.f + expf(-xb));
}

// =====================================================================
__global__ void qknorm(const float* __restrict__ acts,
                       float* __restrict__ qn, float* __restrict__ kn)
{
    int wid  = (blockIdx.x * blockDim.x + threadIdx.x) >> 5;
    int lane = threadIdx.x & 31;
    int t     = wid >> 5;
    int hh    = (wid >> 1) & 15;
    int which = wid & 1;
    const float* src = acts + (size_t)t * 8192 + which * 2048 + hh * 128 + lane * 4;
    float4 x = *(const float4*)src;
    float ss = x.x * x.x + x.y * x.y + x.z * x.z + x.w * x.w;
#pragma unroll
    for (int off = 16; off; off >>= 1) ss += __shfl_xor_sync(0xffffffffu, ss, off);
    float s = rsqrtf(ss + 1e-6f);
    if (which == 0) s *= 0.08838834764831845f;
    float* dst = (which == 0 ? qn : kn) + (size_t)t * 2048 + hh * 128 + lane * 4;
    *(float4*)dst = make_float4(x.x * s, x.y * s, x.z * s, x.w * s);
}

// =====================================================================
// Gated delta-rule scan. Grid (8 dv-tiles, 32 heads), 128 threads.
// =====================================================================
__global__ __launch_bounds__(128) void gdn_scan(
    const float* __restrict__ qn, const float* __restrict__ kn,
    const float* __restrict__ acts, const float* __restrict__ eg,
    const float* __restrict__ bt, float* __restrict__ o)
{
    const int h    = blockIdx.y;
    const int dvt  = blockIdx.x;
    const int hk   = h >> 1;
    const int tid  = threadIdx.x;
    const int w    = tid >> 5;
    const int lane = tid & 31;
    const int dv0  = dvt * 16 + w * 4;

    __shared__ float sq[32][128];
    __shared__ float sk[32][128];
    __shared__ float sv[32][16];
    __shared__ float se[32];
    __shared__ float sb[32];

    float S[4][4];
#pragma unroll
    for (int i = 0; i < 4; i++)
#pragma unroll
        for (int j = 0; j < 4; j++) S[i][j] = 0.f;

    for (int t0 = 0; t0 < T_; t0 += 32) {
        __syncthreads();
        for (int i = tid; i < 32 * 128; i += 128) {
            int tt = i >> 7, cc = i & 127;
            sq[tt][cc] = qn[(size_t)(t0 + tt) * 2048 + hk * 128 + cc];
            sk[tt][cc] = kn[(size_t)(t0 + tt) * 2048 + hk * 128 + cc];
        }
        for (int i = tid; i < 32 * 16; i += 128) {
            int tt = i >> 4, j = i & 15;
            sv[tt][j] = acts[(size_t)(t0 + tt) * 8192 + 4096 + h * 128 + dvt * 16 + j];
        }
        if (tid < 32) {
            se[tid] = eg[(t0 + tid) * 32 + h];
            sb[tid] = bt[(t0 + tid) * 32 + h];
        }
        __syncthreads();
#pragma unroll 1
        for (int tt = 0; tt < 32; tt++) {
            float kk[4], qq[4], vv[4];
#pragma unroll
            for (int i = 0; i < 4; i++) { kk[i] = sk[tt][lane + 32 * i]; qq[i] = sq[tt][lane + 32 * i]; }
#pragma unroll
            for (int j = 0; j < 4; j++) vv[j] = sv[tt][w * 4 + j];
            float e = se[tt], b = sb[tt];
            float kv[4] = {0.f, 0.f, 0.f, 0.f};
            float oq[4] = {0.f, 0.f, 0.f, 0.f};
            float qkr = 0.f;
#pragma unroll
            for (int i = 0; i < 4; i++) {
                qkr = fmaf(qq[i], kk[i], qkr);
#pragma unroll
                for (int j = 0; j < 4; j++) {
                    float s = S[i][j] * e;
                    S[i][j] = s;
                    kv[j] = fmaf(kk[i], s, kv[j]);
                    oq[j] = fmaf(qq[i], s, oq[j]);
                }
            }
#pragma unroll
            for (int off = 16; off; off >>= 1) {
#pragma unroll
                for (int j = 0; j < 4; j++) {
                    kv[j] += __shfl_xor_sync(0xffffffffu, kv[j], off);
                    oq[j] += __shfl_xor_sync(0xffffffffu, oq[j], off);
                }
                qkr += __shfl_xor_sync(0xffffffffu, qkr, off);
            }
            float d[4];
#pragma unroll
            for (int j = 0; j < 4; j++) {
                d[j] = b * (vv[j] - kv[j]);
#pragma unroll
                for (int i = 0; i < 4; i++) S[i][j] = fmaf(kk[i], d[j], S[i][j]);
            }
            float ov = 0.f;
#pragma unroll
            for (int j = 0; j < 4; j++) if (lane == j) ov = fmaf(qkr, d[j], oq[j]);
            if (lane < 4)
                o[(size_t)(t0 + tt) * 4096 + h * 128 + dv0 + lane] = ov;
        }
    }
}

// =====================================================================
// gated RMSNorm + silu(gate); writes tf32-rounded og for the Wo GEMM
// =====================================================================
__global__ void gate_norm(const float* __restrict__ o, const float* __restrict__ big,
                          const float* __restrict__ wn, float* __restrict__ og)
{
    int wid  = (blockIdx.x * blockDim.x + threadIdx.x) >> 5;
    int lane = threadIdx.x & 31;
    int t = wid >> 5;
    int h = wid & 31;
    size_t base = (size_t)t * 4096 + h * 128 + lane * 4;
    float4 x = *(const float4*)(o + base);
    float ss = x.x * x.x + x.y * x.y + x.z * x.z + x.w * x.w;
#pragma unroll
    for (int off = 16; off; off >>= 1) ss += __shfl_xor_sync(0xffffffffu, ss, off);
    float r = rsqrtf(ss * (1.f / 128.f) + 1e-5f);
    float4 gv = *(const float4*)(big + (size_t)t * NPACK + OFF_G + h * 128 + lane * 4);
    float4 wv = *(const float4*)(wn + lane * 4);
    float4 out;
    out.x = tf32r(x.x * r * wv.x * (gv.x / (1.f + expf(-gv.x))));
    out.y = tf32r(x.y * r * wv.y * (gv.y / (1.f + expf(-gv.y))));
    out.z = tf32r(x.z * r * wv.z * (gv.z / (1.f + expf(-gv.z))));
    out.w = tf32r(x.w * r * wv.w * (gv.w / (1.f + expf(-gv.w))));
    *(float4*)(og + base) = out;
}

// =====================================================================
extern "C" void kernel_launch(void* const* d_in, const int* in_sizes, int n_in,
                              void* d_out, int out_size)
{
    const float* h   = (const float*)d_in[0];
    const float* Wq  = (const float*)d_in[1];
    const float* Wk  = (const float*)d_in[2];
    const float* Wv  = (const float*)d_in[3];
    const float* Wa  = (const float*)d_in[4];
    const float* Wb  = (const float*)d_in[5];
    const float* Wg  = (const float*)d_in[6];
    const float* cq  = (const float*)d_in[7];
    const float* ck  = (const float*)d_in[8];
    const float* cv  = (const float*)d_in[9];
    const float* dtb = (const float*)d_in[10];
    const float* Alg = (const float*)d_in[11];
    const float* onw = (const float*)d_in[12];
    const float* Wo  = (const float*)d_in[13];
    float* out = (float*)d_out;

    float *big, *Wp, *hr, *WoR, *acts, *eg, *bt, *qn, *kn, *o, *og;
    cudaGetSymbolAddress((void**)&big,  g_big);
    cudaGetSymbolAddress((void**)&Wp,   g_Wp);
    cudaGetSymbolAddress((void**)&hr,   g_hr);
    cudaGetSymbolAddress((void**)&WoR,  g_WoR);
    cudaGetSymbolAddress((void**)&acts, g_acts);
    cudaGetSymbolAddress((void**)&eg,   g_eg);
    cudaGetSymbolAddress((void**)&bt,   g_bt);
    cudaGetSymbolAddress((void**)&qn,   g_qn);
    cudaGetSymbolAddress((void**)&kn,   g_kn);
    cudaGetSymbolAddress((void**)&o,    g_o);
    cudaGetSymbolAddress((void**)&og,   g_og);

    cudaFuncSetAttribute(mma_gemm, cudaFuncAttributeMaxDynamicSharedMemorySize, GEMM_SMEM);

    // pre-round / pack (tf32)
    round_copy<<<(2048 * 2048 / 4) / 256, 256>>>(h, hr);
    round_copy<<<(4096 * 2048 / 4) / 256, 256>>>(Wo, WoR);
    pack_w<<<2048 * 3136 / 256, 256>>>(Wq, Wk, Wv, Wg, Wa, Wb, Wp);

    // fused projection GEMM: big = hr @ Wp  [2048 x 12544]
    mma_gemm<<<dim3(49, 16), 256, GEMM_SMEM>>>(hr, Wp, big, 2048, NPACK, NPACK);

    gate_beta<<<256, 256>>>(big, dtb, Alg, eg, bt);
    conv_silu<<<16384, 256>>>(big, cq, ck, cv, acts);
    qknorm<<<8192, 256>>>(acts, qn, kn);
    gdn_scan<<<dim3(8, 32), 128>>>(qn, kn, acts, eg, bt, o);
    gate_norm<<<8192, 256>>>(o, big, onw, og);

    // output projection: out = og @ WoR  [2048 x 2048], K=4096
    mma_gemm<<<dim3(8, 16), 256, GEMM_SMEM>>>(og, WoR, out, 4096, 2048, 2048);
}

// round 6
// speedup vs baseline: 2.7292x; 1.0086x over previous
#include <cuda_runtime.h>
#include <math.h>
#include <cstdint>

static constexpr int T_   = 2048;
static constexpr int NH   = 32;
static constexpr int NPACK = 12544;   // q(2048) k(2048) v(4096) g(4096) a(32) b(32) pad(192)
static constexpr int OFF_K = 2048;
static constexpr int OFF_V = 4096;
static constexpr int OFF_G = 8192;
static constexpr int OFF_A = 12288;
static constexpr int OFF_B2 = 12320;
static constexpr int OFF_END = 12352;

// ---- scratch (static __device__ arrays; no runtime allocation) ----
__device__ float g_big [T_ * NPACK];   // fused projection output (q|k|v|gate|xa|xb)
__device__ float g_Wp  [2048 * NPACK]; // packed + tf32-rounded weights
__device__ float g_hr  [T_ * 2048];    // tf32-rounded h
__device__ float g_WoR [4096 * 2048];  // tf32-rounded Wo
__device__ float g_acts[T_ * 8192];    // conv+silu output (q|k|v), stride 8192
__device__ float g_eg  [T_ * NH];
__device__ float g_bt  [T_ * NH];
__device__ float g_qn  [T_ * 2048];
__device__ float g_kn  [T_ * 2048];
__device__ float g_o   [T_ * 4096];
__device__ float g_og  [T_ * 4096];    // normed+gated, tf32-rounded

// round f32 -> tf32 (round-to-nearest) as an f32 bit pattern
__device__ __forceinline__ float tf32r(float x) {
    uint32_t u;
    asm("cvt.rna.tf32.f32 %0, %1;" : "=r"(u) : "f"(x));
    return __uint_as_float(u);
}

__device__ __forceinline__ uint32_t smem_u32(const void* p) {
    uint32_t a;
    asm("{ .reg .u64 t; cvta.to.shared.u64 t, %1; cvt.u32.u64 %0, t; }" : "=r"(a) : "l"(p));
    return a;
}
__device__ __forceinline__ void cp16(uint32_t dst, const void* src) {
    asm volatile("cp.async.cg.shared.global [%0], [%1], 16;" :: "r"(dst), "l"(src));
}
#define CP_COMMIT() asm volatile("cp.async.commit_group;" ::: "memory")
#define CP_WAIT(n)  asm volatile("cp.async.wait_group %0;" :: "n"(n) : "memory")

__device__ __forceinline__ uint32_t lds32(uint32_t a) {
    uint32_t v;
    asm volatile("ld.shared.b32 %0, [%1];" : "=r"(v) : "r"(a));
    return v;
}

__device__ __forceinline__ void mma_tf32(float* c, const uint32_t* a, const uint32_t* b) {
    asm volatile("mma.sync.aligned.m16n8k8.row.col.f32.tf32.tf32.f32 "
        "{%0,%1,%2,%3}, {%4,%5,%6,%7}, {%8,%9}, {%0,%1,%2,%3};"
        : "+f"(c[0]), "+f"(c[1]), "+f"(c[2]), "+f"(c[3])
        : "r"(a[0]), "r"(a[1]), "r"(a[2]), "r"(a[3]), "r"(b[0]), "r"(b[1]));
}

// =====================================================================
// tf32 mma.sync GEMM v4: C[M, N] = A[M, K] @ B[K, N], both tf32-rounded,
// plain row-major. CTA tile 256(M) x 128(N), BK=32, 512 threads
// (16 warps, 4x4), warp tile 64x32. 3-stage cp.async pipeline.
// Conflict-free LDS.32 fragments (R4-verified swizzles):
//   A: 128B rows, 16B chunk f stored at f ^ (r & 7); load chunk (2s+j) ^ g.
//   B: 512B rows, 16B chunk c stored at c ^ ((k & 3) << 1).
// Stage: A 256 x 128B (32KB) + B 32 x 512B (16KB) = 48KB.
// =====================================================================
static constexpr uint32_t STAGE = 49152;
static constexpr uint32_t GEMM_SMEM = 3 * STAGE;   // 144KB

__global__ __launch_bounds__(512, 1) void mma_gemm(
    const float* __restrict__ A, const float* __restrict__ B, float* __restrict__ C,
    int K, int ldb, int ldc)
{
    extern __shared__ char smem[];
    const uint32_t sbase = smem_u32(smem);
    const int tid  = threadIdx.x;
    const int lane = tid & 31;
    const int w    = tid >> 5;
    const int wm   = w >> 2;          // 0..3
    const int wn   = w & 3;           // 0..3
    const int c4   = lane & 3;
    const int g    = lane >> 2;       // 0..7
    const int row0 = blockIdx.y * 256;
    const int col0 = blockIdx.x * 128;

    float acc[4][4][4];
#pragma unroll
    for (int mi = 0; mi < 4; mi++)
#pragma unroll
        for (int ni = 0; ni < 4; ni++)
#pragma unroll
            for (int q = 0; q < 4; q++) acc[mi][ni][q] = 0.f;

    const int nt = K >> 5;

    auto issue = [&](int t, int st) {
        const int k0 = t << 5;
        const uint32_t sA = sbase + st * STAGE;
        const uint32_t sB = sA + 32768;
#pragma unroll
        for (int it = 0; it < 4; it++) {
            int idx = it * 512 + tid;          // 0..2047
            int r = idx >> 3, f = idx & 7;     // row 0..255, 16B-chunk 0..7
            cp16(sA + r * 128 + ((f ^ (r & 7)) << 4),
                 A + (size_t)(row0 + r) * K + k0 + f * 4);
        }
#pragma unroll
        for (int it = 0; it < 2; it++) {
            int idx = it * 512 + tid;          // 0..1023
            int k = idx >> 5, c = idx & 31;    // row 0..31, chunk 0..31
            cp16(sB + k * 512 + ((c ^ ((k & 3) << 1)) << 4),
                 B + (size_t)(k0 + k) * ldb + col0 + c * 4);
        }
    };

    auto compute = [&](int st) {
        const uint32_t sA = sbase + st * STAGE;
        const uint32_t sB = sA + 32768;
#pragma unroll
        for (int s = 0; s < 4; s++) {
            uint32_t af[4][4];
            uint32_t bf[4][2];
            const int f0 = 2 * s, f1 = 2 * s + 1;
#pragma unroll
            for (int mi = 0; mi < 4; mi++) {
                const int r = wm * 64 + mi * 16 + g;   // r & 7 == g
                const uint32_t base = sA + r * 128 + c4 * 4;
                af[mi][0] = lds32(base + ((f0 ^ g) << 4));
                af[mi][1] = lds32(base + 8 * 128 + ((f0 ^ g) << 4));
                af[mi][2] = lds32(base + ((f1 ^ g) << 4));
                af[mi][3] = lds32(base + 8 * 128 + ((f1 ^ g) << 4));
            }
            const int kk = 8 * s + c4;
#pragma unroll
            for (int ni = 0; ni < 4; ni++) {
                const int n = wn * 32 + ni * 8 + g;
                const uint32_t boff = ((uint32_t)((n >> 2) ^ (c4 << 1)) << 4) + (n & 3) * 4;
                bf[ni][0] = lds32(sB + kk * 512 + boff);
                bf[ni][1] = lds32(sB + (kk + 4) * 512 + boff);
            }
#pragma unroll
            for (int mi = 0; mi < 4; mi++)
#pragma unroll
                for (int ni = 0; ni < 4; ni++)
                    mma_tf32(acc[mi][ni], af[mi], bf[ni]);
        }
    };

    issue(0, 0); CP_COMMIT();
    issue(1, 1); CP_COMMIT();
    int st = 0;
    for (int t = 0; t < nt; t++) {
        if (t + 2 < nt) {
            CP_WAIT(1);
            __syncthreads();
            issue(t + 2, (st + 2) % 3);
            CP_COMMIT();
        } else {
            CP_WAIT(0);
            __syncthreads();
        }
        compute(st);
        st = (st + 1) % 3;
    }

#pragma unroll
    for (int mi = 0; mi < 4; mi++) {
        const int r0 = row0 + wm * 64 + mi * 16 + g;
#pragma unroll
        for (int ni = 0; ni < 4; ni++) {
            const int cc = col0 + wn * 32 + ni * 8 + 2 * c4;
            *(float2*)(C + (size_t)r0 * ldc + cc) =
                make_float2(acc[mi][ni][0], acc[mi][ni][1]);
            *(float2*)(C + (size_t)(r0 + 8) * ldc + cc) =
                make_float2(acc[mi][ni][2], acc[mi][ni][3]);
        }
    }
}

// =====================================================================
// Pack + tf32-round all projection weights into Wp[2048, 12544]
// =====================================================================
__global__ void pack_w(const float* __restrict__ Wq, const float* __restrict__ Wk,
                       const float* __restrict__ Wv, const float* __restrict__ Wg,
                       const float* __restrict__ Wa, const float* __restrict__ Wb,
                       float* __restrict__ P)
{
    int idx = blockIdx.x * 256 + threadIdx.x;   // 2048 * 3136
    int k = idx / 3136;
    int n = (idx - k * 3136) * 4;
    float4 v = make_float4(0.f, 0.f, 0.f, 0.f);
    if      (n < OFF_K)   v = *(const float4*)(Wq + (size_t)k * 2048 + n);
    else if (n < OFF_V)   v = *(const float4*)(Wk + (size_t)k * 2048 + n - OFF_K);
    else if (n < OFF_G)   v = *(const float4*)(Wv + (size_t)k * 4096 + n - OFF_V);
    else if (n < OFF_A)   v = *(const float4*)(Wg + (size_t)k * 4096 + n - OFF_G);
    else if (n < OFF_B2)  v = *(const float4*)(Wa + (size_t)k * 32 + n - OFF_A);
    else if (n < OFF_END) v = *(const float4*)(Wb + (size_t)k * 32 + n - OFF_B2);
    v.x = tf32r(v.x); v.y = tf32r(v.y); v.z = tf32r(v.z); v.w = tf32r(v.w);
    *(float4*)(P + (size_t)k * NPACK + n) = v;
}

// tf32-round copy
__global__ void round_copy(const float* __restrict__ src, float* __restrict__ dst)
{
    int i = (blockIdx.x * 256 + threadIdx.x) * 4;
    float4 v = *(const float4*)(src + i);
    v.x = tf32r(v.x); v.y = tf32r(v.y); v.z = tf32r(v.z); v.w = tf32r(v.w);
    *(float4*)(dst + i) = v;
}

// =====================================================================
// Causal depthwise conv (K=4) + SiLU; input stride NPACK, output 8192
// =====================================================================
__global__ void conv_silu(const float* __restrict__ big,
                          const float* __restrict__ cq,
                          const float* __restrict__ ck,
                          const float* __restrict__ cv,
                          float* __restrict__ acts)
{
    int gid = blockIdx.x * blockDim.x + threadIdx.x;
    int t = gid >> 11;
    int c = (gid & 2047) << 2;
    const float* wp = (c < 2048) ? (cq + c * 4)
                    : (c < 4096) ? (ck + (c - 2048) * 4)
                                 : (cv + (c - 4096) * 4);
    float4 w0 = *(const float4*)(wp + 0);
    float4 w1 = *(const float4*)(wp + 4);
    float4 w2 = *(const float4*)(wp + 8);
    float4 w3 = *(const float4*)(wp + 12);
    const float* xp = big + (size_t)t * NPACK + c;
    float4 z  = make_float4(0.f, 0.f, 0.f, 0.f);
    float4 x3 = *(const float4*)xp;
    float4 x2 = (t >= 1) ? *(const float4*)(xp - NPACK)     : z;
    float4 x1 = (t >= 2) ? *(const float4*)(xp - 2 * NPACK) : z;
    float4 x0 = (t >= 3) ? *(const float4*)(xp - 3 * NPACK) : z;
    float4 o;
    o.x = w0.x * x0.x + w0.y * x1.x + w0.z * x2.x + w0.w * x3.x;
    o.y = w1.x * x0.y + w1.y * x1.y + w1.z * x2.y + w1.w * x3.y;
    o.z = w2.x * x0.z + w2.y * x1.z + w2.z * x2.z + w2.w * x3.z;
    o.w = w3.x * x0.w + w3.y * x1.w + w3.z * x2.w + w3.w * x3.w;
    o.x = o.x / (1.f + expf(-o.x));
    o.y = o.y / (1.f + expf(-o.y));
    o.z = o.z / (1.f + expf(-o.z));
    o.w = o.w / (1.f + expf(-o.w));
    *(float4*)(acts + (size_t)t * 8192 + c) = o;
}

// =====================================================================
__global__ void gate_beta(const float* __restrict__ big,
                          const float* __restrict__ dtb, const float* __restrict__ Alg,
                          float* __restrict__ eg, float* __restrict__ bt)
{
    int i = blockIdx.x * blockDim.x + threadIdx.x;   // T_*NH
    int t = i >> 5, h = i & 31;
    float x  = big[(size_t)t * NPACK + OFF_A + h] + dtb[h];
    float sp = (x <= 20.f) ? log1pf(expf(x)) : x;
    eg[i] = expf(-expf(Alg[h]) * sp);
    float xb = big[(size_t)t * NPACK + OFF_B2 + h];
    bt[i] = 1.f / (1.f + expf(-xb));
}

// =====================================================================
__global__ void qknorm(const float* __restrict__ acts,
                       float* __restrict__ qn, float* __restrict__ kn)
{
    int wid  = (blockIdx.x * blockDim.x + threadIdx.x) >> 5;
    int lane = threadIdx.x & 31;
    int t     = wid >> 5;
    int hh    = (wid >> 1) & 15;
    int which = wid & 1;
    const float* src = acts + (size_t)t * 8192 + which * 2048 + hh * 128 + lane * 4;
    float4 x = *(const float4*)src;
    float ss = x.x * x.x + x.y * x.y + x.z * x.z + x.w * x.w;
#pragma unroll
    for (int off = 16; off; off >>= 1) ss += __shfl_xor_sync(0xffffffffu, ss, off);
    float s = rsqrtf(ss + 1e-6f);
    if (which == 0) s *= 0.08838834764831845f;
    float* dst = (which == 0 ? qn : kn) + (size_t)t * 2048 + hh * 128 + lane * 4;
    *(float4*)dst = make_float4(x.x * s, x.y * s, x.z * s, x.w * s);
}

// =====================================================================
// Gated delta-rule scan. Grid (8 dv-tiles, 32 heads), 128 threads.
// =====================================================================
__global__ __launch_bounds__(128) void gdn_scan(
    const float* __restrict__ qn, const float* __restrict__ kn,
    const float* __restrict__ acts, const float* __restrict__ eg,
    const float* __restrict__ bt, float* __restrict__ o)
{
    const int h    = blockIdx.y;
    const int dvt  = blockIdx.x;
    const int hk   = h >> 1;
    const int tid  = threadIdx.x;
    const int w    = tid >> 5;
    const int lane = tid & 31;
    const int dv0  = dvt * 16 + w * 4;

    __shared__ float sq[32][128];
    __shared__ float sk[32][128];
    __shared__ float sv[32][16];
    __shared__ float se[32];
    __shared__ float sb[32];

    float S[4][4];
#pragma unroll
    for (int i = 0; i < 4; i++)
#pragma unroll
        for (int j = 0; j < 4; j++) S[i][j] = 0.f;

    for (int t0 = 0; t0 < T_; t0 += 32) {
        __syncthreads();
        for (int i = tid; i < 32 * 128; i += 128) {
            int tt = i >> 7, cc = i & 127;
            sq[tt][cc] = qn[(size_t)(t0 + tt) * 2048 + hk * 128 + cc];
            sk[tt][cc] = kn[(size_t)(t0 + tt) * 2048 + hk * 128 + cc];
        }
        for (int i = tid; i < 32 * 16; i += 128) {
            int tt = i >> 4, j = i & 15;
            sv[tt][j] = acts[(size_t)(t0 + tt) * 8192 + 4096 + h * 128 + dvt * 16 + j];
        }
        if (tid < 32) {
            se[tid] = eg[(t0 + tid) * 32 + h];
            sb[tid] = bt[(t0 + tid) * 32 + h];
        }
        __syncthreads();
#pragma unroll 1
        for (int tt = 0; tt < 32; tt++) {
            float kk[4], qq[4], vv[4];
#pragma unroll
            for (int i = 0; i < 4; i++) { kk[i] = sk[tt][lane + 32 * i]; qq[i] = sq[tt][lane + 32 * i]; }
#pragma unroll
            for (int j = 0; j < 4; j++) vv[j] = sv[tt][w * 4 + j];
            float e = se[tt], b = sb[tt];
            float kv[4] = {0.f, 0.f, 0.f, 0.f};
            float oq[4] = {0.f, 0.f, 0.f, 0.f};
            float qkr = 0.f;
#pragma unroll
            for (int i = 0; i < 4; i++) {
                qkr = fmaf(qq[i], kk[i], qkr);
#pragma unroll
                for (int j = 0; j < 4; j++) {
                    float s = S[i][j] * e;
                    S[i][j] = s;
                    kv[j] = fmaf(kk[i], s, kv[j]);
                    oq[j] = fmaf(qq[i], s, oq[j]);
                }
            }
#pragma unroll
            for (int off = 16; off; off >>= 1) {
#pragma unroll
                for (int j = 0; j < 4; j++) {
                    kv[j] += __shfl_xor_sync(0xffffffffu, kv[j], off);
                    oq[j] += __shfl_xor_sync(0xffffffffu, oq[j], off);
                }
                qkr += __shfl_xor_sync(0xffffffffu, qkr, off);
            }
            float d[4];
#pragma unroll
            for (int j = 0; j < 4; j++) {
                d[j] = b * (vv[j] - kv[j]);
#pragma unroll
                for (int i = 0; i < 4; i++) S[i][j] = fmaf(kk[i], d[j], S[i][j]);
            }
            float ov = 0.f;
#pragma unroll
            for (int j = 0; j < 4; j++) if (lane == j) ov = fmaf(qkr, d[j], oq[j]);
            if (lane < 4)
                o[(size_t)(t0 + tt) * 4096 + h * 128 + dv0 + lane] = ov;
        }
    }
}

// =====================================================================
// gated RMSNorm + silu(gate); writes tf32-rounded og for the Wo GEMM
// =====================================================================
__global__ void gate_norm(const float* __restrict__ o, const float* __restrict__ big,
                          const float* __restrict__ wn, float* __restrict__ og)
{
    int wid  = (blockIdx.x * blockDim.x + threadIdx.x) >> 5;
    int lane = threadIdx.x & 31;
    int t = wid >> 5;
    int h = wid & 31;
    size_t base = (size_t)t * 4096 + h * 128 + lane * 4;
    float4 x = *(const float4*)(o + base);
    float ss = x.x * x.x + x.y * x.y + x.z * x.z + x.w * x.w;
#pragma unroll
    for (int off = 16; off; off >>= 1) ss += __shfl_xor_sync(0xffffffffu, ss, off);
    float r = rsqrtf(ss * (1.f / 128.f) + 1e-5f);
    float4 gv = *(const float4*)(big + (size_t)t * NPACK + OFF_G + h * 128 + lane * 4);
    float4 wv = *(const float4*)(wn + lane * 4);
    float4 out;
    out.x = tf32r(x.x * r * wv.x * (gv.x / (1.f + expf(-gv.x))));
    out.y = tf32r(x.y * r * wv.y * (gv.y / (1.f + expf(-gv.y))));
    out.z = tf32r(x.z * r * wv.z * (gv.z / (1.f + expf(-gv.z))));
    out.w = tf32r(x.w * r * wv.w * (gv.w / (1.f + expf(-gv.w))));
    *(float4*)(og + base) = out;
}

// =====================================================================
extern "C" void kernel_launch(void* const* d_in, const int* in_sizes, int n_in,
                              void* d_out, int out_size)
{
    const float* h   = (const float*)d_in[0];
    const float* Wq  = (const float*)d_in[1];
    const float* Wk  = (const float*)d_in[2];
    const float* Wv  = (const float*)d_in[3];
    const float* Wa  = (const float*)d_in[4];
    const float* Wb  = (const float*)d_in[5];
    const float* Wg  = (const float*)d_in[6];
    const float* cq  = (const float*)d_in[7];
    const float* ck  = (const float*)d_in[8];
    const float* cv  = (const float*)d_in[9];
    const float* dtb = (const float*)d_in[10];
    const float* Alg = (const float*)d_in[11];
    const float* onw = (const float*)d_in[12];
    const float* Wo  = (const float*)d_in[13];
    float* out = (float*)d_out;

    float *big, *Wp, *hr, *WoR, *acts, *eg, *bt, *qn, *kn, *o, *og;
    cudaGetSymbolAddress((void**)&big,  g_big);
    cudaGetSymbolAddress((void**)&Wp,   g_Wp);
    cudaGetSymbolAddress((void**)&hr,   g_hr);
    cudaGetSymbolAddress((void**)&WoR,  g_WoR);
    cudaGetSymbolAddress((void**)&acts, g_acts);
    cudaGetSymbolAddress((void**)&eg,   g_eg);
    cudaGetSymbolAddress((void**)&bt,   g_bt);
    cudaGetSymbolAddress((void**)&qn,   g_qn);
    cudaGetSymbolAddress((void**)&kn,   g_kn);
    cudaGetSymbolAddress((void**)&o,    g_o);
    cudaGetSymbolAddress((void**)&og,   g_og);

    cudaFuncSetAttribute(mma_gemm, cudaFuncAttributeMaxDynamicSharedMemorySize, GEMM_SMEM);

    // pre-round / pack (tf32)
    round_copy<<<(2048 * 2048 / 4) / 256, 256>>>(h, hr);
    round_copy<<<(4096 * 2048 / 4) / 256, 256>>>(Wo, WoR);
    pack_w<<<2048 * 3136 / 256, 256>>>(Wq, Wk, Wv, Wg, Wa, Wb, Wp);

    // fused projection GEMM: big = hr @ Wp  [2048 x 12544]
    mma_gemm<<<dim3(98, 8), 512, GEMM_SMEM>>>(hr, Wp, big, 2048, NPACK, NPACK);

    gate_beta<<<256, 256>>>(big, dtb, Alg, eg, bt);
    conv_silu<<<16384, 256>>>(big, cq, ck, cv, acts);
    qknorm<<<8192, 256>>>(acts, qn, kn);
    gdn_scan<<<dim3(8, 32), 128>>>(qn, kn, acts, eg, bt, o);
    gate_norm<<<8192, 256>>>(o, big, onw, og);

    // output projection: out = og @ WoR  [2048 x 2048], K=4096
    mma_gemm<<<dim3(16, 8), 512, GEMM_SMEM>>>(og, WoR, out, 4096, 2048, 2048);
}

// round 7
// speedup vs baseline: 3.5969x; 1.3180x over previous
#include <cuda_runtime.h>
#include <math.h>
#include <cstdint>

static constexpr int T_   = 2048;
static constexpr int NH   = 32;
static constexpr int NPACK = 12544;   // q(2048) k(2048) v(4096) g(4096) a(32) b(32) pad(192)
static constexpr int OFF_K = 2048;
static constexpr int OFF_V = 4096;
static constexpr int OFF_G = 8192;
static constexpr int OFF_A = 12288;
static constexpr int OFF_B2 = 12320;
static constexpr int OFF_END = 12352;

// ---- scratch (static __device__ arrays; no runtime allocation) ----
__device__ float g_big [T_ * NPACK];   // fused projection output (q|k|v|gate|xa|xb)
__device__ float g_Wp  [2048 * NPACK]; // packed + tf32-rounded weights
__device__ float g_hr  [T_ * 2048];    // tf32-rounded h
__device__ float g_WoR [4096 * 2048];  // tf32-rounded Wo
__device__ float g_acts[T_ * 8192];    // conv+silu output (q|k|v), stride 8192
__device__ float g_egT [NH * T_];      // exp(g), transposed [h][t]
__device__ float g_btT [NH * T_];      // beta, transposed [h][t]
__device__ float g_qn  [T_ * 2048];    // l2-normed q, dk-permuted rows
__device__ float g_kn  [T_ * 2048];    // l2-normed k, dk-permuted rows
__device__ float g_o   [T_ * 4096];
__device__ float g_og  [T_ * 4096];    // normed+gated, tf32-rounded

// round f32 -> tf32 (round-to-nearest) as an f32 bit pattern
__device__ __forceinline__ float tf32r(float x) {
    uint32_t u;
    asm("cvt.rna.tf32.f32 %0, %1;" : "=r"(u) : "f"(x));
    return __uint_as_float(u);
}

__device__ __forceinline__ uint32_t smem_u32(const void* p) {
    uint32_t a;
    asm("{ .reg .u64 t; cvta.to.shared.u64 t, %1; cvt.u32.u64 %0, t; }" : "=r"(a) : "l"(p));
    return a;
}
__device__ __forceinline__ void cp16(uint32_t dst, const void* src) {
    asm volatile("cp.async.cg.shared.global [%0], [%1], 16;" :: "r"(dst), "l"(src));
}
#define CP_COMMIT() asm volatile("cp.async.commit_group;" ::: "memory")
#define CP_WAIT(n)  asm volatile("cp.async.wait_group %0;" :: "n"(n) : "memory")

__device__ __forceinline__ uint32_t lds32(uint32_t a) {
    uint32_t v;
    asm volatile("ld.shared.b32 %0, [%1];" : "=r"(v) : "r"(a));
    return v;
}

__device__ __forceinline__ void mma_tf32(float* c, const uint32_t* a, const uint32_t* b) {
    asm volatile("mma.sync.aligned.m16n8k8.row.col.f32.tf32.tf32.f32 "
        "{%0,%1,%2,%3}, {%4,%5,%6,%7}, {%8,%9}, {%0,%1,%2,%3};"
        : "+f"(c[0]), "+f"(c[1]), "+f"(c[2]), "+f"(c[3])
        : "r"(a[0]), "r"(a[1]), "r"(a[2]), "r"(a[3]), "r"(b[0]), "r"(b[1]));
}

// =====================================================================
// tf32 mma.sync GEMM: C[M, N] = A[M, K] @ B[K, N], both tf32-rounded,
// plain row-major. CTA tile 256(M) x 128(N), BK=32, 512 threads
// (16 warps, 4x4), warp tile 64x32. 3-stage cp.async pipeline.
// Rasterization: blockIdx.x = row-tile (fast), blockIdx.y = col-tile,
// so consecutive CTAs share the same B columns (L2-friendly).
// =====================================================================
static constexpr uint32_t STAGE = 49152;
static constexpr uint32_t GEMM_SMEM = 3 * STAGE;   // 144KB

__global__ __launch_bounds__(512, 1) void mma_gemm(
    const float* __restrict__ A, const float* __restrict__ B, float* __restrict__ C,
    int K, int ldb, int ldc)
{
    extern __shared__ char smem[];
    const uint32_t sbase = smem_u32(smem);
    const int tid  = threadIdx.x;
    const int lane = tid & 31;
    const int w    = tid >> 5;
    const int wm   = w >> 2;          // 0..3
    const int wn   = w & 3;           // 0..3
    const int c4   = lane & 3;
    const int g    = lane >> 2;       // 0..7
    const int row0 = blockIdx.x * 256;
    const int col0 = blockIdx.y * 128;

    float acc[4][4][4];
#pragma unroll
    for (int mi = 0; mi < 4; mi++)
#pragma unroll
        for (int ni = 0; ni < 4; ni++)
#pragma unroll
            for (int q = 0; q < 4; q++) acc[mi][ni][q] = 0.f;

    const int nt = K >> 5;

    auto issue = [&](int t, int st) {
        const int k0 = t << 5;
        const uint32_t sA = sbase + st * STAGE;
        const uint32_t sB = sA + 32768;
#pragma unroll
        for (int it = 0; it < 4; it++) {
            int idx = it * 512 + tid;          // 0..2047
            int r = idx >> 3, f = idx & 7;     // row 0..255, 16B-chunk 0..7
            cp16(sA + r * 128 + ((f ^ (r & 7)) << 4),
                 A + (size_t)(row0 + r) * K + k0 + f * 4);
        }
#pragma unroll
        for (int it = 0; it < 2; it++) {
            int idx = it * 512 + tid;          // 0..1023
            int k = idx >> 5, c = idx & 31;    // row 0..31, chunk 0..31
            cp16(sB + k * 512 + ((c ^ ((k & 3) << 1)) << 4),
                 B + (size_t)(k0 + k) * ldb + col0 + c * 4);
        }
    };

    auto compute = [&](int st) {
        const uint32_t sA = sbase + st * STAGE;
        const uint32_t sB = sA + 32768;
#pragma unroll
        for (int s = 0; s < 4; s++) {
            uint32_t af[4][4];
            uint32_t bf[4][2];
            const int f0 = 2 * s, f1 = 2 * s + 1;
#pragma unroll
            for (int mi = 0; mi < 4; mi++) {
                const int r = wm * 64 + mi * 16 + g;   // r & 7 == g
                const uint32_t base = sA + r * 128 + c4 * 4;
                af[mi][0] = lds32(base + ((f0 ^ g) << 4));
                af[mi][1] = lds32(base + 8 * 128 + ((f0 ^ g) << 4));
                af[mi][2] = lds32(base + ((f1 ^ g) << 4));
                af[mi][3] = lds32(base + 8 * 128 + ((f1 ^ g) << 4));
            }
            const int kk = 8 * s + c4;
#pragma unroll
            for (int ni = 0; ni < 4; ni++) {
                const int n = wn * 32 + ni * 8 + g;
                const uint32_t boff = ((uint32_t)((n >> 2) ^ (c4 << 1)) << 4) + (n & 3) * 4;
                bf[ni][0] = lds32(sB + kk * 512 + boff);
                bf[ni][1] = lds32(sB + (kk + 4) * 512 + boff);
            }
#pragma unroll
            for (int mi = 0; mi < 4; mi++)
#pragma unroll
                for (int ni = 0; ni < 4; ni++)
                    mma_tf32(acc[mi][ni], af[mi], bf[ni]);
        }
    };

    issue(0, 0); CP_COMMIT();
    issue(1, 1); CP_COMMIT();
    int st = 0;
    for (int t = 0; t < nt; t++) {
        if (t + 2 < nt) {
            CP_WAIT(1);
            __syncthreads();
            issue(t + 2, (st + 2) % 3);
            CP_COMMIT();
        } else {
            CP_WAIT(0);
            __syncthreads();
        }
        compute(st);
        st = (st + 1) % 3;
    }

#pragma unroll
    for (int mi = 0; mi < 4; mi++) {
        const int r0 = row0 + wm * 64 + mi * 16 + g;
#pragma unroll
        for (int ni = 0; ni < 4; ni++) {
            const int cc = col0 + wn * 32 + ni * 8 + 2 * c4;
            *(float2*)(C + (size_t)r0 * ldc + cc) =
                make_float2(acc[mi][ni][0], acc[mi][ni][1]);
            *(float2*)(C + (size_t)(r0 + 8) * ldc + cc) =
                make_float2(acc[mi][ni][2], acc[mi][ni][3]);
        }
    }
}

// =====================================================================
// Pack + tf32-round all projection weights into Wp[2048, 12544]
// =====================================================================
__global__ void pack_w(const float* __restrict__ Wq, const float* __restrict__ Wk,
                       const float* __restrict__ Wv, const float* __restrict__ Wg,
                       const float* __restrict__ Wa, const float* __restrict__ Wb,
                       float* __restrict__ P)
{
    int idx = blockIdx.x * 256 + threadIdx.x;   // 2048 * 3136
    int k = idx / 3136;
    int n = (idx - k * 3136) * 4;
    float4 v = make_float4(0.f, 0.f, 0.f, 0.f);
    if      (n < OFF_K)   v = *(const float4*)(Wq + (size_t)k * 2048 + n);
    else if (n < OFF_V)   v = *(const float4*)(Wk + (size_t)k * 2048 + n - OFF_K);
    else if (n < OFF_G)   v = *(const float4*)(Wv + (size_t)k * 4096 + n - OFF_V);
    else if (n < OFF_A)   v = *(const float4*)(Wg + (size_t)k * 4096 + n - OFF_G);
    else if (n < OFF_B2)  v = *(const float4*)(Wa + (size_t)k * 32 + n - OFF_A);
    else if (n < OFF_END) v = *(const float4*)(Wb + (size_t)k * 32 + n - OFF_B2);
    v.x = tf32r(v.x); v.y = tf32r(v.y); v.z = tf32r(v.z); v.w = tf32r(v.w);
    *(float4*)(P + (size_t)k * NPACK + n) = v;
}

// tf32-round copy
__global__ void round_copy(const float* __restrict__ src, float* __restrict__ dst)
{
    int i = (blockIdx.x * 256 + threadIdx.x) * 4;
    float4 v = *(const float4*)(src + i);
    v.x = tf32r(v.x); v.y = tf32r(v.y); v.z = tf32r(v.z); v.w = tf32r(v.w);
    *(float4*)(dst + i) = v;
}

// =====================================================================
// Causal depthwise conv (K=4) + SiLU, fused with gate/beta computation.
// Blocks [0, 16384): conv path. Blocks [16384, 16640): gate/beta path.
// =====================================================================
__global__ void conv_gate(const float* __restrict__ big,
                          const float* __restrict__ cq,
                          const float* __restrict__ ck,
                          const float* __restrict__ cv,
                          const float* __restrict__ dtb,
                          const float* __restrict__ Alg,
                          float* __restrict__ acts,
                          float* __restrict__ egT,
                          float* __restrict__ btT)
{
    if (blockIdx.x >= 16384) {
        int i = (blockIdx.x - 16384) * 256 + threadIdx.x;   // T_*NH
        int t = i >> 5, hh = i & 31;
        float x  = big[(size_t)t * NPACK + OFF_A + hh] + dtb[hh];
        float sp = (x <= 20.f) ? log1pf(expf(x)) : x;
        egT[(size_t)hh * T_ + t] = expf(-expf(Alg[hh]) * sp);
        float xb = big[(size_t)t * NPACK + OFF_B2 + hh];
        btT[(size_t)hh * T_ + t] = 1.f / (1.f + expf(-xb));
        return;
    }
    int gid = blockIdx.x * blockDim.x + threadIdx.x;
    int t = gid >> 11;
    int c = (gid & 2047) << 2;
    const float* wp = (c < 2048) ? (cq + c * 4)
                    : (c < 4096) ? (ck + (c - 2048) * 4)
                                 : (cv + (c - 4096) * 4);
    float4 w0 = *(const float4*)(wp + 0);
    float4 w1 = *(const float4*)(wp + 4);
    float4 w2 = *(const float4*)(wp + 8);
    float4 w3 = *(const float4*)(wp + 12);
    const float* xp = big + (size_t)t * NPACK + c;
    float4 z  = make_float4(0.f, 0.f, 0.f, 0.f);
    float4 x3 = *(const float4*)xp;
    float4 x2 = (t >= 1) ? *(const float4*)(xp - NPACK)     : z;
    float4 x1 = (t >= 2) ? *(const float4*)(xp - 2 * NPACK) : z;
    float4 x0 = (t >= 3) ? *(const float4*)(xp - 3 * NPACK) : z;
    float4 o;
    o.x = w0.x * x0.x + w0.y * x1.x + w0.z * x2.x + w0.w * x3.x;
    o.y = w1.x * x0.y + w1.y * x1.y + w1.z * x2.y + w1.w * x3.y;
    o.z = w2.x * x0.z + w2.y * x1.z + w2.z * x2.z + w2.w * x3.z;
    o.w = w3.x * x0.w + w3.y * x1.w + w3.z * x2.w + w3.w * x3.w;
    o.x = o.x / (1.f + expf(-o.x));
    o.y = o.y / (1.f + expf(-o.y));
    o.z = o.z / (1.f + expf(-o.z));
    o.w = o.w / (1.f + expf(-o.w));
    *(float4*)(acts + (size_t)t * 8192 + c) = o;
}

// =====================================================================
// l2norm over head_dim=128 for q (scaled) and k, with dk-PERMUTED store:
// element c -> position (c & 15)*8 + (c >> 4) within the 128-float row.
// (So the scan's lane dkg finds its 8 dk values {dkg, dkg+16, ...}
//  contiguous at [dkg*8, dkg*8+8).)
// =====================================================================
__global__ void qknorm(const float* __restrict__ acts,
                       float* __restrict__ qn, float* __restrict__ kn)
{
    int wid  = (blockIdx.x * blockDim.x + threadIdx.x) >> 5;
    int lane = threadIdx.x & 31;
    int t     = wid >> 5;
    int hh    = (wid >> 1) & 15;
    int which = wid & 1;
    const float* src = acts + (size_t)t * 8192 + which * 2048 + hh * 128 + lane * 4;
    float4 x = *(const float4*)src;
    float ss = x.x * x.x + x.y * x.y + x.z * x.z + x.w * x.w;
#pragma unroll
    for (int off = 16; off; off >>= 1) ss += __shfl_xor_sync(0xffffffffu, ss, off);
    float s = rsqrtf(ss + 1e-6f);
    if (which == 0) s *= 0.08838834764831845f;   // DK^-0.5
    float* dst = (which == 0 ? qn : kn) + (size_t)t * 2048 + hh * 128;
    float v[4] = {x.x * s, x.y * s, x.z * s, x.w * s};
#pragma unroll
    for (int j = 0; j < 4; j++) {
        int c = lane * 4 + j;
        dst[((c & 15) << 3) + (c >> 4)] = v[j];
    }
}

// =====================================================================
// Gated delta-rule scan v2. Grid (8 dv-tiles, 32 heads), 128 threads.
// lane = dkg*2 + dvg: dkg in [0,16) owns dk {dkg+16i}, dvg in {0,1}
// owns 2 dv columns. Warp covers 128 dk x 4 dv; block 16 dv.
// Fused decay (S kept un-decayed through the reductions), 4-round
// butterfly over 16 dkg lanes, cp.async double-buffered 32-step chunks.
// =====================================================================
__global__ __launch_bounds__(128) void gdn_scan(
    const float* __restrict__ qp, const float* __restrict__ kp,
    const float* __restrict__ acts, const float* __restrict__ egT,
    const float* __restrict__ btT, float* __restrict__ o)
{
    const int h    = blockIdx.y;
    const int dvt  = blockIdx.x;
    const int hk   = h >> 1;
    const int tid  = threadIdx.x;
    const int w    = tid >> 5;
    const int lane = tid & 31;
    const int dkg  = lane >> 1;
    const int dvg  = lane & 1;

    __shared__ float sq[2][32][128];
    __shared__ float sk[2][32][128];
    __shared__ float sv[2][32][16];
    __shared__ float se[2][32];
    __shared__ float sb[2][32];

    auto fill = [&](int buf, int t0) {
#pragma unroll
        for (int it = 0; it < 8; it++) {
            int idx = it * 128 + tid;          // 0..1023
            int tt = idx >> 5, f = (idx & 31) << 2;
            const float* qsrc = qp + (size_t)(t0 + tt) * 2048 + hk * 128 + f;
            const float* ksrc = kp + (size_t)(t0 + tt) * 2048 + hk * 128 + f;
            cp16(smem_u32(&sq[buf][tt][f]), qsrc);
            cp16(smem_u32(&sk[buf][tt][f]), ksrc);
        }
        {
            int tt = tid >> 2, f = (tid & 3) << 2;
            cp16(smem_u32(&sv[buf][tt][f]),
                 acts + (size_t)(t0 + tt) * 8192 + 4096 + h * 128 + dvt * 16 + f);
        }
        if (tid < 8)
            cp16(smem_u32(&se[buf][tid << 2]), egT + (size_t)h * T_ + t0 + (tid << 2));
        else if (tid < 16)
            cp16(smem_u32(&sb[buf][(tid - 8) << 2]), btT + (size_t)h * T_ + t0 + ((tid - 8) << 2));
    };

    float S[8][2];
#pragma unroll
    for (int i = 0; i < 8; i++) { S[i][0] = 0.f; S[i][1] = 0.f; }

    fill(0, 0); CP_COMMIT();

    for (int c = 0; c < 64; c++) {
        const int buf = c & 1;
        if (c + 1 < 64) { fill(buf ^ 1, (c + 1) << 5); CP_COMMIT(); CP_WAIT(1); }
        else            { CP_WAIT(0); }
        __syncthreads();
#pragma unroll 1
        for (int tt = 0; tt < 32; tt++) {
            float4 k0 = *(const float4*)&sk[buf][tt][dkg << 3];
            float4 k1 = *(const float4*)&sk[buf][tt][(dkg << 3) + 4];
            float4 q0 = *(const float4*)&sq[buf][tt][dkg << 3];
            float4 q1 = *(const float4*)&sq[buf][tt][(dkg << 3) + 4];
            float2 vv = *(const float2*)&sv[buf][tt][(w << 2) + (dvg << 1)];
            float e = se[buf][tt], b = sb[buf][tt];
            float kf[8] = {k0.x, k0.y, k0.z, k0.w, k1.x, k1.y, k1.z, k1.w};
            float qf[8] = {q0.x, q0.y, q0.z, q0.w, q1.x, q1.y, q1.z, q1.w};
            float kv0 = 0.f, kv1 = 0.f, oq0 = 0.f, oq1 = 0.f, qk = 0.f;
#pragma unroll
            for (int i = 0; i < 8; i++) {
                qk  = fmaf(qf[i], kf[i], qk);
                kv0 = fmaf(kf[i], S[i][0], kv0);
                kv1 = fmaf(kf[i], S[i][1], kv1);
                oq0 = fmaf(qf[i], S[i][0], oq0);
                oq1 = fmaf(qf[i], S[i][1], oq1);
            }
#pragma unroll
            for (int m = 2; m <= 16; m <<= 1) {
                kv0 += __shfl_xor_sync(0xffffffffu, kv0, m);
                kv1 += __shfl_xor_sync(0xffffffffu, kv1, m);
                oq0 += __shfl_xor_sync(0xffffffffu, oq0, m);
                oq1 += __shfl_xor_sync(0xffffffffu, oq1, m);
                qk  += __shfl_xor_sync(0xffffffffu, qk,  m);
            }
            float d0 = b * (vv.x - e * kv0);
            float d1 = b * (vv.y - e * kv1);
#pragma unroll
            for (int i = 0; i < 8; i++) {
                S[i][0] = fmaf(S[i][0], e, kf[i] * d0);
                S[i][1] = fmaf(S[i][1], e, kf[i] * d1);
            }
            if (dkg == 0) {
                float2 ov = make_float2(fmaf(qk, d0, e * oq0), fmaf(qk, d1, e * oq1));
                *(float2*)(o + (size_t)((c << 5) + tt) * 4096 + h * 128
                             + dvt * 16 + (w << 2) + (dvg << 1)) = ov;
            }
        }
        __syncthreads();
    }
}

// =====================================================================
// gated RMSNorm + silu(gate); writes tf32-rounded og for the Wo GEMM
// =====================================================================
__global__ void gate_norm(const float* __restrict__ o, const float* __restrict__ big,
                          const float* __restrict__ wn, float* __restrict__ og)
{
    int wid  = (blockIdx.x * blockDim.x + threadIdx.x) >> 5;
    int lane = threadIdx.x & 31;
    int t = wid >> 5;
    int h = wid & 31;
    size_t base = (size_t)t * 4096 + h * 128 + lane * 4;
    float4 x = *(const float4*)(o + base);
    float ss = x.x * x.x + x.y * x.y + x.z * x.z + x.w * x.w;
#pragma unroll
    for (int off = 16; off; off >>= 1) ss += __shfl_xor_sync(0xffffffffu, ss, off);
    float r = rsqrtf(ss * (1.f / 128.f) + 1e-5f);
    float4 gv = *(const float4*)(big + (size_t)t * NPACK + OFF_G + h * 128 + lane * 4);
    float4 wv = *(const float4*)(wn + lane * 4);
    float4 out;
    out.x = tf32r(x.x * r * wv.x * (gv.x / (1.f + expf(-gv.x))));
    out.y = tf32r(x.y * r * wv.y * (gv.y / (1.f + expf(-gv.y))));
    out.z = tf32r(x.z * r * wv.z * (gv.z / (1.f + expf(-gv.z))));
    out.w = tf32r(x.w * r * wv.w * (gv.w / (1.f + expf(-gv.w))));
    *(float4*)(og + base) = out;
}

// =====================================================================
extern "C" void kernel_launch(void* const* d_in, const int* in_sizes, int n_in,
                              void* d_out, int out_size)
{
    const float* h   = (const float*)d_in[0];
    const float* Wq  = (const float*)d_in[1];
    const float* Wk  = (const float*)d_in[2];
    const float* Wv  = (const float*)d_in[3];
    const float* Wa  = (const float*)d_in[4];
    const float* Wb  = (const float*)d_in[5];
    const float* Wg  = (const float*)d_in[6];
    const float* cq  = (const float*)d_in[7];
    const float* ck  = (const float*)d_in[8];
    const float* cv  = (const float*)d_in[9];
    const float* dtb = (const float*)d_in[10];
    const float* Alg = (const float*)d_in[11];
    const float* onw = (const float*)d_in[12];
    const float* Wo  = (const float*)d_in[13];
    float* out = (float*)d_out;

    float *big, *Wp, *hr, *WoR, *acts, *egT, *btT, *qn, *kn, *o, *og;
    cudaGetSymbolAddress((void**)&big,  g_big);
    cudaGetSymbolAddress((void**)&Wp,   g_Wp);
    cudaGetSymbolAddress((void**)&hr,   g_hr);
    cudaGetSymbolAddress((void**)&WoR,  g_WoR);
    cudaGetSymbolAddress((void**)&acts, g_acts);
    cudaGetSymbolAddress((void**)&egT,  g_egT);
    cudaGetSymbolAddress((void**)&btT,  g_btT);
    cudaGetSymbolAddress((void**)&qn,   g_qn);
    cudaGetSymbolAddress((void**)&kn,   g_kn);
    cudaGetSymbolAddress((void**)&o,    g_o);
    cudaGetSymbolAddress((void**)&og,   g_og);

    cudaFuncSetAttribute(mma_gemm, cudaFuncAttributeMaxDynamicSharedMemorySize, GEMM_SMEM);

    // 1: round h; 2: pack weights
    round_copy<<<(2048 * 2048 / 4) / 256, 256>>>(h, hr);
    pack_w<<<2048 * 3136 / 256, 256>>>(Wq, Wk, Wv, Wg, Wa, Wb, Wp);

    // 3: fused projection GEMM: big = hr @ Wp  [2048 x 12544]
    mma_gemm<<<dim3(8, 98), 512, GEMM_SMEM>>>(hr, Wp, big, 2048, NPACK, NPACK);

    // 4: conv+silu and gate/beta (merged)
    conv_gate<<<16640, 256>>>(big, cq, ck, cv, dtb, Alg, acts, egT, btT);
    // 5: qk l2norm (permuted store)
    qknorm<<<8192, 256>>>(acts, qn, kn);
    // 6: the scan (profiled launch)
    gdn_scan<<<dim3(8, 32), 128>>>(qn, kn, acts, egT, btT, o);
    // 7: gated rmsnorm
    gate_norm<<<8192, 256>>>(o, big, onw, og);
    // 8: round Wo
    round_copy<<<(4096 * 2048 / 4) / 256, 256>>>(Wo, WoR);
    // 9: output projection: out = og @ WoR  [2048 x 2048], K=4096
    mma_gemm<<<dim3(8, 16), 512, GEMM_SMEM>>>(og, WoR, out, 4096, 2048, 2048);
}

// round 8
// speedup vs baseline: 3.5994x; 1.0007x over previous
#include <cuda_runtime.h>
#include <math.h>
#include <cstdint>

static constexpr int T_   = 2048;
static constexpr int NH   = 32;
static constexpr int NPACK = 12544;   // q(2048) k(2048) v(4096) g(4096) a(32) b(32) pad(192)
static constexpr int OFF_K = 2048;
static constexpr int OFF_V = 4096;
static constexpr int OFF_G = 8192;
static constexpr int OFF_A = 12288;
static constexpr int OFF_B2 = 12320;
static constexpr int OFF_END = 12352;

// ---- scratch (static __device__ arrays; no runtime allocation) ----
__device__ float g_big [T_ * NPACK];   // fused projection output (q|k|v|gate|xa|xb)
__device__ float g_Wp  [2048 * NPACK]; // packed + tf32-rounded weights
__device__ float g_hr  [T_ * 2048];    // tf32-rounded h
__device__ float g_WoR [4096 * 2048];  // tf32-rounded Wo
__device__ float g_acts[T_ * 8192];    // conv+silu output (q|k|v), stride 8192
__device__ float g_egT [NH * T_];      // exp(g), transposed [h][t]
__device__ float g_btT [NH * T_];      // beta, transposed [h][t]
__device__ float g_qn  [T_ * 2048];    // l2-normed q, dk-permuted rows
__device__ float g_kn  [T_ * 2048];    // l2-normed k, dk-permuted rows
__device__ float g_o   [T_ * 4096];
__device__ float g_og  [T_ * 4096];    // normed+gated, tf32-rounded

// round f32 -> tf32 (round-to-nearest) as an f32 bit pattern
__device__ __forceinline__ float tf32r(float x) {
    uint32_t u;
    asm("cvt.rna.tf32.f32 %0, %1;" : "=r"(u) : "f"(x));
    return __uint_as_float(u);
}

__device__ __forceinline__ uint32_t smem_u32(const void* p) {
    uint32_t a;
    asm("{ .reg .u64 t; cvta.to.shared.u64 t, %1; cvt.u32.u64 %0, t; }" : "=r"(a) : "l"(p));
    return a;
}
__device__ __forceinline__ void cp16(uint32_t dst, const void* src) {
    asm volatile("cp.async.cg.shared.global [%0], [%1], 16;" :: "r"(dst), "l"(src));
}
#define CP_COMMIT() asm volatile("cp.async.commit_group;" ::: "memory")
#define CP_WAIT(n)  asm volatile("cp.async.wait_group %0;" :: "n"(n) : "memory")

__device__ __forceinline__ uint32_t lds32(uint32_t a) {
    uint32_t v;
    asm volatile("ld.shared.b32 %0, [%1];" : "=r"(v) : "r"(a));
    return v;
}

__device__ __forceinline__ void mma_tf32(float* c, const uint32_t* a, const uint32_t* b) {
    asm volatile("mma.sync.aligned.m16n8k8.row.col.f32.tf32.tf32.f32 "
        "{%0,%1,%2,%3}, {%4,%5,%6,%7}, {%8,%9}, {%0,%1,%2,%3};"
        : "+f"(c[0]), "+f"(c[1]), "+f"(c[2]), "+f"(c[3])
        : "r"(a[0]), "r"(a[1]), "r"(a[2]), "r"(a[3]), "r"(b[0]), "r"(b[1]));
}

// =====================================================================
// tf32 mma.sync GEMM: C[M, N] = A[M, K] @ B[K, N], both tf32-rounded,
// plain row-major. CTA tile 256(M) x 128(N), BK=32, 512 threads
// (16 warps, 4x4), warp tile 64x32. 3-stage cp.async pipeline.
// Rasterization: blockIdx.x = row-tile (fast), blockIdx.y = col-tile,
// so consecutive CTAs share the same B columns (L2-friendly).
// =====================================================================
static constexpr uint32_t STAGE = 49152;
static constexpr uint32_t GEMM_SMEM = 3 * STAGE;   // 144KB

__global__ __launch_bounds__(512, 1) void mma_gemm(
    const float* __restrict__ A, const float* __restrict__ B, float* __restrict__ C,
    int K, int ldb, int ldc)
{
    extern __shared__ char smem[];
    const uint32_t sbase = smem_u32(smem);
    const int tid  = threadIdx.x;
    const int lane = tid & 31;
    const int w    = tid >> 5;
    const int wm   = w >> 2;          // 0..3
    const int wn   = w & 3;           // 0..3
    const int c4   = lane & 3;
    const int g    = lane >> 2;       // 0..7
    const int row0 = blockIdx.x * 256;
    const int col0 = blockIdx.y * 128;

    float acc[4][4][4];
#pragma unroll
    for (int mi = 0; mi < 4; mi++)
#pragma unroll
        for (int ni = 0; ni < 4; ni++)
#pragma unroll
            for (int q = 0; q < 4; q++) acc[mi][ni][q] = 0.f;

    const int nt = K >> 5;

    auto issue = [&](int t, int st) {
        const int k0 = t << 5;
        const uint32_t sA = sbase + st * STAGE;
        const uint32_t sB = sA + 32768;
#pragma unroll
        for (int it = 0; it < 4; it++) {
            int idx = it * 512 + tid;          // 0..2047
            int r = idx >> 3, f = idx & 7;     // row 0..255, 16B-chunk 0..7
            cp16(sA + r * 128 + ((f ^ (r & 7)) << 4),
                 A + (size_t)(row0 + r) * K + k0 + f * 4);
        }
#pragma unroll
        for (int it = 0; it < 2; it++) {
            int idx = it * 512 + tid;          // 0..1023
            int k = idx >> 5, c = idx & 31;    // row 0..31, chunk 0..31
            cp16(sB + k * 512 + ((c ^ ((k & 3) << 1)) << 4),
                 B + (size_t)(k0 + k) * ldb + col0 + c * 4);
        }
    };

    auto compute = [&](int st) {
        const uint32_t sA = sbase + st * STAGE;
        const uint32_t sB = sA + 32768;
#pragma unroll
        for (int s = 0; s < 4; s++) {
            uint32_t af[4][4];
            uint32_t bf[4][2];
            const int f0 = 2 * s, f1 = 2 * s + 1;
#pragma unroll
            for (int mi = 0; mi < 4; mi++) {
                const int r = wm * 64 + mi * 16 + g;   // r & 7 == g
                const uint32_t base = sA + r * 128 + c4 * 4;
                af[mi][0] = lds32(base + ((f0 ^ g) << 4));
                af[mi][1] = lds32(base + 8 * 128 + ((f0 ^ g) << 4));
                af[mi][2] = lds32(base + ((f1 ^ g) << 4));
                af[mi][3] = lds32(base + 8 * 128 + ((f1 ^ g) << 4));
            }
            const int kk = 8 * s + c4;
#pragma unroll
            for (int ni = 0; ni < 4; ni++) {
                const int n = wn * 32 + ni * 8 + g;
                const uint32_t boff = ((uint32_t)((n >> 2) ^ (c4 << 1)) << 4) + (n & 3) * 4;
                bf[ni][0] = lds32(sB + kk * 512 + boff);
                bf[ni][1] = lds32(sB + (kk + 4) * 512 + boff);
            }
#pragma unroll
            for (int mi = 0; mi < 4; mi++)
#pragma unroll
                for (int ni = 0; ni < 4; ni++)
                    mma_tf32(acc[mi][ni], af[mi], bf[ni]);
        }
    };

    issue(0, 0); CP_COMMIT();
    issue(1, 1); CP_COMMIT();
    int st = 0;
    for (int t = 0; t < nt; t++) {
        if (t + 2 < nt) {
            CP_WAIT(1);
            __syncthreads();
            issue(t + 2, (st + 2) % 3);
            CP_COMMIT();
        } else {
            CP_WAIT(0);
            __syncthreads();
        }
        compute(st);
        st = (st + 1) % 3;
    }

#pragma unroll
    for (int mi = 0; mi < 4; mi++) {
        const int r0 = row0 + wm * 64 + mi * 16 + g;
#pragma unroll
        for (int ni = 0; ni < 4; ni++) {
            const int cc = col0 + wn * 32 + ni * 8 + 2 * c4;
            *(float2*)(C + (size_t)r0 * ldc + cc) =
                make_float2(acc[mi][ni][0], acc[mi][ni][1]);
            *(float2*)(C + (size_t)(r0 + 8) * ldc + cc) =
                make_float2(acc[mi][ni][2], acc[mi][ni][3]);
        }
    }
}

// =====================================================================
// Pack + tf32-round all projection weights into Wp[2048, 12544]
// =====================================================================
__global__ void pack_w(const float* __restrict__ Wq, const float* __restrict__ Wk,
                       const float* __restrict__ Wv, const float* __restrict__ Wg,
                       const float* __restrict__ Wa, const float* __restrict__ Wb,
                       float* __restrict__ P)
{
    int idx = blockIdx.x * 256 + threadIdx.x;   // 2048 * 3136
    int k = idx / 3136;
    int n = (idx - k * 3136) * 4;
    float4 v = make_float4(0.f, 0.f, 0.f, 0.f);
    if      (n < OFF_K)   v = *(const float4*)(Wq + (size_t)k * 2048 + n);
    else if (n < OFF_V)   v = *(const float4*)(Wk + (size_t)k * 2048 + n - OFF_K);
    else if (n < OFF_G)   v = *(const float4*)(Wv + (size_t)k * 4096 + n - OFF_V);
    else if (n < OFF_A)   v = *(const float4*)(Wg + (size_t)k * 4096 + n - OFF_G);
    else if (n < OFF_B2)  v = *(const float4*)(Wa + (size_t)k * 32 + n - OFF_A);
    else if (n < OFF_END) v = *(const float4*)(Wb + (size_t)k * 32 + n - OFF_B2);
    v.x = tf32r(v.x); v.y = tf32r(v.y); v.z = tf32r(v.z); v.w = tf32r(v.w);
    *(float4*)(P + (size_t)k * NPACK + n) = v;
}

// tf32-round copy
__global__ void round_copy(const float* __restrict__ src, float* __restrict__ dst)
{
    int i = (blockIdx.x * 256 + threadIdx.x) * 4;
    float4 v = *(const float4*)(src + i);
    v.x = tf32r(v.x); v.y = tf32r(v.y); v.z = tf32r(v.z); v.w = tf32r(v.w);
    *(float4*)(dst + i) = v;
}

// =====================================================================
// Causal depthwise conv (K=4) + SiLU, fused with gate/beta computation.
// Blocks [0, 16384): conv path. Blocks [16384, 16640): gate/beta path.
// =====================================================================
__global__ void conv_gate(const float* __restrict__ big,
                          const float* __restrict__ cq,
                          const float* __restrict__ ck,
                          const float* __restrict__ cv,
                          const float* __restrict__ dtb,
                          const float* __restrict__ Alg,
                          float* __restrict__ acts,
                          float* __restrict__ egT,
                          float* __restrict__ btT)
{
    if (blockIdx.x >= 16384) {
        int i = (blockIdx.x - 16384) * 256 + threadIdx.x;   // T_*NH
        int t = i >> 5, hh = i & 31;
        float x  = big[(size_t)t * NPACK + OFF_A + hh] + dtb[hh];
        float sp = (x <= 20.f) ? log1pf(expf(x)) : x;
        egT[(size_t)hh * T_ + t] = expf(-expf(Alg[hh]) * sp);
        float xb = big[(size_t)t * NPACK + OFF_B2 + hh];
        btT[(size_t)hh * T_ + t] = 1.f / (1.f + expf(-xb));
        return;
    }
    int gid = blockIdx.x * blockDim.x + threadIdx.x;
    int t = gid >> 11;
    int c = (gid & 2047) << 2;
    const float* wp = (c < 2048) ? (cq + c * 4)
                    : (c < 4096) ? (ck + (c - 2048) * 4)
                                 : (cv + (c - 4096) * 4);
    float4 w0 = *(const float4*)(wp + 0);
    float4 w1 = *(const float4*)(wp + 4);
    float4 w2 = *(const float4*)(wp + 8);
    float4 w3 = *(const float4*)(wp + 12);
    const float* xp = big + (size_t)t * NPACK + c;
    float4 z  = make_float4(0.f, 0.f, 0.f, 0.f);
    float4 x3 = *(const float4*)xp;
    float4 x2 = (t >= 1) ? *(const float4*)(xp - NPACK)     : z;
    float4 x1 = (t >= 2) ? *(const float4*)(xp - 2 * NPACK) : z;
    float4 x0 = (t >= 3) ? *(const float4*)(xp - 3 * NPACK) : z;
    float4 o;
    o.x = w0.x * x0.x + w0.y * x1.x + w0.z * x2.x + w0.w * x3.x;
    o.y = w1.x * x0.y + w1.y * x1.y + w1.z * x2.y + w1.w * x3.y;
    o.z = w2.x * x0.z + w2.y * x1.z + w2.z * x2.z + w2.w * x3.z;
    o.w = w3.x * x0.w + w3.y * x1.w + w3.z * x2.w + w3.w * x3.w;
    o.x = o.x / (1.f + expf(-o.x));
    o.y = o.y / (1.f + expf(-o.y));
    o.z = o.z / (1.f + expf(-o.z));
    o.w = o.w / (1.f + expf(-o.w));
    *(float4*)(acts + (size_t)t * 8192 + c) = o;
}

// =====================================================================
// l2norm over head_dim=128 for q (scaled) and k, with dk-PERMUTED store:
// element c -> position (c & 15)*8 + (c >> 4) within the 128-float row.
// (So the scan's lane dkg finds its 8 dk values {dkg, dkg+16, ...}
//  contiguous at [dkg*8, dkg*8+8).)
// =====================================================================
__global__ void qknorm(const float* __restrict__ acts,
                       float* __restrict__ qn, float* __restrict__ kn)
{
    int wid  = (blockIdx.x * blockDim.x + threadIdx.x) >> 5;
    int lane = threadIdx.x & 31;
    int t     = wid >> 5;
    int hh    = (wid >> 1) & 15;
    int which = wid & 1;
    const float* src = acts + (size_t)t * 8192 + which * 2048 + hh * 128 + lane * 4;
    float4 x = *(const float4*)src;
    float ss = x.x * x.x + x.y * x.y + x.z * x.z + x.w * x.w;
#pragma unroll
    for (int off = 16; off; off >>= 1) ss += __shfl_xor_sync(0xffffffffu, ss, off);
    float s = rsqrtf(ss + 1e-6f);
    if (which == 0) s *= 0.08838834764831845f;   // DK^-0.5
    float* dst = (which == 0 ? qn : kn) + (size_t)t * 2048 + hh * 128;
    float v[4] = {x.x * s, x.y * s, x.z * s, x.w * s};
#pragma unroll
    for (int j = 0; j < 4; j++) {
        int c = lane * 4 + j;
        dst[((c & 15) << 3) + (c >> 4)] = v[j];
    }
}

// =====================================================================
// Gated delta-rule scan v2. Grid (8 dv-tiles, 32 heads), 128 threads.
// lane = dkg*2 + dvg: dkg in [0,16) owns dk {dkg+16i}, dvg in {0,1}
// owns 2 dv columns. Warp covers 128 dk x 4 dv; block 16 dv.
// Fused decay (S kept un-decayed through the reductions), 4-round
// butterfly over 16 dkg lanes, cp.async double-buffered 32-step chunks.
// =====================================================================
__global__ __launch_bounds__(128) void gdn_scan(
    const float* __restrict__ qp, const float* __restrict__ kp,
    const float* __restrict__ acts, const float* __restrict__ egT,
    const float* __restrict__ btT, float* __restrict__ o)
{
    const int h    = blockIdx.y;
    const int dvt  = blockIdx.x;
    const int hk   = h >> 1;
    const int tid  = threadIdx.x;
    const int w    = tid >> 5;
    const int lane = tid & 31;
    const int dkg  = lane >> 1;
    const int dvg  = lane & 1;

    __shared__ float sq[2][32][128];
    __shared__ float sk[2][32][128];
    __shared__ float sv[2][32][16];
    __shared__ float se[2][32];
    __shared__ float sb[2][32];

    auto fill = [&](int buf, int t0) {
#pragma unroll
        for (int it = 0; it < 8; it++) {
            int idx = it * 128 + tid;          // 0..1023
            int tt = idx >> 5, f = (idx & 31) << 2;
            const float* qsrc = qp + (size_t)(t0 + tt) * 2048 + hk * 128 + f;
            const float* ksrc = kp + (size_t)(t0 + tt) * 2048 + hk * 128 + f;
            cp16(smem_u32(&sq[buf][tt][f]), qsrc);
            cp16(smem_u32(&sk[buf][tt][f]), ksrc);
        }
        {
            int tt = tid >> 2, f = (tid & 3) << 2;
            cp16(smem_u32(&sv[buf][tt][f]),
                 acts + (size_t)(t0 + tt) * 8192 + 4096 + h * 128 + dvt * 16 + f);
        }
        if (tid < 8)
            cp16(smem_u32(&se[buf][tid << 2]), egT + (size_t)h * T_ + t0 + (tid << 2));
        else if (tid < 16)
            cp16(smem_u32(&sb[buf][(tid - 8) << 2]), btT + (size_t)h * T_ + t0 + ((tid - 8) << 2));
    };

    float S[8][2];
#pragma unroll
    for (int i = 0; i < 8; i++) { S[i][0] = 0.f; S[i][1] = 0.f; }

    fill(0, 0); CP_COMMIT();

    for (int c = 0; c < 64; c++) {
        const int buf = c & 1;
        if (c + 1 < 64) { fill(buf ^ 1, (c + 1) << 5); CP_COMMIT(); CP_WAIT(1); }
        else            { CP_WAIT(0); }
        __syncthreads();
#pragma unroll 1
        for (int tt = 0; tt < 32; tt++) {
            float4 k0 = *(const float4*)&sk[buf][tt][dkg << 3];
            float4 k1 = *(const float4*)&sk[buf][tt][(dkg << 3) + 4];
            float4 q0 = *(const float4*)&sq[buf][tt][dkg << 3];
            float4 q1 = *(const float4*)&sq[buf][tt][(dkg << 3) + 4];
            float2 vv = *(const float2*)&sv[buf][tt][(w << 2) + (dvg << 1)];
            float e = se[buf][tt], b = sb[buf][tt];
            float kf[8] = {k0.x, k0.y, k0.z, k0.w, k1.x, k1.y, k1.z, k1.w};
            float qf[8] = {q0.x, q0.y, q0.z, q0.w, q1.x, q1.y, q1.z, q1.w};
            float kv0 = 0.f, kv1 = 0.f, oq0 = 0.f, oq1 = 0.f, qk = 0.f;
#pragma unroll
            for (int i = 0; i < 8; i++) {
                qk  = fmaf(qf[i], kf[i], qk);
                kv0 = fmaf(kf[i], S[i][0], kv0);
                kv1 = fmaf(kf[i], S[i][1], kv1);
                oq0 = fmaf(qf[i], S[i][0], oq0);
                oq1 = fmaf(qf[i], S[i][1], oq1);
            }
#pragma unroll
            for (int m = 2; m <= 16; m <<= 1) {
                kv0 += __shfl_xor_sync(0xffffffffu, kv0, m);
                kv1 += __shfl_xor_sync(0xffffffffu, kv1, m);
                oq0 += __shfl_xor_sync(0xffffffffu, oq0, m);
                oq1 += __shfl_xor_sync(0xffffffffu, oq1, m);
                qk  += __shfl_xor_sync(0xffffffffu, qk,  m);
            }
            float d0 = b * (vv.x - e * kv0);
            float d1 = b * (vv.y - e * kv1);
#pragma unroll
            for (int i = 0; i < 8; i++) {
                S[i][0] = fmaf(S[i][0], e, kf[i] * d0);
                S[i][1] = fmaf(S[i][1], e, kf[i] * d1);
            }
            if (dkg == 0) {
                float2 ov = make_float2(fmaf(qk, d0, e * oq0), fmaf(qk, d1, e * oq1));
                *(float2*)(o + (size_t)((c << 5) + tt) * 4096 + h * 128
                             + dvt * 16 + (w << 2) + (dvg << 1)) = ov;
            }
        }
        __syncthreads();
    }
}

// =====================================================================
// gated RMSNorm + silu(gate); writes tf32-rounded og for the Wo GEMM
// =====================================================================
__global__ void gate_norm(const float* __restrict__ o, const float* __restrict__ big,
                          const float* __restrict__ wn, float* __restrict__ og)
{
    int wid  = (blockIdx.x * blockDim.x + threadIdx.x) >> 5;
    int lane = threadIdx.x & 31;
    int t = wid >> 5;
    int h = wid & 31;
    size_t base = (size_t)t * 4096 + h * 128 + lane * 4;
    float4 x = *(const float4*)(o + base);
    float ss = x.x * x.x + x.y * x.y + x.z * x.z + x.w * x.w;
#pragma unroll
    for (int off = 16; off; off >>= 1) ss += __shfl_xor_sync(0xffffffffu, ss, off);
    float r = rsqrtf(ss * (1.f / 128.f) + 1e-5f);
    float4 gv = *(const float4*)(big + (size_t)t * NPACK + OFF_G + h * 128 + lane * 4);
    float4 wv = *(const float4*)(wn + lane * 4);
    float4 out;
    out.x = tf32r(x.x * r * wv.x * (gv.x / (1.f + expf(-gv.x))));
    out.y = tf32r(x.y * r * wv.y * (gv.y / (1.f + expf(-gv.y))));
    out.z = tf32r(x.z * r * wv.z * (gv.z / (1.f + expf(-gv.z))));
    out.w = tf32r(x.w * r * wv.w * (gv.w / (1.f + expf(-gv.w))));
    *(float4*)(og + base) = out;
}

// =====================================================================
extern "C" void kernel_launch(void* const* d_in, const int* in_sizes, int n_in,
                              void* d_out, int out_size)
{
    const float* h   = (const float*)d_in[0];
    const float* Wq  = (const float*)d_in[1];
    const float* Wk  = (const float*)d_in[2];
    const float* Wv  = (const float*)d_in[3];
    const float* Wa  = (const float*)d_in[4];
    const float* Wb  = (const float*)d_in[5];
    const float* Wg  = (const float*)d_in[6];
    const float* cq  = (const float*)d_in[7];
    const float* ck  = (const float*)d_in[8];
    const float* cv  = (const float*)d_in[9];
    const float* dtb = (const float*)d_in[10];
    const float* Alg = (const float*)d_in[11];
    const float* onw = (const float*)d_in[12];
    const float* Wo  = (const float*)d_in[13];
    float* out = (float*)d_out;

    float *big, *Wp, *hr, *WoR, *acts, *egT, *btT, *qn, *kn, *o, *og;
    cudaGetSymbolAddress((void**)&big,  g_big);
    cudaGetSymbolAddress((void**)&Wp,   g_Wp);
    cudaGetSymbolAddress((void**)&hr,   g_hr);
    cudaGetSymbolAddress((void**)&WoR,  g_WoR);
    cudaGetSymbolAddress((void**)&acts, g_acts);
    cudaGetSymbolAddress((void**)&egT,  g_egT);
    cudaGetSymbolAddress((void**)&btT,  g_btT);
    cudaGetSymbolAddress((void**)&qn,   g_qn);
    cudaGetSymbolAddress((void**)&kn,   g_kn);
    cudaGetSymbolAddress((void**)&o,    g_o);
    cudaGetSymbolAddress((void**)&og,   g_og);

    cudaFuncSetAttribute(mma_gemm, cudaFuncAttributeMaxDynamicSharedMemorySize, GEMM_SMEM);

    // 1: round h; 2: pack weights
    round_copy<<<(2048 * 2048 / 4) / 256, 256>>>(h, hr);
    pack_w<<<2048 * 3136 / 256, 256>>>(Wq, Wk, Wv, Wg, Wa, Wb, Wp);

    // 3: fused projection GEMM: big = hr @ Wp  [2048 x 12544]
    mma_gemm<<<dim3(8, 98), 512, GEMM_SMEM>>>(hr, Wp, big, 2048, NPACK, NPACK);

    // 4: conv+silu and gate/beta (merged)
    conv_gate<<<16640, 256>>>(big, cq, ck, cv, dtb, Alg, acts, egT, btT);
    // 5: qk l2norm (permuted store)
    qknorm<<<8192, 256>>>(acts, qn, kn);
    // 6: the scan (profiled launch)
    gdn_scan<<<dim3(8, 32), 128>>>(qn, kn, acts, egT, btT, o);
    // 7: gated rmsnorm
    gate_norm<<<8192, 256>>>(o, big, onw, og);
    // 8: round Wo
    round_copy<<<(4096 * 2048 / 4) / 256, 256>>>(Wo, WoR);
    // 9: output projection: out = og @ WoR  [2048 x 2048], K=4096
    mma_gemm<<<dim3(8, 16), 512, GEMM_SMEM>>>(og, WoR, out, 4096, 2048, 2048);
}

// round 9
// speedup vs baseline: 3.6015x; 1.0006x over previous
#include <cuda_runtime.h>
#include <math.h>
#include <cstdint>

static constexpr int T_   = 2048;
static constexpr int NH   = 32;
static constexpr int NPACK = 12544;   // q(2048) k(2048) v(4096) g(4096) a(32) b(32) pad(192)
static constexpr int OFF_K = 2048;
static constexpr int OFF_V = 4096;
static constexpr int OFF_G = 8192;
static constexpr int OFF_A = 12288;
static constexpr int OFF_B2 = 12320;
static constexpr int OFF_END = 12352;

// ---- scratch (static __device__ arrays; no runtime allocation) ----
__device__ float g_big [T_ * NPACK];   // fused projection output (q|k|v|gate|xa|xb)
__device__ float g_Wp  [2048 * NPACK]; // packed + tf32-rounded weights
__device__ float g_hr  [T_ * 2048];    // tf32-rounded h
__device__ float g_WoR [4096 * 2048];  // tf32-rounded Wo
__device__ float g_acts[T_ * 8192];    // conv+silu output (q|k|v), stride 8192
__device__ float g_egT [NH * T_];      // exp(g), transposed [h][t]
__device__ float g_btT [NH * T_];      // beta, transposed [h][t]
__device__ float g_qn  [T_ * 2048];    // l2-normed q, dk-permuted rows
__device__ float g_kn  [T_ * 2048];    // l2-normed k, dk-permuted rows
__device__ float g_o   [T_ * 4096];
__device__ float g_og  [T_ * 4096];    // normed+gated, tf32-rounded

// round f32 -> tf32 (round-to-nearest) as an f32 bit pattern
__device__ __forceinline__ float tf32r(float x) {
    uint32_t u;
    asm("cvt.rna.tf32.f32 %0, %1;" : "=r"(u) : "f"(x));
    return __uint_as_float(u);
}

__device__ __forceinline__ uint32_t smem_u32(const void* p) {
    uint32_t a;
    asm("{ .reg .u64 t; cvta.to.shared.u64 t, %1; cvt.u32.u64 %0, t; }" : "=r"(a) : "l"(p));
    return a;
}
__device__ __forceinline__ void cp16(uint32_t dst, const void* src) {
    asm volatile("cp.async.cg.shared.global [%0], [%1], 16;" :: "r"(dst), "l"(src));
}
#define CP_COMMIT() asm volatile("cp.async.commit_group;" ::: "memory")
#define CP_WAIT(n)  asm volatile("cp.async.wait_group %0;" :: "n"(n) : "memory")

__device__ __forceinline__ uint32_t lds32(uint32_t a) {
    uint32_t v;
    asm volatile("ld.shared.b32 %0, [%1];" : "=r"(v) : "r"(a));
    return v;
}

__device__ __forceinline__ void mma_tf32(float* c, const uint32_t* a, const uint32_t* b) {
    asm volatile("mma.sync.aligned.m16n8k8.row.col.f32.tf32.tf32.f32 "
        "{%0,%1,%2,%3}, {%4,%5,%6,%7}, {%8,%9}, {%0,%1,%2,%3};"
        : "+f"(c[0]), "+f"(c[1]), "+f"(c[2]), "+f"(c[3])
        : "r"(a[0]), "r"(a[1]), "r"(a[2]), "r"(a[3]), "r"(b[0]), "r"(b[1]));
}

// =====================================================================
// tf32 mma.sync GEMM: C[M, N] = A[M, K] @ B[K, N], both tf32-rounded,
// plain row-major. CTA tile 256(M) x 128(N), BK=32, 512 threads
// (16 warps, 4x4), warp tile 64x32. 3-stage cp.async pipeline.
// Rasterization: blockIdx.x = row-tile (fast), blockIdx.y = col-tile,
// so consecutive CTAs share the same B columns (L2-friendly).
// =====================================================================
static constexpr uint32_t STAGE = 49152;
static constexpr uint32_t GEMM_SMEM = 3 * STAGE;   // 144KB

__global__ __launch_bounds__(512, 1) void mma_gemm(
    const float* __restrict__ A, const float* __restrict__ B, float* __restrict__ C,
    int K, int ldb, int ldc)
{
    extern __shared__ char smem[];
    const uint32_t sbase = smem_u32(smem);
    const int tid  = threadIdx.x;
    const int lane = tid & 31;
    const int w    = tid >> 5;
    const int wm   = w >> 2;          // 0..3
    const int wn   = w & 3;           // 0..3
    const int c4   = lane & 3;
    const int g    = lane >> 2;       // 0..7
    const int row0 = blockIdx.x * 256;
    const int col0 = blockIdx.y * 128;

    float acc[4][4][4];
#pragma unroll
    for (int mi = 0; mi < 4; mi++)
#pragma unroll
        for (int ni = 0; ni < 4; ni++)
#pragma unroll
            for (int q = 0; q < 4; q++) acc[mi][ni][q] = 0.f;

    const int nt = K >> 5;

    auto issue = [&](int t, int st) {
        const int k0 = t << 5;
        const uint32_t sA = sbase + st * STAGE;
        const uint32_t sB = sA + 32768;
#pragma unroll
        for (int it = 0; it < 4; it++) {
            int idx = it * 512 + tid;          // 0..2047
            int r = idx >> 3, f = idx & 7;     // row 0..255, 16B-chunk 0..7
            cp16(sA + r * 128 + ((f ^ (r & 7)) << 4),
                 A + (size_t)(row0 + r) * K + k0 + f * 4);
        }
#pragma unroll
        for (int it = 0; it < 2; it++) {
            int idx = it * 512 + tid;          // 0..1023
            int k = idx >> 5, c = idx & 31;    // row 0..31, chunk 0..31
            cp16(sB + k * 512 + ((c ^ ((k & 3) << 1)) << 4),
                 B + (size_t)(k0 + k) * ldb + col0 + c * 4);
        }
    };

    auto compute = [&](int st) {
        const uint32_t sA = sbase + st * STAGE;
        const uint32_t sB = sA + 32768;
#pragma unroll
        for (int s = 0; s < 4; s++) {
            uint32_t af[4][4];
            uint32_t bf[4][2];
            const int f0 = 2 * s, f1 = 2 * s + 1;
#pragma unroll
            for (int mi = 0; mi < 4; mi++) {
                const int r = wm * 64 + mi * 16 + g;   // r & 7 == g
                const uint32_t base = sA + r * 128 + c4 * 4;
                af[mi][0] = lds32(base + ((f0 ^ g) << 4));
                af[mi][1] = lds32(base + 8 * 128 + ((f0 ^ g) << 4));
                af[mi][2] = lds32(base + ((f1 ^ g) << 4));
                af[mi][3] = lds32(base + 8 * 128 + ((f1 ^ g) << 4));
            }
            const int kk = 8 * s + c4;
#pragma unroll
            for (int ni = 0; ni < 4; ni++) {
                const int n = wn * 32 + ni * 8 + g;
                const uint32_t boff = ((uint32_t)((n >> 2) ^ (c4 << 1)) << 4) + (n & 3) * 4;
                bf[ni][0] = lds32(sB + kk * 512 + boff);
                bf[ni][1] = lds32(sB + (kk + 4) * 512 + boff);
            }
#pragma unroll
            for (int mi = 0; mi < 4; mi++)
#pragma unroll
                for (int ni = 0; ni < 4; ni++)
                    mma_tf32(acc[mi][ni], af[mi], bf[ni]);
        }
    };

    issue(0, 0); CP_COMMIT();
    issue(1, 1); CP_COMMIT();
    int st = 0;
    for (int t = 0; t < nt; t++) {
        if (t + 2 < nt) {
            CP_WAIT(1);
            __syncthreads();
            issue(t + 2, (st + 2) % 3);
            CP_COMMIT();
        } else {
            CP_WAIT(0);
            __syncthreads();
        }
        compute(st);
        st = (st + 1) % 3;
    }

#pragma unroll
    for (int mi = 0; mi < 4; mi++) {
        const int r0 = row0 + wm * 64 + mi * 16 + g;
#pragma unroll
        for (int ni = 0; ni < 4; ni++) {
            const int cc = col0 + wn * 32 + ni * 8 + 2 * c4;
            *(float2*)(C + (size_t)r0 * ldc + cc) =
                make_float2(acc[mi][ni][0], acc[mi][ni][1]);
            *(float2*)(C + (size_t)(r0 + 8) * ldc + cc) =
                make_float2(acc[mi][ni][2], acc[mi][ni][3]);
        }
    }
}

// =====================================================================
// Pack + tf32-round all projection weights into Wp[2048, 12544]
// =====================================================================
__global__ void pack_w(const float* __restrict__ Wq, const float* __restrict__ Wk,
                       const float* __restrict__ Wv, const float* __restrict__ Wg,
                       const float* __restrict__ Wa, const float* __restrict__ Wb,
                       float* __restrict__ P)
{
    int idx = blockIdx.x * 256 + threadIdx.x;   // 2048 * 3136
    int k = idx / 3136;
    int n = (idx - k * 3136) * 4;
    float4 v = make_float4(0.f, 0.f, 0.f, 0.f);
    if      (n < OFF_K)   v = *(const float4*)(Wq + (size_t)k * 2048 + n);
    else if (n < OFF_V)   v = *(const float4*)(Wk + (size_t)k * 2048 + n - OFF_K);
    else if (n < OFF_G)   v = *(const float4*)(Wv + (size_t)k * 4096 + n - OFF_V);
    else if (n < OFF_A)   v = *(const float4*)(Wg + (size_t)k * 4096 + n - OFF_G);
    else if (n < OFF_B2)  v = *(const float4*)(Wa + (size_t)k * 32 + n - OFF_A);
    else if (n < OFF_END) v = *(const float4*)(Wb + (size_t)k * 32 + n - OFF_B2);
    v.x = tf32r(v.x); v.y = tf32r(v.y); v.z = tf32r(v.z); v.w = tf32r(v.w);
    *(float4*)(P + (size_t)k * NPACK + n) = v;
}

// tf32-round copy
__global__ void round_copy(const float* __restrict__ src, float* __restrict__ dst)
{
    int i = (blockIdx.x * 256 + threadIdx.x) * 4;
    float4 v = *(const float4*)(src + i);
    v.x = tf32r(v.x); v.y = tf32r(v.y); v.z = tf32r(v.z); v.w = tf32r(v.w);
    *(float4*)(dst + i) = v;
}

// =====================================================================
// Causal depthwise conv (K=4) + SiLU, fused with gate/beta computation.
// Blocks [0, 16384): conv path. Blocks [16384, 16640): gate/beta path.
// =====================================================================
__global__ void conv_gate(const float* __restrict__ big,
                          const float* __restrict__ cq,
                          const float* __restrict__ ck,
                          const float* __restrict__ cv,
                          const float* __restrict__ dtb,
                          const float* __restrict__ Alg,
                          float* __restrict__ acts,
                          float* __restrict__ egT,
                          float* __restrict__ btT)
{
    if (blockIdx.x >= 16384) {
        int i = (blockIdx.x - 16384) * 256 + threadIdx.x;   // T_*NH
        int t = i >> 5, hh = i & 31;
        float x  = big[(size_t)t * NPACK + OFF_A + hh] + dtb[hh];
        float sp = (x <= 20.f) ? log1pf(expf(x)) : x;
        egT[(size_t)hh * T_ + t] = expf(-expf(Alg[hh]) * sp);
        float xb = big[(size_t)t * NPACK + OFF_B2 + hh];
        btT[(size_t)hh * T_ + t] = 1.f / (1.f + expf(-xb));
        return;
    }
    int gid = blockIdx.x * blockDim.x + threadIdx.x;
    int t = gid >> 11;
    int c = (gid & 2047) << 2;
    const float* wp = (c < 2048) ? (cq + c * 4)
                    : (c < 4096) ? (ck + (c - 2048) * 4)
                                 : (cv + (c - 4096) * 4);
    float4 w0 = *(const float4*)(wp + 0);
    float4 w1 = *(const float4*)(wp + 4);
    float4 w2 = *(const float4*)(wp + 8);
    float4 w3 = *(const float4*)(wp + 12);
    const float* xp = big + (size_t)t * NPACK + c;
    float4 z  = make_float4(0.f, 0.f, 0.f, 0.f);
    float4 x3 = *(const float4*)xp;
    float4 x2 = (t >= 1) ? *(const float4*)(xp - NPACK)     : z;
    float4 x1 = (t >= 2) ? *(const float4*)(xp - 2 * NPACK) : z;
    float4 x0 = (t >= 3) ? *(const float4*)(xp - 3 * NPACK) : z;
    float4 o;
    o.x = w0.x * x0.x + w0.y * x1.x + w0.z * x2.x + w0.w * x3.x;
    o.y = w1.x * x0.y + w1.y * x1.y + w1.z * x2.y + w1.w * x3.y;
    o.z = w2.x * x0.z + w2.y * x1.z + w2.z * x2.z + w2.w * x3.z;
    o.w = w3.x * x0.w + w3.y * x1.w + w3.z * x2.w + w3.w * x3.w;
    o.x = o.x / (1.f + expf(-o.x));
    o.y = o.y / (1.f + expf(-o.y));
    o.z = o.z / (1.f + expf(-o.z));
    o.w = o.w / (1.f + expf(-o.w));
    *(float4*)(acts + (size_t)t * 8192 + c) = o;
}

// =====================================================================
// l2norm over head_dim=128 for q (scaled) and k, with dk-PERMUTED store:
// element c -> position (c & 15)*8 + (c >> 4) within the 128-float row.
// (So the scan's lane dkg finds its 8 dk values {dkg, dkg+16, ...}
//  contiguous at [dkg*8, dkg*8+8).)
// =====================================================================
__global__ void qknorm(const float* __restrict__ acts,
                       float* __restrict__ qn, float* __restrict__ kn)
{
    int wid  = (blockIdx.x * blockDim.x + threadIdx.x) >> 5;
    int lane = threadIdx.x & 31;
    int t     = wid >> 5;
    int hh    = (wid >> 1) & 15;
    int which = wid & 1;
    const float* src = acts + (size_t)t * 8192 + which * 2048 + hh * 128 + lane * 4;
    float4 x = *(const float4*)src;
    float ss = x.x * x.x + x.y * x.y + x.z * x.z + x.w * x.w;
#pragma unroll
    for (int off = 16; off; off >>= 1) ss += __shfl_xor_sync(0xffffffffu, ss, off);
    float s = rsqrtf(ss + 1e-6f);
    if (which == 0) s *= 0.08838834764831845f;   // DK^-0.5
    float* dst = (which == 0 ? qn : kn) + (size_t)t * 2048 + hh * 128;
    float v[4] = {x.x * s, x.y * s, x.z * s, x.w * s};
#pragma unroll
    for (int j = 0; j < 4; j++) {
        int c = lane * 4 + j;
        dst[((c & 15) << 3) + (c >> 4)] = v[j];
    }
}

// =====================================================================
// Gated delta-rule scan v2. Grid (8 dv-tiles, 32 heads), 128 threads.
// lane = dkg*2 + dvg: dkg in [0,16) owns dk {dkg+16i}, dvg in {0,1}
// owns 2 dv columns. Warp covers 128 dk x 4 dv; block 16 dv.
// Fused decay (S kept un-decayed through the reductions), 4-round
// butterfly over 16 dkg lanes, cp.async double-buffered 32-step chunks.
// =====================================================================
__global__ __launch_bounds__(128) void gdn_scan(
    const float* __restrict__ qp, const float* __restrict__ kp,
    const float* __restrict__ acts, const float* __restrict__ egT,
    const float* __restrict__ btT, float* __restrict__ o)
{
    const int h    = blockIdx.y;
    const int dvt  = blockIdx.x;
    const int hk   = h >> 1;
    const int tid  = threadIdx.x;
    const int w    = tid >> 5;
    const int lane = tid & 31;
    const int dkg  = lane >> 1;
    const int dvg  = lane & 1;

    __shared__ float sq[2][32][128];
    __shared__ float sk[2][32][128];
    __shared__ float sv[2][32][16];
    __shared__ float se[2][32];
    __shared__ float sb[2][32];

    auto fill = [&](int buf, int t0) {
#pragma unroll
        for (int it = 0; it < 8; it++) {
            int idx = it * 128 + tid;          // 0..1023
            int tt = idx >> 5, f = (idx & 31) << 2;
            const float* qsrc = qp + (size_t)(t0 + tt) * 2048 + hk * 128 + f;
            const float* ksrc = kp + (size_t)(t0 + tt) * 2048 + hk * 128 + f;
            cp16(smem_u32(&sq[buf][tt][f]), qsrc);
            cp16(smem_u32(&sk[buf][tt][f]), ksrc);
        }
        {
            int tt = tid >> 2, f = (tid & 3) << 2;
            cp16(smem_u32(&sv[buf][tt][f]),
                 acts + (size_t)(t0 + tt) * 8192 + 4096 + h * 128 + dvt * 16 + f);
        }
        if (tid < 8)
            cp16(smem_u32(&se[buf][tid << 2]), egT + (size_t)h * T_ + t0 + (tid << 2));
        else if (tid < 16)
            cp16(smem_u32(&sb[buf][(tid - 8) << 2]), btT + (size_t)h * T_ + t0 + ((tid - 8) << 2));
    };

    float S[8][2];
#pragma unroll
    for (int i = 0; i < 8; i++) { S[i][0] = 0.f; S[i][1] = 0.f; }

    fill(0, 0); CP_COMMIT();

    for (int c = 0; c < 64; c++) {
        const int buf = c & 1;
        if (c + 1 < 64) { fill(buf ^ 1, (c + 1) << 5); CP_COMMIT(); CP_WAIT(1); }
        else            { CP_WAIT(0); }
        __syncthreads();
#pragma unroll 1
        for (int tt = 0; tt < 32; tt++) {
            float4 k0 = *(const float4*)&sk[buf][tt][dkg << 3];
            float4 k1 = *(const float4*)&sk[buf][tt][(dkg << 3) + 4];
            float4 q0 = *(const float4*)&sq[buf][tt][dkg << 3];
            float4 q1 = *(const float4*)&sq[buf][tt][(dkg << 3) + 4];
            float2 vv = *(const float2*)&sv[buf][tt][(w << 2) + (dvg << 1)];
            float e = se[buf][tt], b = sb[buf][tt];
            float kf[8] = {k0.x, k0.y, k0.z, k0.w, k1.x, k1.y, k1.z, k1.w};
            float qf[8] = {q0.x, q0.y, q0.z, q0.w, q1.x, q1.y, q1.z, q1.w};
            float kv0 = 0.f, kv1 = 0.f, oq0 = 0.f, oq1 = 0.f, qk = 0.f;
#pragma unroll
            for (int i = 0; i < 8; i++) {
                qk  = fmaf(qf[i], kf[i], qk);
                kv0 = fmaf(kf[i], S[i][0], kv0);
                kv1 = fmaf(kf[i], S[i][1], kv1);
                oq0 = fmaf(qf[i], S[i][0], oq0);
                oq1 = fmaf(qf[i], S[i][1], oq1);
            }
#pragma unroll
            for (int m = 2; m <= 16; m <<= 1) {
                kv0 += __shfl_xor_sync(0xffffffffu, kv0, m);
                kv1 += __shfl_xor_sync(0xffffffffu, kv1, m);
                oq0 += __shfl_xor_sync(0xffffffffu, oq0, m);
                oq1 += __shfl_xor_sync(0xffffffffu, oq1, m);
                qk  += __shfl_xor_sync(0xffffffffu, qk,  m);
            }
            float d0 = b * (vv.x - e * kv0);
            float d1 = b * (vv.y - e * kv1);
#pragma unroll
            for (int i = 0; i < 8; i++) {
                S[i][0] = fmaf(S[i][0], e, kf[i] * d0);
                S[i][1] = fmaf(S[i][1], e, kf[i] * d1);
            }
            if (dkg == 0) {
                float2 ov = make_float2(fmaf(qk, d0, e * oq0), fmaf(qk, d1, e * oq1));
                *(float2*)(o + (size_t)((c << 5) + tt) * 4096 + h * 128
                             + dvt * 16 + (w << 2) + (dvg << 1)) = ov;
            }
        }
        __syncthreads();
    }
}

// =====================================================================
// gated RMSNorm + silu(gate); writes tf32-rounded og for the Wo GEMM
// =====================================================================
__global__ void gate_norm(const float* __restrict__ o, const float* __restrict__ big,
                          const float* __restrict__ wn, float* __restrict__ og)
{
    int wid  = (blockIdx.x * blockDim.x + threadIdx.x) >> 5;
    int lane = threadIdx.x & 31;
    int t = wid >> 5;
    int h = wid & 31;
    size_t base = (size_t)t * 4096 + h * 128 + lane * 4;
    float4 x = *(const float4*)(o + base);
    float ss = x.x * x.x + x.y * x.y + x.z * x.z + x.w * x.w;
#pragma unroll
    for (int off = 16; off; off >>= 1) ss += __shfl_xor_sync(0xffffffffu, ss, off);
    float r = rsqrtf(ss * (1.f / 128.f) + 1e-5f);
    float4 gv = *(const float4*)(big + (size_t)t * NPACK + OFF_G + h * 128 + lane * 4);
    float4 wv = *(const float4*)(wn + lane * 4);
    float4 out;
    out.x = tf32r(x.x * r * wv.x * (gv.x / (1.f + expf(-gv.x))));
    out.y = tf32r(x.y * r * wv.y * (gv.y / (1.f + expf(-gv.y))));
    out.z = tf32r(x.z * r * wv.z * (gv.z / (1.f + expf(-gv.z))));
    out.w = tf32r(x.w * r * wv.w * (gv.w / (1.f + expf(-gv.w))));
    *(float4*)(og + base) = out;
}

// =====================================================================
extern "C" void kernel_launch(void* const* d_in, const int* in_sizes, int n_in,
                              void* d_out, int out_size)
{
    const float* h   = (const float*)d_in[0];
    const float* Wq  = (const float*)d_in[1];
    const float* Wk  = (const float*)d_in[2];
    const float* Wv  = (const float*)d_in[3];
    const float* Wa  = (const float*)d_in[4];
    const float* Wb  = (const float*)d_in[5];
    const float* Wg  = (const float*)d_in[6];
    const float* cq  = (const float*)d_in[7];
    const float* ck  = (const float*)d_in[8];
    const float* cv  = (const float*)d_in[9];
    const float* dtb = (const float*)d_in[10];
    const float* Alg = (const float*)d_in[11];
    const float* onw = (const float*)d_in[12];
    const float* Wo  = (const float*)d_in[13];
    float* out = (float*)d_out;

    float *big, *Wp, *hr, *WoR, *acts, *egT, *btT, *qn, *kn, *o, *og;
    cudaGetSymbolAddress((void**)&big,  g_big);
    cudaGetSymbolAddress((void**)&Wp,   g_Wp);
    cudaGetSymbolAddress((void**)&hr,   g_hr);
    cudaGetSymbolAddress((void**)&WoR,  g_WoR);
    cudaGetSymbolAddress((void**)&acts, g_acts);
    cudaGetSymbolAddress((void**)&egT,  g_egT);
    cudaGetSymbolAddress((void**)&btT,  g_btT);
    cudaGetSymbolAddress((void**)&qn,   g_qn);
    cudaGetSymbolAddress((void**)&kn,   g_kn);
    cudaGetSymbolAddress((void**)&o,    g_o);
    cudaGetSymbolAddress((void**)&og,   g_og);

    cudaFuncSetAttribute(mma_gemm, cudaFuncAttributeMaxDynamicSharedMemorySize, GEMM_SMEM);

    // 1: round h; 2: pack weights
    round_copy<<<(2048 * 2048 / 4) / 256, 256>>>(h, hr);
    pack_w<<<2048 * 3136 / 256, 256>>>(Wq, Wk, Wv, Wg, Wa, Wb, Wp);

    // 3: fused projection GEMM: big = hr @ Wp  [2048 x 12544]
    mma_gemm<<<dim3(8, 98), 512, GEMM_SMEM>>>(hr, Wp, big, 2048, NPACK, NPACK);

    // 4: conv+silu and gate/beta (merged)
    conv_gate<<<16640, 256>>>(big, cq, ck, cv, dtb, Alg, acts, egT, btT);
    // 5: qk l2norm (permuted store)
    qknorm<<<8192, 256>>>(acts, qn, kn);
    // 6: the scan (profiled launch)
    gdn_scan<<<dim3(8, 32), 128>>>(qn, kn, acts, egT, btT, o);
    // 7: gated rmsnorm
    gate_norm<<<8192, 256>>>(o, big, onw, og);
    // 8: round Wo
    round_copy<<<(4096 * 2048 / 4) / 256, 256>>>(Wo, WoR);
    // 9: output projection: out = og @ WoR  [2048 x 2048], K=4096
    mma_gemm<<<dim3(8, 16), 512, GEMM_SMEM>>>(og, WoR, out, 4096, 2048, 2048);
}

// round 10
// speedup vs baseline: 3.6506x; 1.0136x over previous
#include <cuda_runtime.h>
#include <math.h>
#include <cstdint>

static constexpr int T_   = 2048;
static constexpr int NH   = 32;
static constexpr int NPACK = 12544;
static constexpr int OFF_K = 2048;
static constexpr int OFF_V = 4096;
static constexpr int OFF_G = 8192;
static constexpr int OFF_A = 12288;
static constexpr int OFF_B2 = 12320;
static constexpr int OFF_END = 12352;

__device__ float g_big [T_ * NPACK];
__device__ float g_Wp  [2048 * NPACK];
__device__ float g_hr  [T_ * 2048];
__device__ float g_WoR [4096 * 2048];
__device__ float g_acts[T_ * 8192];    // only v region [4096,8192) used
__device__ float g_egT [NH * T_];
__device__ float g_btT [NH * T_];
__device__ float g_qn  [T_ * 2048];    // l2-normed q, dk-permuted rows
__device__ float g_kn  [T_ * 2048];
__device__ float g_qkd [16 * T_];      // q_t . k_t  [hk][t]
__device__ float g_o   [T_ * 4096];
__device__ float g_og  [T_ * 4096];

__device__ __forceinline__ float tf32r(float x) {
    uint32_t u;
    asm("cvt.rna.tf32.f32 %0, %1;" : "=r"(u) : "f"(x));
    return __uint_as_float(u);
}
__device__ __forceinline__ uint32_t smem_u32(const void* p) {
    uint32_t a;
    asm("{ .reg .u64 t; cvta.to.shared.u64 t, %1; cvt.u32.u64 %0, t; }" : "=r"(a) : "l"(p));
    return a;
}
__device__ __forceinline__ void cp16(uint32_t dst, const void* src) {
    asm volatile("cp.async.cg.shared.global [%0], [%1], 16;" :: "r"(dst), "l"(src));
}
#define CP_COMMIT() asm volatile("cp.async.commit_group;" ::: "memory")
#define CP_WAIT(n)  asm volatile("cp.async.wait_group %0;" :: "n"(n) : "memory")

__device__ __forceinline__ uint32_t lds32(uint32_t a) {
    uint32_t v;
    asm volatile("ld.shared.b32 %0, [%1];" : "=r"(v) : "r"(a));
    return v;
}
__device__ __forceinline__ void mma_tf32(float* c, const uint32_t* a, const uint32_t* b) {
    asm volatile("mma.sync.aligned.m16n8k8.row.col.f32.tf32.tf32.f32 "
        "{%0,%1,%2,%3}, {%4,%5,%6,%7}, {%8,%9}, {%0,%1,%2,%3};"
        : "+f"(c[0]), "+f"(c[1]), "+f"(c[2]), "+f"(c[3])
        : "r"(a[0]), "r"(a[1]), "r"(a[2]), "r"(a[3]), "r"(b[0]), "r"(b[1]));
}

// ---- packed f32x2 helpers (sm_100+ base ISA) ----
typedef unsigned long long u64;
__device__ __forceinline__ u64 f2b(float x) {
    u64 r; asm("mov.b64 %0, {%1, %1};" : "=l"(r) : "f"(x)); return r;
}
__device__ __forceinline__ float f2hadd(u64 v) {
    float a, b; asm("mov.b64 {%0, %1}, %2;" : "=f"(a), "=f"(b) : "l"(v)); return a + b;
}
__device__ __forceinline__ u64 f2fma(u64 a, u64 b, u64 c) {
    u64 d; asm("fma.rn.f32x2 %0, %1, %2, %3;" : "=l"(d) : "l"(a), "l"(b), "l"(c)); return d;
}
__device__ __forceinline__ u64 f2mul(u64 a, u64 b) {
    u64 d; asm("mul.rn.f32x2 %0, %1, %2;" : "=l"(d) : "l"(a), "l"(b)); return d;
}

// ================= tf32 mma.sync GEMM, 4-stage cp.async =================
static constexpr uint32_t STAGE = 49152;
static constexpr uint32_t GEMM_SMEM = 4 * STAGE;   // 192KB

__global__ __launch_bounds__(512, 1) void mma_gemm(
    const float* __restrict__ A, const float* __restrict__ B, float* __restrict__ C,
    int K, int ldb, int ldc)
{
    extern __shared__ char smem[];
    const uint32_t sbase = smem_u32(smem);
    const int tid  = threadIdx.x;
    const int lane = tid & 31;
    const int w    = tid >> 5;
    const int wm   = w >> 2;
    const int wn   = w & 3;
    const int c4   = lane & 3;
    const int g    = lane >> 2;
    const int row0 = blockIdx.x * 256;
    const int col0 = blockIdx.y * 128;

    float acc[4][4][4];
#pragma unroll
    for (int mi = 0; mi < 4; mi++)
#pragma unroll
        for (int ni = 0; ni < 4; ni++)
#pragma unroll
            for (int q = 0; q < 4; q++) acc[mi][ni][q] = 0.f;

    const int nt = K >> 5;

    auto issue = [&](int t, int st) {
        const int k0 = t << 5;
        const uint32_t sA = sbase + st * STAGE;
        const uint32_t sB = sA + 32768;
#pragma unroll
        for (int it = 0; it < 4; it++) {
            int idx = it * 512 + tid;
            int r = idx >> 3, f = idx & 7;
            cp16(sA + r * 128 + ((f ^ (r & 7)) << 4),
                 A + (size_t)(row0 + r) * K + k0 + f * 4);
        }
#pragma unroll
        for (int it = 0; it < 2; it++) {
            int idx = it * 512 + tid;
            int k = idx >> 5, c = idx & 31;
            cp16(sB + k * 512 + ((c ^ ((k & 3) << 1)) << 4),
                 B + (size_t)(k0 + k) * ldb + col0 + c * 4);
        }
    };

    auto compute = [&](int st) {
        const uint32_t sA = sbase + st * STAGE;
        const uint32_t sB = sA + 32768;
#pragma unroll
        for (int s = 0; s < 4; s++) {
            uint32_t af[4][4];
            uint32_t bf[4][2];
            const int f0 = 2 * s, f1 = 2 * s + 1;
#pragma unroll
            for (int mi = 0; mi < 4; mi++) {
                const int r = wm * 64 + mi * 16 + g;
                const uint32_t base = sA + r * 128 + c4 * 4;
                af[mi][0] = lds32(base + ((f0 ^ g) << 4));
                af[mi][1] = lds32(base + 8 * 128 + ((f0 ^ g) << 4));
                af[mi][2] = lds32(base + ((f1 ^ g) << 4));
                af[mi][3] = lds32(base + 8 * 128 + ((f1 ^ g) << 4));
            }
            const int kk = 8 * s + c4;
#pragma unroll
            for (int ni = 0; ni < 4; ni++) {
                const int n = wn * 32 + ni * 8 + g;
                const uint32_t boff = ((uint32_t)((n >> 2) ^ (c4 << 1)) << 4) + (n & 3) * 4;
                bf[ni][0] = lds32(sB + kk * 512 + boff);
                bf[ni][1] = lds32(sB + (kk + 4) * 512 + boff);
            }
#pragma unroll
            for (int mi = 0; mi < 4; mi++)
#pragma unroll
                for (int ni = 0; ni < 4; ni++)
                    mma_tf32(acc[mi][ni], af[mi], bf[ni]);
        }
    };

    issue(0, 0); CP_COMMIT();
    issue(1, 1); CP_COMMIT();
    issue(2, 2); CP_COMMIT();
    int st = 0;
    for (int t = 0; t < nt; t++) {
        if (t + 3 < nt) {
            CP_WAIT(2);
            __syncthreads();
            issue(t + 3, (st + 3) & 3);
            CP_COMMIT();
        } else {
            CP_WAIT(0);
            __syncthreads();
        }
        compute(st);
        st = (st + 1) & 3;
    }

#pragma unroll
    for (int mi = 0; mi < 4; mi++) {
        const int r0 = row0 + wm * 64 + mi * 16 + g;
#pragma unroll
        for (int ni = 0; ni < 4; ni++) {
            const int cc = col0 + wn * 32 + ni * 8 + 2 * c4;
            *(float2*)(C + (size_t)r0 * ldc + cc) =
                make_float2(acc[mi][ni][0], acc[mi][ni][1]);
            *(float2*)(C + (size_t)(r0 + 8) * ldc + cc) =
                make_float2(acc[mi][ni][2], acc[mi][ni][3]);
        }
    }
}

// ================= weight pack + rounding =================
__global__ void pack_w(const float* __restrict__ Wq, const float* __restrict__ Wk,
                       const float* __restrict__ Wv, const float* __restrict__ Wg,
                       const float* __restrict__ Wa, const float* __restrict__ Wb,
                       float* __restrict__ P)
{
    int idx = blockIdx.x * 256 + threadIdx.x;
    int k = idx / 3136;
    int n = (idx - k * 3136) * 4;
    float4 v = make_float4(0.f, 0.f, 0.f, 0.f);
    if      (n < OFF_K)   v = *(const float4*)(Wq + (size_t)k * 2048 + n);
    else if (n < OFF_V)   v = *(const float4*)(Wk + (size_t)k * 2048 + n - OFF_K);
    else if (n < OFF_G)   v = *(const float4*)(Wv + (size_t)k * 4096 + n - OFF_V);
    else if (n < OFF_A)   v = *(const float4*)(Wg + (size_t)k * 4096 + n - OFF_G);
    else if (n < OFF_B2)  v = *(const float4*)(Wa + (size_t)k * 32 + n - OFF_A);
    else if (n < OFF_END) v = *(const float4*)(Wb + (size_t)k * 32 + n - OFF_B2);
    v.x = tf32r(v.x); v.y = tf32r(v.y); v.z = tf32r(v.z); v.w = tf32r(v.w);
    *(float4*)(P + (size_t)k * NPACK + n) = v;
}

__global__ void round_copy(const float* __restrict__ src, float* __restrict__ dst)
{
    int i = (blockIdx.x * 256 + threadIdx.x) * 4;
    float4 v = *(const float4*)(src + i);
    v.x = tf32r(v.x); v.y = tf32r(v.y); v.z = tf32r(v.z); v.w = tf32r(v.w);
    *(float4*)(dst + i) = v;
}

// =====================================================================
// Fused: v-conv+SiLU; q/k conv+SiLU+l2norm+permute (direct to qn/kn);
// gate/beta. blocks [0,8192)=v, [8192,16384)=q/k warps, [16384,16640)=gate.
// =====================================================================
__global__ void conv_norm(const float* __restrict__ big,
                          const float* __restrict__ cq, const float* __restrict__ ck,
                          const float* __restrict__ cv, const float* __restrict__ dtb,
                          const float* __restrict__ Alg, float* __restrict__ acts,
                          float* __restrict__ egT, float* __restrict__ btT,
                          float* __restrict__ qn, float* __restrict__ kn)
{
    int b = blockIdx.x;
    float4 z = make_float4(0.f, 0.f, 0.f, 0.f);
    if (b < 8192) {
        int gid = b * 256 + threadIdx.x;
        int t = gid >> 10;
        int c = (gid & 1023) << 2;
        const float* wp = cv + c * 4;
        float4 w0 = *(const float4*)(wp + 0), w1 = *(const float4*)(wp + 4);
        float4 w2 = *(const float4*)(wp + 8), w3 = *(const float4*)(wp + 12);
        const float* xp = big + (size_t)t * NPACK + 4096 + c;
        float4 x3 = *(const float4*)xp;
        float4 x2 = (t >= 1) ? *(const float4*)(xp - NPACK)     : z;
        float4 x1 = (t >= 2) ? *(const float4*)(xp - 2 * NPACK) : z;
        float4 x0 = (t >= 3) ? *(const float4*)(xp - 3 * NPACK) : z;
        float4 o;
        o.x = w0.x * x0.x + w0.y * x1.x + w0.z * x2.x + w0.w * x3.x;
        o.y = w1.x * x0.y + w1.y * x1.y + w1.z * x2.y + w1.w * x3.y;
        o.z = w2.x * x0.z + w2.y * x1.z + w2.z * x2.z + w2.w * x3.z;
        o.w = w3.x * x0.w + w3.y * x1.w + w3.z * x2.w + w3.w * x3.w;
        o.x = o.x / (1.f + expf(-o.x)); o.y = o.y / (1.f + expf(-o.y));
        o.z = o.z / (1.f + expf(-o.z)); o.w = o.w / (1.f + expf(-o.w));
        *(float4*)(acts + (size_t)t * 8192 + 4096 + c) = o;
    } else if (b < 16384) {
        int gw   = (b - 8192) * 8 + (threadIdx.x >> 5);
        int lane = threadIdx.x & 31;
        int t     = gw >> 5;
        int rest  = gw & 31;
        int which = rest & 1;
        int hh    = rest >> 1;
        int cl    = lane * 4;
        const float* wp = (which ? ck : cq) + (hh * 128 + cl) * 4;
        float4 w0 = *(const float4*)(wp + 0), w1 = *(const float4*)(wp + 4);
        float4 w2 = *(const float4*)(wp + 8), w3 = *(const float4*)(wp + 12);
        const float* xp = big + (size_t)t * NPACK + which * 2048 + hh * 128 + cl;
        float4 x3 = *(const float4*)xp;
        float4 x2 = (t >= 1) ? *(const float4*)(xp - NPACK)     : z;
        float4 x1 = (t >= 2) ? *(const float4*)(xp - 2 * NPACK) : z;
        float4 x0 = (t >= 3) ? *(const float4*)(xp - 3 * NPACK) : z;
        float v[4];
        v[0] = w0.x * x0.x + w0.y * x1.x + w0.z * x2.x + w0.w * x3.x;
        v[1] = w1.x * x0.y + w1.y * x1.y + w1.z * x2.y + w1.w * x3.y;
        v[2] = w2.x * x0.z + w2.y * x1.z + w2.z * x2.z + w2.w * x3.z;
        v[3] = w3.x * x0.w + w3.y * x1.w + w3.z * x2.w + w3.w * x3.w;
#pragma unroll
        for (int j = 0; j < 4; j++) v[j] = v[j] / (1.f + expf(-v[j]));
        float ss = v[0] * v[0] + v[1] * v[1] + v[2] * v[2] + v[3] * v[3];
#pragma unroll
        for (int off = 16; off; off >>= 1) ss += __shfl_xor_sync(0xffffffffu, ss, off);
        float s = rsqrtf(ss + 1e-6f);
        if (which == 0) s *= 0.08838834764831845f;
        float* dst = (which ? kn : qn) + (size_t)t * 2048 + hh * 128;
#pragma unroll
        for (int j = 0; j < 4; j++) {
            int c = cl + j;
            dst[((c & 15) << 3) + (c >> 4)] = v[j] * s;
        }
    } else {
        int i = (b - 16384) * 256 + threadIdx.x;
        int t = i >> 5, hh = i & 31;
        float x  = big[(size_t)t * NPACK + OFF_A + hh] + dtb[hh];
        float sp = (x <= 20.f) ? log1pf(expf(x)) : x;
        egT[(size_t)hh * T_ + t] = expf(-expf(Alg[hh]) * sp);
        float xb = big[(size_t)t * NPACK + OFF_B2 + hh];
        btT[(size_t)hh * T_ + t] = 1.f / (1.f + expf(-xb));
    }
}

// one warp per (t, hk): qkd[hk][t] = qn_t . kn_t
__global__ void qk_dot(const float* __restrict__ qn, const float* __restrict__ kn,
                       float* __restrict__ qkd)
{
    int wid  = (blockIdx.x * 256 + threadIdx.x) >> 5;   // 0..32767
    int lane = threadIdx.x & 31;
    int t = wid >> 4, hk = wid & 15;
    const float* qs = qn + (size_t)t * 2048 + hk * 128 + lane * 4;
    const float* ks = kn + (size_t)t * 2048 + hk * 128 + lane * 4;
    float4 a = *(const float4*)qs;
    float4 c = *(const float4*)ks;
    float d = a.x * c.x + a.y * c.y + a.z * c.z + a.w * c.w;
#pragma unroll
    for (int off = 16; off; off >>= 1) d += __shfl_xor_sync(0xffffffffu, d, off);
    if (lane == 0) qkd[(size_t)hk * T_ + t] = d;
}

// =====================================================================
// Gated delta-rule scan v3: f32x2 packed math + precomputed q.k.
// Grid (8 dv-tiles, 32 heads), 128 threads. lane = dkg*2+dvg.
// =====================================================================
__global__ __launch_bounds__(128) void gdn_scan(
    const float* __restrict__ qp, const float* __restrict__ kp,
    const float* __restrict__ acts, const float* __restrict__ egT,
    const float* __restrict__ btT, const float* __restrict__ qkd,
    float* __restrict__ o)
{
    const int h    = blockIdx.y;
    const int dvt  = blockIdx.x;
    const int hk   = h >> 1;
    const int tid  = threadIdx.x;
    const int w    = tid >> 5;
    const int lane = tid & 31;
    const int dkg  = lane >> 1;
    const int dvg  = lane & 1;

    __shared__ float sq[2][32][128];
    __shared__ float sk[2][32][128];
    __shared__ float sv[2][32][16];
    __shared__ float se[2][32];
    __shared__ float sb[2][32];
    __shared__ float sqk[2][32];

    auto fill = [&](int buf, int t0) {
#pragma unroll
        for (int it = 0; it < 8; it++) {
            int idx = it * 128 + tid;
            int tt = idx >> 5, f = (idx & 31) << 2;
            cp16(smem_u32(&sq[buf][tt][f]), qp + (size_t)(t0 + tt) * 2048 + hk * 128 + f);
            cp16(smem_u32(&sk[buf][tt][f]), kp + (size_t)(t0 + tt) * 2048 + hk * 128 + f);
        }
        {
            int tt = tid >> 2, f = (tid & 3) << 2;
            cp16(smem_u32(&sv[buf][tt][f]),
                 acts + (size_t)(t0 + tt) * 8192 + 4096 + h * 128 + dvt * 16 + f);
        }
        if (tid < 8)
            cp16(smem_u32(&se[buf][tid << 2]), egT + (size_t)h * T_ + t0 + (tid << 2));
        else if (tid < 16)
            cp16(smem_u32(&sb[buf][(tid - 8) << 2]), btT + (size_t)h * T_ + t0 + ((tid - 8) << 2));
        else if (tid < 24)
            cp16(smem_u32(&sqk[buf][(tid - 16) << 2]), qkd + (size_t)hk * T_ + t0 + ((tid - 16) << 2));
    };

    u64 S2[4][2];
#pragma unroll
    for (int i = 0; i < 4; i++) { S2[i][0] = 0ull; S2[i][1] = 0ull; }

    fill(0, 0); CP_COMMIT();

    for (int c = 0; c < 64; c++) {
        const int buf = c & 1;
        if (c + 1 < 64) { fill(buf ^ 1, (c + 1) << 5); CP_COMMIT(); CP_WAIT(1); }
        else            { CP_WAIT(0); }
        __syncthreads();
#pragma unroll 1
        for (int tt = 0; tt < 32; tt++) {
            ulonglong2 ku0 = *(const ulonglong2*)&sk[buf][tt][dkg << 3];
            ulonglong2 ku1 = *(const ulonglong2*)&sk[buf][tt][(dkg << 3) + 4];
            ulonglong2 qu0 = *(const ulonglong2*)&sq[buf][tt][dkg << 3];
            ulonglong2 qu1 = *(const ulonglong2*)&sq[buf][tt][(dkg << 3) + 4];
            u64 kf2[4] = {ku0.x, ku0.y, ku1.x, ku1.y};
            u64 qf2[4] = {qu0.x, qu0.y, qu1.x, qu1.y};
            float2 vv = *(const float2*)&sv[buf][tt][(w << 2) + (dvg << 1)];
            float e = se[buf][tt], bb = sb[buf][tt], qk = sqk[buf][tt];
            u64 kv0 = 0ull, kv1 = 0ull, oq0 = 0ull, oq1 = 0ull;
#pragma unroll
            for (int i = 0; i < 4; i++) {
                kv0 = f2fma(kf2[i], S2[i][0], kv0);
                kv1 = f2fma(kf2[i], S2[i][1], kv1);
                oq0 = f2fma(qf2[i], S2[i][0], oq0);
                oq1 = f2fma(qf2[i], S2[i][1], oq1);
            }
            float kv0s = f2hadd(kv0), kv1s = f2hadd(kv1);
            float oq0s = f2hadd(oq0), oq1s = f2hadd(oq1);
#pragma unroll
            for (int m = 2; m <= 16; m <<= 1) {
                kv0s += __shfl_xor_sync(0xffffffffu, kv0s, m);
                kv1s += __shfl_xor_sync(0xffffffffu, kv1s, m);
                oq0s += __shfl_xor_sync(0xffffffffu, oq0s, m);
                oq1s += __shfl_xor_sync(0xffffffffu, oq1s, m);
            }
            float d0 = bb * (vv.x - e * kv0s);
            float d1 = bb * (vv.y - e * kv1s);
            u64 e2 = f2b(e), d02 = f2b(d0), d12 = f2b(d1);
#pragma unroll
            for (int i = 0; i < 4; i++) {
                S2[i][0] = f2fma(S2[i][0], e2, f2mul(kf2[i], d02));
                S2[i][1] = f2fma(S2[i][1], e2, f2mul(kf2[i], d12));
            }
            if (dkg == 0) {
                float2 ov = make_float2(fmaf(qk, d0, e * oq0s), fmaf(qk, d1, e * oq1s));
                *(float2*)(o + (size_t)((c << 5) + tt) * 4096 + h * 128
                             + dvt * 16 + (w << 2) + (dvg << 1)) = ov;
            }
        }
        __syncthreads();
    }
}

// ================= gated RMSNorm + silu(gate), tf32-rounded =================
__global__ void gate_norm(const float* __restrict__ o, const float* __restrict__ big,
                          const float* __restrict__ wn, float* __restrict__ og)
{
    int wid  = (blockIdx.x * blockDim.x + threadIdx.x) >> 5;
    int lane = threadIdx.x & 31;
    int t = wid >> 5;
    int h = wid & 31;
    size_t base = (size_t)t * 4096 + h * 128 + lane * 4;
    float4 x = *(const float4*)(o + base);
    float ss = x.x * x.x + x.y * x.y + x.z * x.z + x.w * x.w;
#pragma unroll
    for (int off = 16; off; off >>= 1) ss += __shfl_xor_sync(0xffffffffu, ss, off);
    float r = rsqrtf(ss * (1.f / 128.f) + 1e-5f);
    float4 gv = *(const float4*)(big + (size_t)t * NPACK + OFF_G + h * 128 + lane * 4);
    float4 wv = *(const float4*)(wn + lane * 4);
    float4 out;
    out.x = tf32r(x.x * r * wv.x * (gv.x / (1.f + expf(-gv.x))));
    out.y = tf32r(x.y * r * wv.y * (gv.y / (1.f + expf(-gv.y))));
    out.z = tf32r(x.z * r * wv.z * (gv.z / (1.f + expf(-gv.z))));
    out.w = tf32r(x.w * r * wv.w * (gv.w / (1.f + expf(-gv.w))));
    *(float4*)(og + base) = out;
}

// =====================================================================
extern "C" void kernel_launch(void* const* d_in, const int* in_sizes, int n_in,
                              void* d_out, int out_size)
{
    const float* h   = (const float*)d_in[0];
    const float* Wq  = (const float*)d_in[1];
    const float* Wk  = (const float*)d_in[2];
    const float* Wv  = (const float*)d_in[3];
    const float* Wa  = (const float*)d_in[4];
    const float* Wb  = (const float*)d_in[5];
    const float* Wg  = (const float*)d_in[6];
    const float* cq  = (const float*)d_in[7];
    const float* ck  = (const float*)d_in[8];
    const float* cv  = (const float*)d_in[9];
    const float* dtb = (const float*)d_in[10];
    const float* Alg = (const float*)d_in[11];
    const float* onw = (const float*)d_in[12];
    const float* Wo  = (const float*)d_in[13];
    float* out = (float*)d_out;

    float *big, *Wp, *hr, *WoR, *acts, *egT, *btT, *qn, *kn, *qkd, *o, *og;
    cudaGetSymbolAddress((void**)&big,  g_big);
    cudaGetSymbolAddress((void**)&Wp,   g_Wp);
    cudaGetSymbolAddress((void**)&hr,   g_hr);
    cudaGetSymbolAddress((void**)&WoR,  g_WoR);
    cudaGetSymbolAddress((void**)&acts, g_acts);
    cudaGetSymbolAddress((void**)&egT,  g_egT);
    cudaGetSymbolAddress((void**)&btT,  g_btT);
    cudaGetSymbolAddress((void**)&qn,   g_qn);
    cudaGetSymbolAddress((void**)&kn,   g_kn);
    cudaGetSymbolAddress((void**)&qkd,  g_qkd);
    cudaGetSymbolAddress((void**)&o,    g_o);
    cudaGetSymbolAddress((void**)&og,   g_og);

    cudaFuncSetAttribute(mma_gemm, cudaFuncAttributeMaxDynamicSharedMemorySize, GEMM_SMEM);

    round_copy<<<(2048 * 2048 / 4) / 256, 256>>>(h, hr);
    pack_w<<<2048 * 3136 / 256, 256>>>(Wq, Wk, Wv, Wg, Wa, Wb, Wp);

    mma_gemm<<<dim3(8, 98), 512, GEMM_SMEM>>>(hr, Wp, big, 2048, NPACK, NPACK);

    conv_norm<<<16640, 256>>>(big, cq, ck, cv, dtb, Alg, acts, egT, btT, qn, kn);
    qk_dot<<<4096, 256>>>(qn, kn, qkd);
    gdn_scan<<<dim3(8, 32), 128>>>(qn, kn, acts, egT, btT, qkd, o);
    gate_norm<<<8192, 256>>>(o, big, onw, og);

    round_copy<<<(4096 * 2048 / 4) / 256, 256>>>(Wo, WoR);
    mma_gemm<<<dim3(8, 16), 512, GEMM_SMEM>>>(og, WoR, out, 4096, 2048, 2048);
}

// round 11
// speedup vs baseline: 3.6601x; 1.0026x over previous
#include <cuda_runtime.h>
#include <math.h>
#include <cstdint>

static constexpr int T_   = 2048;
static constexpr int NH   = 32;
static constexpr int NPACK = 12544;
static constexpr int OFF_K = 2048;
static constexpr int OFF_V = 4096;
static constexpr int OFF_G = 8192;
static constexpr int OFF_A = 12288;
static constexpr int OFF_B2 = 12320;
static constexpr int OFF_END = 12352;

__device__ float g_big [T_ * NPACK];
__device__ float g_Wp  [2048 * NPACK];
__device__ float g_hr  [T_ * 2048];
__device__ float g_WoR [4096 * 2048];
__device__ float g_acts[T_ * 8192];    // only v region [4096,8192) used
__device__ float g_egT [NH * T_];
__device__ float g_btT [NH * T_];
__device__ float g_qn  [T_ * 2048];    // l2-normed q, dk-permuted rows
__device__ float g_kn  [T_ * 2048];
__device__ float g_qkd [16 * T_];      // q_t . k_t  [hk][t]
__device__ float g_o   [T_ * 4096];
__device__ float g_og  [T_ * 4096];

__device__ __forceinline__ float tf32r(float x) {
    uint32_t u;
    asm("cvt.rna.tf32.f32 %0, %1;" : "=r"(u) : "f"(x));
    return __uint_as_float(u);
}
__device__ __forceinline__ uint32_t smem_u32(const void* p) {
    uint32_t a;
    asm("{ .reg .u64 t; cvta.to.shared.u64 t, %1; cvt.u32.u64 %0, t; }" : "=r"(a) : "l"(p));
    return a;
}
__device__ __forceinline__ void cp16(uint32_t dst, const void* src) {
    asm volatile("cp.async.cg.shared.global [%0], [%1], 16;" :: "r"(dst), "l"(src));
}
#define CP_COMMIT() asm volatile("cp.async.commit_group;" ::: "memory")
#define CP_WAIT(n)  asm volatile("cp.async.wait_group %0;" :: "n"(n) : "memory")

__device__ __forceinline__ uint32_t lds32(uint32_t a) {
    uint32_t v;
    asm volatile("ld.shared.b32 %0, [%1];" : "=r"(v) : "r"(a));
    return v;
}
__device__ __forceinline__ void mma_tf32(float* c, const uint32_t* a, const uint32_t* b) {
    asm volatile("mma.sync.aligned.m16n8k8.row.col.f32.tf32.tf32.f32 "
        "{%0,%1,%2,%3}, {%4,%5,%6,%7}, {%8,%9}, {%0,%1,%2,%3};"
        : "+f"(c[0]), "+f"(c[1]), "+f"(c[2]), "+f"(c[3])
        : "r"(a[0]), "r"(a[1]), "r"(a[2]), "r"(a[3]), "r"(b[0]), "r"(b[1]));
}

// ---- packed f32x2 helpers (sm_100+ base ISA) ----
typedef unsigned long long u64;
__device__ __forceinline__ u64 f2b(float x) {
    u64 r; asm("mov.b64 %0, {%1, %1};" : "=l"(r) : "f"(x)); return r;
}
__device__ __forceinline__ float f2hadd(u64 v) {
    float a, b; asm("mov.b64 {%0, %1}, %2;" : "=f"(a), "=f"(b) : "l"(v)); return a + b;
}
__device__ __forceinline__ u64 f2fma(u64 a, u64 b, u64 c) {
    u64 d; asm("fma.rn.f32x2 %0, %1, %2, %3;" : "=l"(d) : "l"(a), "l"(b), "l"(c)); return d;
}
__device__ __forceinline__ u64 f2mul(u64 a, u64 b) {
    u64 d; asm("mul.rn.f32x2 %0, %1, %2;" : "=l"(d) : "l"(a), "l"(b)); return d;
}

// ================= tf32 mma.sync GEMM, 4-stage cp.async =================
static constexpr uint32_t STAGE = 49152;
static constexpr uint32_t GEMM_SMEM = 4 * STAGE;   // 192KB

__global__ __launch_bounds__(512, 1) void mma_gemm(
    const float* __restrict__ A, const float* __restrict__ B, float* __restrict__ C,
    int K, int ldb, int ldc)
{
    extern __shared__ char smem[];
    const uint32_t sbase = smem_u32(smem);
    const int tid  = threadIdx.x;
    const int lane = tid & 31;
    const int w    = tid >> 5;
    const int wm   = w >> 2;
    const int wn   = w & 3;
    const int c4   = lane & 3;
    const int g    = lane >> 2;
    const int row0 = blockIdx.x * 256;
    const int col0 = blockIdx.y * 128;

    float acc[4][4][4];
#pragma unroll
    for (int mi = 0; mi < 4; mi++)
#pragma unroll
        for (int ni = 0; ni < 4; ni++)
#pragma unroll
            for (int q = 0; q < 4; q++) acc[mi][ni][q] = 0.f;

    const int nt = K >> 5;

    auto issue = [&](int t, int st) {
        const int k0 = t << 5;
        const uint32_t sA = sbase + st * STAGE;
        const uint32_t sB = sA + 32768;
#pragma unroll
        for (int it = 0; it < 4; it++) {
            int idx = it * 512 + tid;
            int r = idx >> 3, f = idx & 7;
            cp16(sA + r * 128 + ((f ^ (r & 7)) << 4),
                 A + (size_t)(row0 + r) * K + k0 + f * 4);
        }
#pragma unroll
        for (int it = 0; it < 2; it++) {
            int idx = it * 512 + tid;
            int k = idx >> 5, c = idx & 31;
            cp16(sB + k * 512 + ((c ^ ((k & 3) << 1)) << 4),
                 B + (size_t)(k0 + k) * ldb + col0 + c * 4);
        }
    };

    auto compute = [&](int st) {
        const uint32_t sA = sbase + st * STAGE;
        const uint32_t sB = sA + 32768;
#pragma unroll
        for (int s = 0; s < 4; s++) {
            uint32_t af[4][4];
            uint32_t bf[4][2];
            const int f0 = 2 * s, f1 = 2 * s + 1;
#pragma unroll
            for (int mi = 0; mi < 4; mi++) {
                const int r = wm * 64 + mi * 16 + g;
                const uint32_t base = sA + r * 128 + c4 * 4;
                af[mi][0] = lds32(base + ((f0 ^ g) << 4));
                af[mi][1] = lds32(base + 8 * 128 + ((f0 ^ g) << 4));
                af[mi][2] = lds32(base + ((f1 ^ g) << 4));
                af[mi][3] = lds32(base + 8 * 128 + ((f1 ^ g) << 4));
            }
            const int kk = 8 * s + c4;
#pragma unroll
            for (int ni = 0; ni < 4; ni++) {
                const int n = wn * 32 + ni * 8 + g;
                const uint32_t boff = ((uint32_t)((n >> 2) ^ (c4 << 1)) << 4) + (n & 3) * 4;
                bf[ni][0] = lds32(sB + kk * 512 + boff);
                bf[ni][1] = lds32(sB + (kk + 4) * 512 + boff);
            }
#pragma unroll
            for (int mi = 0; mi < 4; mi++)
#pragma unroll
                for (int ni = 0; ni < 4; ni++)
                    mma_tf32(acc[mi][ni], af[mi], bf[ni]);
        }
    };

    issue(0, 0); CP_COMMIT();
    issue(1, 1); CP_COMMIT();
    issue(2, 2); CP_COMMIT();
    int st = 0;
    for (int t = 0; t < nt; t++) {
        if (t + 3 < nt) {
            CP_WAIT(2);
            __syncthreads();
            issue(t + 3, (st + 3) & 3);
            CP_COMMIT();
        } else {
            CP_WAIT(0);
            __syncthreads();
        }
        compute(st);
        st = (st + 1) & 3;
    }

#pragma unroll
    for (int mi = 0; mi < 4; mi++) {
        const int r0 = row0 + wm * 64 + mi * 16 + g;
#pragma unroll
        for (int ni = 0; ni < 4; ni++) {
            const int cc = col0 + wn * 32 + ni * 8 + 2 * c4;
            *(float2*)(C + (size_t)r0 * ldc + cc) =
                make_float2(acc[mi][ni][0], acc[mi][ni][1]);
            *(float2*)(C + (size_t)(r0 + 8) * ldc + cc) =
                make_float2(acc[mi][ni][2], acc[mi][ni][3]);
        }
    }
}

// ================= weight pack + rounding =================
__global__ void pack_w(const float* __restrict__ Wq, const float* __restrict__ Wk,
                       const float* __restrict__ Wv, const float* __restrict__ Wg,
                       const float* __restrict__ Wa, const float* __restrict__ Wb,
                       float* __restrict__ P)
{
    int idx = blockIdx.x * 256 + threadIdx.x;
    int k = idx / 3136;
    int n = (idx - k * 3136) * 4;
    float4 v = make_float4(0.f, 0.f, 0.f, 0.f);
    if      (n < OFF_K)   v = *(const float4*)(Wq + (size_t)k * 2048 + n);
    else if (n < OFF_V)   v = *(const float4*)(Wk + (size_t)k * 2048 + n - OFF_K);
    else if (n < OFF_G)   v = *(const float4*)(Wv + (size_t)k * 4096 + n - OFF_V);
    else if (n < OFF_A)   v = *(const float4*)(Wg + (size_t)k * 4096 + n - OFF_G);
    else if (n < OFF_B2)  v = *(const float4*)(Wa + (size_t)k * 32 + n - OFF_A);
    else if (n < OFF_END) v = *(const float4*)(Wb + (size_t)k * 32 + n - OFF_B2);
    v.x = tf32r(v.x); v.y = tf32r(v.y); v.z = tf32r(v.z); v.w = tf32r(v.w);
    *(float4*)(P + (size_t)k * NPACK + n) = v;
}

__global__ void round_copy(const float* __restrict__ src, float* __restrict__ dst)
{
    int i = (blockIdx.x * 256 + threadIdx.x) * 4;
    float4 v = *(const float4*)(src + i);
    v.x = tf32r(v.x); v.y = tf32r(v.y); v.z = tf32r(v.z); v.w = tf32r(v.w);
    *(float4*)(dst + i) = v;
}

// =====================================================================
// Fused: v-conv+SiLU; q/k conv+SiLU+l2norm+permute (direct to qn/kn);
// gate/beta. blocks [0,8192)=v, [8192,16384)=q/k warps, [16384,16640)=gate.
// =====================================================================
__global__ void conv_norm(const float* __restrict__ big,
                          const float* __restrict__ cq, const float* __restrict__ ck,
                          const float* __restrict__ cv, const float* __restrict__ dtb,
                          const float* __restrict__ Alg, float* __restrict__ acts,
                          float* __restrict__ egT, float* __restrict__ btT,
                          float* __restrict__ qn, float* __restrict__ kn)
{
    int b = blockIdx.x;
    float4 z = make_float4(0.f, 0.f, 0.f, 0.f);
    if (b < 8192) {
        int gid = b * 256 + threadIdx.x;
        int t = gid >> 10;
        int c = (gid & 1023) << 2;
        const float* wp = cv + c * 4;
        float4 w0 = *(const float4*)(wp + 0), w1 = *(const float4*)(wp + 4);
        float4 w2 = *(const float4*)(wp + 8), w3 = *(const float4*)(wp + 12);
        const float* xp = big + (size_t)t * NPACK + 4096 + c;
        float4 x3 = *(const float4*)xp;
        float4 x2 = (t >= 1) ? *(const float4*)(xp - NPACK)     : z;
        float4 x1 = (t >= 2) ? *(const float4*)(xp - 2 * NPACK) : z;
        float4 x0 = (t >= 3) ? *(const float4*)(xp - 3 * NPACK) : z;
        float4 o;
        o.x = w0.x * x0.x + w0.y * x1.x + w0.z * x2.x + w0.w * x3.x;
        o.y = w1.x * x0.y + w1.y * x1.y + w1.z * x2.y + w1.w * x3.y;
        o.z = w2.x * x0.z + w2.y * x1.z + w2.z * x2.z + w2.w * x3.z;
        o.w = w3.x * x0.w + w3.y * x1.w + w3.z * x2.w + w3.w * x3.w;
        o.x = o.x / (1.f + expf(-o.x)); o.y = o.y / (1.f + expf(-o.y));
        o.z = o.z / (1.f + expf(-o.z)); o.w = o.w / (1.f + expf(-o.w));
        *(float4*)(acts + (size_t)t * 8192 + 4096 + c) = o;
    } else if (b < 16384) {
        int gw   = (b - 8192) * 8 + (threadIdx.x >> 5);
        int lane = threadIdx.x & 31;
        int t     = gw >> 5;
        int rest  = gw & 31;
        int which = rest & 1;
        int hh    = rest >> 1;
        int cl    = lane * 4;
        const float* wp = (which ? ck : cq) + (hh * 128 + cl) * 4;
        float4 w0 = *(const float4*)(wp + 0), w1 = *(const float4*)(wp + 4);
        float4 w2 = *(const float4*)(wp + 8), w3 = *(const float4*)(wp + 12);
        const float* xp = big + (size_t)t * NPACK + which * 2048 + hh * 128 + cl;
        float4 x3 = *(const float4*)xp;
        float4 x2 = (t >= 1) ? *(const float4*)(xp - NPACK)     : z;
        float4 x1 = (t >= 2) ? *(const float4*)(xp - 2 * NPACK) : z;
        float4 x0 = (t >= 3) ? *(const float4*)(xp - 3 * NPACK) : z;
        float v[4];
        v[0] = w0.x * x0.x + w0.y * x1.x + w0.z * x2.x + w0.w * x3.x;
        v[1] = w1.x * x0.y + w1.y * x1.y + w1.z * x2.y + w1.w * x3.y;
        v[2] = w2.x * x0.z + w2.y * x1.z + w2.z * x2.z + w2.w * x3.z;
        v[3] = w3.x * x0.w + w3.y * x1.w + w3.z * x2.w + w3.w * x3.w;
#pragma unroll
        for (int j = 0; j < 4; j++) v[j] = v[j] / (1.f + expf(-v[j]));
        float ss = v[0] * v[0] + v[1] * v[1] + v[2] * v[2] + v[3] * v[3];
#pragma unroll
        for (int off = 16; off; off >>= 1) ss += __shfl_xor_sync(0xffffffffu, ss, off);
        float s = rsqrtf(ss + 1e-6f);
        if (which == 0) s *= 0.08838834764831845f;
        float* dst = (which ? kn : qn) + (size_t)t * 2048 + hh * 128;
#pragma unroll
        for (int j = 0; j < 4; j++) {
            int c = cl + j;
            dst[((c & 15) << 3) + (c >> 4)] = v[j] * s;
        }
    } else {
        int i = (b - 16384) * 256 + threadIdx.x;
        int t = i >> 5, hh = i & 31;
        float x  = big[(size_t)t * NPACK + OFF_A + hh] + dtb[hh];
        float sp = (x <= 20.f) ? log1pf(expf(x)) : x;
        egT[(size_t)hh * T_ + t] = expf(-expf(Alg[hh]) * sp);
        float xb = big[(size_t)t * NPACK + OFF_B2 + hh];
        btT[(size_t)hh * T_ + t] = 1.f / (1.f + expf(-xb));
    }
}

// one warp per (t, hk): qkd[hk][t] = qn_t . kn_t
__global__ void qk_dot(const float* __restrict__ qn, const float* __restrict__ kn,
                       float* __restrict__ qkd)
{
    int wid  = (blockIdx.x * 256 + threadIdx.x) >> 5;   // 0..32767
    int lane = threadIdx.x & 31;
    int t = wid >> 4, hk = wid & 15;
    const float* qs = qn + (size_t)t * 2048 + hk * 128 + lane * 4;
    const float* ks = kn + (size_t)t * 2048 + hk * 128 + lane * 4;
    float4 a = *(const float4*)qs;
    float4 c = *(const float4*)ks;
    float d = a.x * c.x + a.y * c.y + a.z * c.z + a.w * c.w;
#pragma unroll
    for (int off = 16; off; off >>= 1) d += __shfl_xor_sync(0xffffffffu, d, off);
    if (lane == 0) qkd[(size_t)hk * T_ + t] = d;
}

// =====================================================================
// Gated delta-rule scan v3: f32x2 packed math + precomputed q.k.
// Grid (8 dv-tiles, 32 heads), 128 threads. lane = dkg*2+dvg.
// =====================================================================
__global__ __launch_bounds__(128) void gdn_scan(
    const float* __restrict__ qp, const float* __restrict__ kp,
    const float* __restrict__ acts, const float* __restrict__ egT,
    const float* __restrict__ btT, const float* __restrict__ qkd,
    float* __restrict__ o)
{
    const int h    = blockIdx.y;
    const int dvt  = blockIdx.x;
    const int hk   = h >> 1;
    const int tid  = threadIdx.x;
    const int w    = tid >> 5;
    const int lane = tid & 31;
    const int dkg  = lane >> 1;
    const int dvg  = lane & 1;

    __shared__ float sq[2][32][128];
    __shared__ float sk[2][32][128];
    __shared__ float sv[2][32][16];
    __shared__ float se[2][32];
    __shared__ float sb[2][32];
    __shared__ float sqk[2][32];

    auto fill = [&](int buf, int t0) {
#pragma unroll
        for (int it = 0; it < 8; it++) {
            int idx = it * 128 + tid;
            int tt = idx >> 5, f = (idx & 31) << 2;
            cp16(smem_u32(&sq[buf][tt][f]), qp + (size_t)(t0 + tt) * 2048 + hk * 128 + f);
            cp16(smem_u32(&sk[buf][tt][f]), kp + (size_t)(t0 + tt) * 2048 + hk * 128 + f);
        }
        {
            int tt = tid >> 2, f = (tid & 3) << 2;
            cp16(smem_u32(&sv[buf][tt][f]),
                 acts + (size_t)(t0 + tt) * 8192 + 4096 + h * 128 + dvt * 16 + f);
        }
        if (tid < 8)
            cp16(smem_u32(&se[buf][tid << 2]), egT + (size_t)h * T_ + t0 + (tid << 2));
        else if (tid < 16)
            cp16(smem_u32(&sb[buf][(tid - 8) << 2]), btT + (size_t)h * T_ + t0 + ((tid - 8) << 2));
        else if (tid < 24)
            cp16(smem_u32(&sqk[buf][(tid - 16) << 2]), qkd + (size_t)hk * T_ + t0 + ((tid - 16) << 2));
    };

    u64 S2[4][2];
#pragma unroll
    for (int i = 0; i < 4; i++) { S2[i][0] = 0ull; S2[i][1] = 0ull; }

    fill(0, 0); CP_COMMIT();

    for (int c = 0; c < 64; c++) {
        const int buf = c & 1;
        if (c + 1 < 64) { fill(buf ^ 1, (c + 1) << 5); CP_COMMIT(); CP_WAIT(1); }
        else            { CP_WAIT(0); }
        __syncthreads();
#pragma unroll 1
        for (int tt = 0; tt < 32; tt++) {
            ulonglong2 ku0 = *(const ulonglong2*)&sk[buf][tt][dkg << 3];
            ulonglong2 ku1 = *(const ulonglong2*)&sk[buf][tt][(dkg << 3) + 4];
            ulonglong2 qu0 = *(const ulonglong2*)&sq[buf][tt][dkg << 3];
            ulonglong2 qu1 = *(const ulonglong2*)&sq[buf][tt][(dkg << 3) + 4];
            u64 kf2[4] = {ku0.x, ku0.y, ku1.x, ku1.y};
            u64 qf2[4] = {qu0.x, qu0.y, qu1.x, qu1.y};
            float2 vv = *(const float2*)&sv[buf][tt][(w << 2) + (dvg << 1)];
            float e = se[buf][tt], bb = sb[buf][tt], qk = sqk[buf][tt];
            u64 kv0 = 0ull, kv1 = 0ull, oq0 = 0ull, oq1 = 0ull;
#pragma unroll
            for (int i = 0; i < 4; i++) {
                kv0 = f2fma(kf2[i], S2[i][0], kv0);
                kv1 = f2fma(kf2[i], S2[i][1], kv1);
                oq0 = f2fma(qf2[i], S2[i][0], oq0);
                oq1 = f2fma(qf2[i], S2[i][1], oq1);
            }
            float kv0s = f2hadd(kv0), kv1s = f2hadd(kv1);
            float oq0s = f2hadd(oq0), oq1s = f2hadd(oq1);
#pragma unroll
            for (int m = 2; m <= 16; m <<= 1) {
                kv0s += __shfl_xor_sync(0xffffffffu, kv0s, m);
                kv1s += __shfl_xor_sync(0xffffffffu, kv1s, m);
                oq0s += __shfl_xor_sync(0xffffffffu, oq0s, m);
                oq1s += __shfl_xor_sync(0xffffffffu, oq1s, m);
            }
            float d0 = bb * (vv.x - e * kv0s);
            float d1 = bb * (vv.y - e * kv1s);
            u64 e2 = f2b(e), d02 = f2b(d0), d12 = f2b(d1);
#pragma unroll
            for (int i = 0; i < 4; i++) {
                S2[i][0] = f2fma(S2[i][0], e2, f2mul(kf2[i], d02));
                S2[i][1] = f2fma(S2[i][1], e2, f2mul(kf2[i], d12));
            }
            if (dkg == 0) {
                float2 ov = make_float2(fmaf(qk, d0, e * oq0s), fmaf(qk, d1, e * oq1s));
                *(float2*)(o + (size_t)((c << 5) + tt) * 4096 + h * 128
                             + dvt * 16 + (w << 2) + (dvg << 1)) = ov;
            }
        }
        __syncthreads();
    }
}

// ================= gated RMSNorm + silu(gate), tf32-rounded =================
__global__ void gate_norm(const float* __restrict__ o, const float* __restrict__ big,
                          const float* __restrict__ wn, float* __restrict__ og)
{
    int wid  = (blockIdx.x * blockDim.x + threadIdx.x) >> 5;
    int lane = threadIdx.x & 31;
    int t = wid >> 5;
    int h = wid & 31;
    size_t base = (size_t)t * 4096 + h * 128 + lane * 4;
    float4 x = *(const float4*)(o + base);
    float ss = x.x * x.x + x.y * x.y + x.z * x.z + x.w * x.w;
#pragma unroll
    for (int off = 16; off; off >>= 1) ss += __shfl_xor_sync(0xffffffffu, ss, off);
    float r = rsqrtf(ss * (1.f / 128.f) + 1e-5f);
    float4 gv = *(const float4*)(big + (size_t)t * NPACK + OFF_G + h * 128 + lane * 4);
    float4 wv = *(const float4*)(wn + lane * 4);
    float4 out;
    out.x = tf32r(x.x * r * wv.x * (gv.x / (1.f + expf(-gv.x))));
    out.y = tf32r(x.y * r * wv.y * (gv.y / (1.f + expf(-gv.y))));
    out.z = tf32r(x.z * r * wv.z * (gv.z / (1.f + expf(-gv.z))));
    out.w = tf32r(x.w * r * wv.w * (gv.w / (1.f + expf(-gv.w))));
    *(float4*)(og + base) = out;
}

// =====================================================================
extern "C" void kernel_launch(void* const* d_in, const int* in_sizes, int n_in,
                              void* d_out, int out_size)
{
    const float* h   = (const float*)d_in[0];
    const float* Wq  = (const float*)d_in[1];
    const float* Wk  = (const float*)d_in[2];
    const float* Wv  = (const float*)d_in[3];
    const float* Wa  = (const float*)d_in[4];
    const float* Wb  = (const float*)d_in[5];
    const float* Wg  = (const float*)d_in[6];
    const float* cq  = (const float*)d_in[7];
    const float* ck  = (const float*)d_in[8];
    const float* cv  = (const float*)d_in[9];
    const float* dtb = (const float*)d_in[10];
    const float* Alg = (const float*)d_in[11];
    const float* onw = (const float*)d_in[12];
    const float* Wo  = (const float*)d_in[13];
    float* out = (float*)d_out;

    float *big, *Wp, *hr, *WoR, *acts, *egT, *btT, *qn, *kn, *qkd, *o, *og;
    cudaGetSymbolAddress((void**)&big,  g_big);
    cudaGetSymbolAddress((void**)&Wp,   g_Wp);
    cudaGetSymbolAddress((void**)&hr,   g_hr);
    cudaGetSymbolAddress((void**)&WoR,  g_WoR);
    cudaGetSymbolAddress((void**)&acts, g_acts);
    cudaGetSymbolAddress((void**)&egT,  g_egT);
    cudaGetSymbolAddress((void**)&btT,  g_btT);
    cudaGetSymbolAddress((void**)&qn,   g_qn);
    cudaGetSymbolAddress((void**)&kn,   g_kn);
    cudaGetSymbolAddress((void**)&qkd,  g_qkd);
    cudaGetSymbolAddress((void**)&o,    g_o);
    cudaGetSymbolAddress((void**)&og,   g_og);

    cudaFuncSetAttribute(mma_gemm, cudaFuncAttributeMaxDynamicSharedMemorySize, GEMM_SMEM);

    round_copy<<<(2048 * 2048 / 4) / 256, 256>>>(h, hr);
    pack_w<<<2048 * 3136 / 256, 256>>>(Wq, Wk, Wv, Wg, Wa, Wb, Wp);

    mma_gemm<<<dim3(8, 98), 512, GEMM_SMEM>>>(hr, Wp, big, 2048, NPACK, NPACK);

    conv_norm<<<16640, 256>>>(big, cq, ck, cv, dtb, Alg, acts, egT, btT, qn, kn);
    qk_dot<<<4096, 256>>>(qn, kn, qkd);
    gdn_scan<<<dim3(8, 32), 128>>>(qn, kn, acts, egT, btT, qkd, o);
    gate_norm<<<8192, 256>>>(o, big, onw, og);

    round_copy<<<(4096 * 2048 / 4) / 256, 256>>>(Wo, WoR);
    mma_gemm<<<dim3(8, 16), 512, GEMM_SMEM>>>(og, WoR, out, 4096, 2048, 2048);
}

// round 12
// speedup vs baseline: 5.4665x; 1.4936x over previous
#include <cuda_runtime.h>
#include <cuda_fp16.h>
#include <math.h>
#include <cstdint>

static constexpr int T_   = 2048;
static constexpr int NH   = 32;
static constexpr int NPACK = 12544;
static constexpr int OFF_K = 2048;
static constexpr int OFF_V = 4096;
static constexpr int OFF_G = 8192;
static constexpr int OFF_A = 12288;
static constexpr int OFF_B2 = 12320;
static constexpr int OFF_END = 12352;

__device__ float  g_big [T_ * NPACK];
__device__ __half g_Wp  [2048 * NPACK];   // packed fp16 weights
__device__ __half g_hr  [T_ * 2048];      // fp16 h
__device__ __half g_WoR [4096 * 2048];    // fp16 Wo
__device__ __half g_og  [T_ * 4096];      // fp16 normed+gated
__device__ float  g_acts[T_ * 8192];      // only v region [4096,8192) used
__device__ float  g_egT [NH * T_];
__device__ float  g_btT [NH * T_];
__device__ float  g_qn  [T_ * 2048];      // l2-normed q, dk-permuted rows
__device__ float  g_kn  [T_ * 2048];
__device__ float  g_qkd [16 * T_];        // q_t . k_t  [hk][t]
__device__ float  g_o   [T_ * 4096];

__device__ __forceinline__ uint32_t smem_u32(const void* p) {
    uint32_t a;
    asm("{ .reg .u64 t; cvta.to.shared.u64 t, %1; cvt.u32.u64 %0, t; }" : "=r"(a) : "l"(p));
    return a;
}
__device__ __forceinline__ void cp16(uint32_t dst, const void* src) {
    asm volatile("cp.async.cg.shared.global [%0], [%1], 16;" :: "r"(dst), "l"(src));
}
#define CP_COMMIT() asm volatile("cp.async.commit_group;" ::: "memory")
#define CP_WAIT(n)  asm volatile("cp.async.wait_group %0;" :: "n"(n) : "memory")

__device__ __forceinline__ void ldsm_x4(uint32_t addr, uint32_t* r) {
    asm volatile("ldmatrix.sync.aligned.m8n8.x4.shared.b16 {%0,%1,%2,%3}, [%4];"
        : "=r"(r[0]), "=r"(r[1]), "=r"(r[2]), "=r"(r[3]) : "r"(addr));
}
__device__ __forceinline__ void ldsm_x2t(uint32_t addr, uint32_t* r) {
    asm volatile("ldmatrix.sync.aligned.m8n8.x2.trans.shared.b16 {%0,%1}, [%2];"
        : "=r"(r[0]), "=r"(r[1]) : "r"(addr));
}
__device__ __forceinline__ void mma_f16(float* c, const uint32_t* a, const uint32_t* b) {
    asm volatile("mma.sync.aligned.m16n8k16.row.col.f32.f16.f16.f32 "
        "{%0,%1,%2,%3}, {%4,%5,%6,%7}, {%8,%9}, {%0,%1,%2,%3};"
        : "+f"(c[0]), "+f"(c[1]), "+f"(c[2]), "+f"(c[3])
        : "r"(a[0]), "r"(a[1]), "r"(a[2]), "r"(a[3]), "r"(b[0]), "r"(b[1]));
}

// ---- packed f32x2 helpers (sm_100+ base ISA) ----
typedef unsigned long long u64;
__device__ __forceinline__ u64 f2b(float x) {
    u64 r; asm("mov.b64 %0, {%1, %1};" : "=l"(r) : "f"(x)); return r;
}
__device__ __forceinline__ float f2hadd(u64 v) {
    float a, b; asm("mov.b64 {%0, %1}, %2;" : "=f"(a), "=f"(b) : "l"(v)); return a + b;
}
__device__ __forceinline__ u64 f2fma(u64 a, u64 b, u64 c) {
    u64 d; asm("fma.rn.f32x2 %0, %1, %2, %3;" : "=l"(d) : "l"(a), "l"(b), "l"(c)); return d;
}
__device__ __forceinline__ u64 f2mul(u64 a, u64 b) {
    u64 d; asm("mul.rn.f32x2 %0, %1, %2;" : "=l"(d) : "l"(a), "l"(b)); return d;
}

// =====================================================================
// fp16 mma.sync GEMM: C[M,N] = A[M,K] @ B[K,N], A/B fp16, C fp32.
// CTA tile 256(M) x 128(N), BK=64, 512 threads (16 warps, 4x4),
// warp tile 64x32, m16n8k16. ldmatrix fragments, 4-stage cp.async.
// A smem: 256 rows x 128B (64 halves), chunk f at f^(r&7).
// B smem: 64 k-rows x 256B (128 halves), chunk cn at cn^(k&7).
// Stage = 32KB A + 16KB B = 48KB.
// =====================================================================
static constexpr uint32_t STAGE = 49152;
static constexpr uint32_t GEMM_SMEM = 4 * STAGE;   // 192KB

__global__ __launch_bounds__(512, 1) void mma_gemm(
    const __half* __restrict__ A, const __half* __restrict__ B, float* __restrict__ C,
    int K, int ldb, int ldc)
{
    extern __shared__ char smem[];
    const uint32_t sbase = smem_u32(smem);
    const int tid  = threadIdx.x;
    const int lane = tid & 31;
    const int w    = tid >> 5;
    const int wm   = w >> 2;
    const int wn   = w & 3;
    const int c4   = lane & 3;
    const int g    = lane >> 2;
    const int row0 = blockIdx.x * 256;
    const int col0 = blockIdx.y * 128;
    const int mA   = lane >> 3;        // ldmatrix matrix id
    const int iA   = lane & 7;         // ldmatrix row-in-matrix

    float acc[4][4][4];
#pragma unroll
    for (int mi = 0; mi < 4; mi++)
#pragma unroll
        for (int ni = 0; ni < 4; ni++)
#pragma unroll
            for (int q = 0; q < 4; q++) acc[mi][ni][q] = 0.f;

    const int nt = K >> 6;

    auto issue = [&](int t, int st) {
        const int k0 = t << 6;
        const uint32_t sA = sbase + st * STAGE;
        const uint32_t sB = sA + 32768;
#pragma unroll
        for (int it = 0; it < 4; it++) {
            int idx = it * 512 + tid;          // 0..2047 A chunks
            int r = idx >> 3, f = idx & 7;
            cp16(sA + r * 128 + (((uint32_t)(f ^ (r & 7))) << 4),
                 A + (size_t)(row0 + r) * K + k0 + f * 8);
        }
#pragma unroll
        for (int it = 0; it < 2; it++) {
            int idx = it * 512 + tid;          // 0..1023 B chunks
            int k = idx >> 4, cn = idx & 15;
            cp16(sB + k * 256 + (((uint32_t)(cn ^ (k & 7))) << 4),
                 B + (size_t)(k0 + k) * ldb + col0 + cn * 8);
        }
    };

    auto compute = [&](int st) {
        const uint32_t sA = sbase + st * STAGE;
        const uint32_t sB = sA + 32768;
#pragma unroll
        for (int s = 0; s < 4; s++) {          // 4 k-steps of 16
            uint32_t af[4][4];
            uint32_t bf[4][2];
#pragma unroll
            for (int mi = 0; mi < 4; mi++) {
                int row = wm * 64 + mi * 16 + iA + ((mA & 1) << 3);
                int f = 2 * s + (mA >> 1);
                ldsm_x4(sA + row * 128 + (((uint32_t)(f ^ (row & 7))) << 4), af[mi]);
            }
#pragma unroll
            for (int ni = 0; ni < 4; ni++) {
                int cn = 4 * wn + ni;
                int k = 16 * s + ((mA & 1) << 3) + iA;
                ldsm_x2t(sB + k * 256 + (((uint32_t)(cn ^ (k & 7))) << 4), bf[ni]);
            }
#pragma unroll
            for (int mi = 0; mi < 4; mi++)
#pragma unroll
                for (int ni = 0; ni < 4; ni++)
                    mma_f16(acc[mi][ni], af[mi], bf[ni]);
        }
    };

    issue(0, 0); CP_COMMIT();
    issue(1, 1); CP_COMMIT();
    issue(2, 2); CP_COMMIT();
    int st = 0;
    for (int t = 0; t < nt; t++) {
        if (t + 3 < nt) {
            CP_WAIT(2);
            __syncthreads();
            issue(t + 3, (st + 3) & 3);
            CP_COMMIT();
        } else {
            CP_WAIT(0);
            __syncthreads();
        }
        compute(st);
        st = (st + 1) & 3;
    }

#pragma unroll
    for (int mi = 0; mi < 4; mi++) {
        const int r0 = row0 + wm * 64 + mi * 16 + g;
#pragma unroll
        for (int ni = 0; ni < 4; ni++) {
            const int cc = col0 + wn * 32 + ni * 8 + 2 * c4;
            *(float2*)(C + (size_t)r0 * ldc + cc) =
                make_float2(acc[mi][ni][0], acc[mi][ni][1]);
            *(float2*)(C + (size_t)(r0 + 8) * ldc + cc) =
                make_float2(acc[mi][ni][2], acc[mi][ni][3]);
        }
    }
}

// ================= weight pack (fp16) =================
__global__ void pack_w(const float* __restrict__ Wq, const float* __restrict__ Wk,
                       const float* __restrict__ Wv, const float* __restrict__ Wg,
                       const float* __restrict__ Wa, const float* __restrict__ Wb,
                       __half* __restrict__ P)
{
    int idx = blockIdx.x * 256 + threadIdx.x;
    int k = idx / 3136;
    int n = (idx - k * 3136) * 4;
    float4 v = make_float4(0.f, 0.f, 0.f, 0.f);
    if      (n < OFF_K)   v = *(const float4*)(Wq + (size_t)k * 2048 + n);
    else if (n < OFF_V)   v = *(const float4*)(Wk + (size_t)k * 2048 + n - OFF_K);
    else if (n < OFF_G)   v = *(const float4*)(Wv + (size_t)k * 4096 + n - OFF_V);
    else if (n < OFF_A)   v = *(const float4*)(Wg + (size_t)k * 4096 + n - OFF_G);
    else if (n < OFF_B2)  v = *(const float4*)(Wa + (size_t)k * 32 + n - OFF_A);
    else if (n < OFF_END) v = *(const float4*)(Wb + (size_t)k * 32 + n - OFF_B2);
    __half* p = P + (size_t)k * NPACK + n;
    *(__half2*)(p + 0) = __floats2half2_rn(v.x, v.y);
    *(__half2*)(p + 2) = __floats2half2_rn(v.z, v.w);
}

// float -> fp16 copy
__global__ void half_copy(const float* __restrict__ src, __half* __restrict__ dst)
{
    int i = (blockIdx.x * 256 + threadIdx.x) * 4;
    float4 v = *(const float4*)(src + i);
    *(__half2*)(dst + i + 0) = __floats2half2_rn(v.x, v.y);
    *(__half2*)(dst + i + 2) = __floats2half2_rn(v.z, v.w);
}

// =====================================================================
// Fused: v-conv+SiLU; q/k conv+SiLU+l2norm+permute (direct to qn/kn);
// gate/beta. blocks [0,8192)=v, [8192,16384)=q/k warps, [16384,16640)=gate.
// =====================================================================
__global__ void conv_norm(const float* __restrict__ big,
                          const float* __restrict__ cq, const float* __restrict__ ck,
                          const float* __restrict__ cv, const float* __restrict__ dtb,
                          const float* __restrict__ Alg, float* __restrict__ acts,
                          float* __restrict__ egT, float* __restrict__ btT,
                          float* __restrict__ qn, float* __restrict__ kn)
{
    int b = blockIdx.x;
    float4 z = make_float4(0.f, 0.f, 0.f, 0.f);
    if (b < 8192) {
        int gid = b * 256 + threadIdx.x;
        int t = gid >> 10;
        int c = (gid & 1023) << 2;
        const float* wp = cv + c * 4;
        float4 w0 = *(const float4*)(wp + 0), w1 = *(const float4*)(wp + 4);
        float4 w2 = *(const float4*)(wp + 8), w3 = *(const float4*)(wp + 12);
        const float* xp = big + (size_t)t * NPACK + 4096 + c;
        float4 x3 = *(const float4*)xp;
        float4 x2 = (t >= 1) ? *(const float4*)(xp - NPACK)     : z;
        float4 x1 = (t >= 2) ? *(const float4*)(xp - 2 * NPACK) : z;
        float4 x0 = (t >= 3) ? *(const float4*)(xp - 3 * NPACK) : z;
        float4 o;
        o.x = w0.x * x0.x + w0.y * x1.x + w0.z * x2.x + w0.w * x3.x;
        o.y = w1.x * x0.y + w1.y * x1.y + w1.z * x2.y + w1.w * x3.y;
        o.z = w2.x * x0.z + w2.y * x1.z + w2.z * x2.z + w2.w * x3.z;
        o.w = w3.x * x0.w + w3.y * x1.w + w3.z * x2.w + w3.w * x3.w;
        o.x = o.x / (1.f + expf(-o.x)); o.y = o.y / (1.f + expf(-o.y));
        o.z = o.z / (1.f + expf(-o.z)); o.w = o.w / (1.f + expf(-o.w));
        *(float4*)(acts + (size_t)t * 8192 + 4096 + c) = o;
    } else if (b < 16384) {
        int gw   = (b - 8192) * 8 + (threadIdx.x >> 5);
        int lane = threadIdx.x & 31;
        int t     = gw >> 5;
        int rest  = gw & 31;
        int which = rest & 1;
        int hh    = rest >> 1;
        int cl    = lane * 4;
        const float* wp = (which ? ck : cq) + (hh * 128 + cl) * 4;
        float4 w0 = *(const float4*)(wp + 0), w1 = *(const float4*)(wp + 4);
        float4 w2 = *(const float4*)(wp + 8), w3 = *(const float4*)(wp + 12);
        const float* xp = big + (size_t)t * NPACK + which * 2048 + hh * 128 + cl;
        float4 x3 = *(const float4*)xp;
        float4 x2 = (t >= 1) ? *(const float4*)(xp - NPACK)     : z;
        float4 x1 = (t >= 2) ? *(const float4*)(xp - 2 * NPACK) : z;
        float4 x0 = (t >= 3) ? *(const float4*)(xp - 3 * NPACK) : z;
        float v[4];
        v[0] = w0.x * x0.x + w0.y * x1.x + w0.z * x2.x + w0.w * x3.x;
        v[1] = w1.x * x0.y + w1.y * x1.y + w1.z * x2.y + w1.w * x3.y;
        v[2] = w2.x * x0.z + w2.y * x1.z + w2.z * x2.z + w2.w * x3.z;
        v[3] = w3.x * x0.w + w3.y * x1.w + w3.z * x2.w + w3.w * x3.w;
#pragma unroll
        for (int j = 0; j < 4; j++) v[j] = v[j] / (1.f + expf(-v[j]));
        float ss = v[0] * v[0] + v[1] * v[1] + v[2] * v[2] + v[3] * v[3];
#pragma unroll
        for (int off = 16; off; off >>= 1) ss += __shfl_xor_sync(0xffffffffu, ss, off);
        float s = rsqrtf(ss + 1e-6f);
        if (which == 0) s *= 0.08838834764831845f;
        float* dst = (which ? kn : qn) + (size_t)t * 2048 + hh * 128;
#pragma unroll
        for (int j = 0; j < 4; j++) {
            int c = cl + j;
            dst[((c & 15) << 3) + (c >> 4)] = v[j] * s;
        }
    } else {
        int i = (b - 16384) * 256 + threadIdx.x;
        int t = i >> 5, hh = i & 31;
        float x  = big[(size_t)t * NPACK + OFF_A + hh] + dtb[hh];
        float sp = (x <= 20.f) ? log1pf(expf(x)) : x;
        egT[(size_t)hh * T_ + t] = expf(-expf(Alg[hh]) * sp);
        float xb = big[(size_t)t * NPACK + OFF_B2 + hh];
        btT[(size_t)hh * T_ + t] = 1.f / (1.f + expf(-xb));
    }
}

// one warp per (t, hk): qkd[hk][t] = qn_t . kn_t
__global__ void qk_dot(const float* __restrict__ qn, const float* __restrict__ kn,
                       float* __restrict__ qkd)
{
    int wid  = (blockIdx.x * 256 + threadIdx.x) >> 5;
    int lane = threadIdx.x & 31;
    int t = wid >> 4, hk = wid & 15;
    const float* qs = qn + (size_t)t * 2048 + hk * 128 + lane * 4;
    const float* ks = kn + (size_t)t * 2048 + hk * 128 + lane * 4;
    float4 a = *(const float4*)qs;
    float4 c = *(const float4*)ks;
    float d = a.x * c.x + a.y * c.y + a.z * c.z + a.w * c.w;
#pragma unroll
    for (int off = 16; off; off >>= 1) d += __shfl_xor_sync(0xffffffffu, d, off);
    if (lane == 0) qkd[(size_t)hk * T_ + t] = d;
}

// =====================================================================
// Gated delta-rule scan v3 (unchanged from R11).
// =====================================================================
__global__ __launch_bounds__(128) void gdn_scan(
    const float* __restrict__ qp, const float* __restrict__ kp,
    const float* __restrict__ acts, const float* __restrict__ egT,
    const float* __restrict__ btT, const float* __restrict__ qkd,
    float* __restrict__ o)
{
    const int h    = blockIdx.y;
    const int dvt  = blockIdx.x;
    const int hk   = h >> 1;
    const int tid  = threadIdx.x;
    const int w    = tid >> 5;
    const int lane = tid & 31;
    const int dkg  = lane >> 1;
    const int dvg  = lane & 1;

    __shared__ float sq[2][32][128];
    __shared__ float sk[2][32][128];
    __shared__ float sv[2][32][16];
    __shared__ float se[2][32];
    __shared__ float sb[2][32];
    __shared__ float sqk[2][32];

    auto fill = [&](int buf, int t0) {
#pragma unroll
        for (int it = 0; it < 8; it++) {
            int idx = it * 128 + tid;
            int tt = idx >> 5, f = (idx & 31) << 2;
            cp16(smem_u32(&sq[buf][tt][f]), qp + (size_t)(t0 + tt) * 2048 + hk * 128 + f);
            cp16(smem_u32(&sk[buf][tt][f]), kp + (size_t)(t0 + tt) * 2048 + hk * 128 + f);
        }
        {
            int tt = tid >> 2, f = (tid & 3) << 2;
            cp16(smem_u32(&sv[buf][tt][f]),
                 acts + (size_t)(t0 + tt) * 8192 + 4096 + h * 128 + dvt * 16 + f);
        }
        if (tid < 8)
            cp16(smem_u32(&se[buf][tid << 2]), egT + (size_t)h * T_ + t0 + (tid << 2));
        else if (tid < 16)
            cp16(smem_u32(&sb[buf][(tid - 8) << 2]), btT + (size_t)h * T_ + t0 + ((tid - 8) << 2));
        else if (tid < 24)
            cp16(smem_u32(&sqk[buf][(tid - 16) << 2]), qkd + (size_t)hk * T_ + t0 + ((tid - 16) << 2));
    };

    u64 S2[4][2];
#pragma unroll
    for (int i = 0; i < 4; i++) { S2[i][0] = 0ull; S2[i][1] = 0ull; }

    fill(0, 0); CP_COMMIT();

    for (int c = 0; c < 64; c++) {
        const int buf = c & 1;
        if (c + 1 < 64) { fill(buf ^ 1, (c + 1) << 5); CP_COMMIT(); CP_WAIT(1); }
        else            { CP_WAIT(0); }
        __syncthreads();
#pragma unroll 1
        for (int tt = 0; tt < 32; tt++) {
            ulonglong2 ku0 = *(const ulonglong2*)&sk[buf][tt][dkg << 3];
            ulonglong2 ku1 = *(const ulonglong2*)&sk[buf][tt][(dkg << 3) + 4];
            ulonglong2 qu0 = *(const ulonglong2*)&sq[buf][tt][dkg << 3];
            ulonglong2 qu1 = *(const ulonglong2*)&sq[buf][tt][(dkg << 3) + 4];
            u64 kf2[4] = {ku0.x, ku0.y, ku1.x, ku1.y};
            u64 qf2[4] = {qu0.x, qu0.y, qu1.x, qu1.y};
            float2 vv = *(const float2*)&sv[buf][tt][(w << 2) + (dvg << 1)];
            float e = se[buf][tt], bb = sb[buf][tt], qk = sqk[buf][tt];
            u64 kv0 = 0ull, kv1 = 0ull, oq0 = 0ull, oq1 = 0ull;
#pragma unroll
            for (int i = 0; i < 4; i++) {
                kv0 = f2fma(kf2[i], S2[i][0], kv0);
                kv1 = f2fma(kf2[i], S2[i][1], kv1);
                oq0 = f2fma(qf2[i], S2[i][0], oq0);
                oq1 = f2fma(qf2[i], S2[i][1], oq1);
            }
            float kv0s = f2hadd(kv0), kv1s = f2hadd(kv1);
            float oq0s = f2hadd(oq0), oq1s = f2hadd(oq1);
#pragma unroll
            for (int m = 2; m <= 16; m <<= 1) {
                kv0s += __shfl_xor_sync(0xffffffffu, kv0s, m);
                kv1s += __shfl_xor_sync(0xffffffffu, kv1s, m);
                oq0s += __shfl_xor_sync(0xffffffffu, oq0s, m);
                oq1s += __shfl_xor_sync(0xffffffffu, oq1s, m);
            }
            float d0 = bb * (vv.x - e * kv0s);
            float d1 = bb * (vv.y - e * kv1s);
            u64 e2 = f2b(e), d02 = f2b(d0), d12 = f2b(d1);
#pragma unroll
            for (int i = 0; i < 4; i++) {
                S2[i][0] = f2fma(S2[i][0], e2, f2mul(kf2[i], d02));
                S2[i][1] = f2fma(S2[i][1], e2, f2mul(kf2[i], d12));
            }
            if (dkg == 0) {
                float2 ov = make_float2(fmaf(qk, d0, e * oq0s), fmaf(qk, d1, e * oq1s));
                *(float2*)(o + (size_t)((c << 5) + tt) * 4096 + h * 128
                             + dvt * 16 + (w << 2) + (dvg << 1)) = ov;
            }
        }
        __syncthreads();
    }
}

// ============ gated RMSNorm + silu(gate), fp16 output ============
__global__ void gate_norm(const float* __restrict__ o, const float* __restrict__ big,
                          const float* __restrict__ wn, __half* __restrict__ og)
{
    int wid  = (blockIdx.x * blockDim.x + threadIdx.x) >> 5;
    int lane = threadIdx.x & 31;
    int t = wid >> 5;
    int h = wid & 31;
    size_t base = (size_t)t * 4096 + h * 128 + lane * 4;
    float4 x = *(const float4*)(o + base);
    float ss = x.x * x.x + x.y * x.y + x.z * x.z + x.w * x.w;
#pragma unroll
    for (int off = 16; off; off >>= 1) ss += __shfl_xor_sync(0xffffffffu, ss, off);
    float r = rsqrtf(ss * (1.f / 128.f) + 1e-5f);
    float4 gv = *(const float4*)(big + (size_t)t * NPACK + OFF_G + h * 128 + lane * 4);
    float4 wv = *(const float4*)(wn + lane * 4);
    float ox = x.x * r * wv.x * (gv.x / (1.f + expf(-gv.x)));
    float oy = x.y * r * wv.y * (gv.y / (1.f + expf(-gv.y)));
    float oz = x.z * r * wv.z * (gv.z / (1.f + expf(-gv.z)));
    float ow = x.w * r * wv.w * (gv.w / (1.f + expf(-gv.w)));
    *(__half2*)(og + base + 0) = __floats2half2_rn(ox, oy);
    *(__half2*)(og + base + 2) = __floats2half2_rn(oz, ow);
}

// =====================================================================
extern "C" void kernel_launch(void* const* d_in, const int* in_sizes, int n_in,
                              void* d_out, int out_size)
{
    const float* h   = (const float*)d_in[0];
    const float* Wq  = (const float*)d_in[1];
    const float* Wk  = (const float*)d_in[2];
    const float* Wv  = (const float*)d_in[3];
    const float* Wa  = (const float*)d_in[4];
    const float* Wb  = (const float*)d_in[5];
    const float* Wg  = (const float*)d_in[6];
    const float* cq  = (const float*)d_in[7];
    const float* ck  = (const float*)d_in[8];
    const float* cv  = (const float*)d_in[9];
    const float* dtb = (const float*)d_in[10];
    const float* Alg = (const float*)d_in[11];
    const float* onw = (const float*)d_in[12];
    const float* Wo  = (const float*)d_in[13];
    float* out = (float*)d_out;

    float *big, *acts, *egT, *btT, *qn, *kn, *qkd, *o;
    __half *Wp, *hr, *WoR, *og;
    cudaGetSymbolAddress((void**)&big,  g_big);
    cudaGetSymbolAddress((void**)&Wp,   g_Wp);
    cudaGetSymbolAddress((void**)&hr,   g_hr);
    cudaGetSymbolAddress((void**)&WoR,  g_WoR);
    cudaGetSymbolAddress((void**)&acts, g_acts);
    cudaGetSymbolAddress((void**)&egT,  g_egT);
    cudaGetSymbolAddress((void**)&btT,  g_btT);
    cudaGetSymbolAddress((void**)&qn,   g_qn);
    cudaGetSymbolAddress((void**)&kn,   g_kn);
    cudaGetSymbolAddress((void**)&qkd,  g_qkd);
    cudaGetSymbolAddress((void**)&o,    g_o);
    cudaGetSymbolAddress((void**)&og,   g_og);

    cudaFuncSetAttribute(mma_gemm, cudaFuncAttributeMaxDynamicSharedMemorySize, GEMM_SMEM);

    half_copy<<<(2048 * 2048 / 4) / 256, 256>>>(h, hr);
    pack_w<<<2048 * 3136 / 256, 256>>>(Wq, Wk, Wv, Wg, Wa, Wb, Wp);

    mma_gemm<<<dim3(8, 98), 512, GEMM_SMEM>>>(hr, Wp, big, 2048, NPACK, NPACK);

    conv_norm<<<16640, 256>>>(big, cq, ck, cv, dtb, Alg, acts, egT, btT, qn, kn);
    qk_dot<<<4096, 256>>>(qn, kn, qkd);
    gdn_scan<<<dim3(8, 32), 128>>>(qn, kn, acts, egT, btT, qkd, o);
    gate_norm<<<8192, 256>>>(o, big, onw, og);

    half_copy<<<(4096 * 2048 / 4) / 256, 256>>>(Wo, WoR);
    mma_gemm<<<dim3(8, 16), 512, GEMM_SMEM>>>(og, WoR, out, 4096, 2048, 2048);
}

// round 13
// speedup vs baseline: 5.4687x; 1.0004x over previous
#include <cuda_runtime.h>
#include <cuda_fp16.h>
#include <math.h>
#include <cstdint>

static constexpr int T_   = 2048;
static constexpr int NH   = 32;
static constexpr int NPACK = 12544;
static constexpr int OFF_K = 2048;
static constexpr int OFF_V = 4096;
static constexpr int OFF_G = 8192;
static constexpr int OFF_A = 12288;
static constexpr int OFF_B2 = 12320;
static constexpr int OFF_END = 12352;

__device__ float  g_big [T_ * NPACK];
__device__ __half g_Wp  [2048 * NPACK];   // packed fp16 weights
__device__ __half g_hr  [T_ * 2048];      // fp16 h
__device__ __half g_WoR [4096 * 2048];    // fp16 Wo
__device__ __half g_og  [T_ * 4096];      // fp16 normed+gated
__device__ float  g_acts[T_ * 8192];      // only v region [4096,8192) used
__device__ float  g_egT [NH * T_];
__device__ float  g_btT [NH * T_];
__device__ float  g_qn  [T_ * 2048];      // l2-normed q, dk-permuted rows
__device__ float  g_kn  [T_ * 2048];
__device__ float  g_qkd [16 * T_];        // q_t . k_t        [hk][t]
__device__ float  g_kkx [16 * 1024];      // k_{2p+1} . k_2p  [hk][p]
__device__ float  g_qkx [16 * 1024];      // q_{2p+1} . k_2p  [hk][p]
__device__ float  g_o   [T_ * 4096];

__device__ __forceinline__ uint32_t smem_u32(const void* p) {
    uint32_t a;
    asm("{ .reg .u64 t; cvta.to.shared.u64 t, %1; cvt.u32.u64 %0, t; }" : "=r"(a) : "l"(p));
    return a;
}
__device__ __forceinline__ void cp16(uint32_t dst, const void* src) {
    asm volatile("cp.async.cg.shared.global [%0], [%1], 16;" :: "r"(dst), "l"(src));
}
#define CP_COMMIT() asm volatile("cp.async.commit_group;" ::: "memory")
#define CP_WAIT(n)  asm volatile("cp.async.wait_group %0;" :: "n"(n) : "memory")

__device__ __forceinline__ void ldsm_x4(uint32_t addr, uint32_t* r) {
    asm volatile("ldmatrix.sync.aligned.m8n8.x4.shared.b16 {%0,%1,%2,%3}, [%4];"
        : "=r"(r[0]), "=r"(r[1]), "=r"(r[2]), "=r"(r[3]) : "r"(addr));
}
__device__ __forceinline__ void ldsm_x2t(uint32_t addr, uint32_t* r) {
    asm volatile("ldmatrix.sync.aligned.m8n8.x2.trans.shared.b16 {%0,%1}, [%2];"
        : "=r"(r[0]), "=r"(r[1]) : "r"(addr));
}
__device__ __forceinline__ void mma_f16(float* c, const uint32_t* a, const uint32_t* b) {
    asm volatile("mma.sync.aligned.m16n8k16.row.col.f32.f16.f16.f32 "
        "{%0,%1,%2,%3}, {%4,%5,%6,%7}, {%8,%9}, {%0,%1,%2,%3};"
        : "+f"(c[0]), "+f"(c[1]), "+f"(c[2]), "+f"(c[3])
        : "r"(a[0]), "r"(a[1]), "r"(a[2]), "r"(a[3]), "r"(b[0]), "r"(b[1]));
}

// ---- packed f32x2 helpers (sm_100+ base ISA) ----
typedef unsigned long long u64;
__device__ __forceinline__ u64 f2b(float x) {
    u64 r; asm("mov.b64 %0, {%1, %1};" : "=l"(r) : "f"(x)); return r;
}
__device__ __forceinline__ float f2hadd(u64 v) {
    float a, b; asm("mov.b64 {%0, %1}, %2;" : "=f"(a), "=f"(b) : "l"(v)); return a + b;
}
__device__ __forceinline__ u64 f2fma(u64 a, u64 b, u64 c) {
    u64 d; asm("fma.rn.f32x2 %0, %1, %2, %3;" : "=l"(d) : "l"(a), "l"(b), "l"(c)); return d;
}
__device__ __forceinline__ u64 f2mul(u64 a, u64 b) {
    u64 d; asm("mul.rn.f32x2 %0, %1, %2;" : "=l"(d) : "l"(a), "l"(b)); return d;
}

// =====================================================================
// fp16 mma.sync GEMM (unchanged from R12, proven).
// =====================================================================
static constexpr uint32_t STAGE = 49152;
static constexpr uint32_t GEMM_SMEM = 4 * STAGE;   // 192KB

__global__ __launch_bounds__(512, 1) void mma_gemm(
    const __half* __restrict__ A, const __half* __restrict__ B, float* __restrict__ C,
    int K, int ldb, int ldc)
{
    extern __shared__ char smem[];
    const uint32_t sbase = smem_u32(smem);
    const int tid  = threadIdx.x;
    const int lane = tid & 31;
    const int w    = tid >> 5;
    const int wm   = w >> 2;
    const int wn   = w & 3;
    const int c4   = lane & 3;
    const int g    = lane >> 2;
    const int row0 = blockIdx.x * 256;
    const int col0 = blockIdx.y * 128;
    const int mA   = lane >> 3;
    const int iA   = lane & 7;

    float acc[4][4][4];
#pragma unroll
    for (int mi = 0; mi < 4; mi++)
#pragma unroll
        for (int ni = 0; ni < 4; ni++)
#pragma unroll
            for (int q = 0; q < 4; q++) acc[mi][ni][q] = 0.f;

    const int nt = K >> 6;

    auto issue = [&](int t, int st) {
        const int k0 = t << 6;
        const uint32_t sA = sbase + st * STAGE;
        const uint32_t sB = sA + 32768;
#pragma unroll
        for (int it = 0; it < 4; it++) {
            int idx = it * 512 + tid;
            int r = idx >> 3, f = idx & 7;
            cp16(sA + r * 128 + (((uint32_t)(f ^ (r & 7))) << 4),
                 A + (size_t)(row0 + r) * K + k0 + f * 8);
        }
#pragma unroll
        for (int it = 0; it < 2; it++) {
            int idx = it * 512 + tid;
            int k = idx >> 4, cn = idx & 15;
            cp16(sB + k * 256 + (((uint32_t)(cn ^ (k & 7))) << 4),
                 B + (size_t)(k0 + k) * ldb + col0 + cn * 8);
        }
    };

    auto compute = [&](int st) {
        const uint32_t sA = sbase + st * STAGE;
        const uint32_t sB = sA + 32768;
#pragma unroll
        for (int s = 0; s < 4; s++) {
            uint32_t af[4][4];
            uint32_t bf[4][2];
#pragma unroll
            for (int mi = 0; mi < 4; mi++) {
                int row = wm * 64 + mi * 16 + iA + ((mA & 1) << 3);
                int f = 2 * s + (mA >> 1);
                ldsm_x4(sA + row * 128 + (((uint32_t)(f ^ (row & 7))) << 4), af[mi]);
            }
#pragma unroll
            for (int ni = 0; ni < 4; ni++) {
                int cn = 4 * wn + ni;
                int k = 16 * s + ((mA & 1) << 3) + iA;
                ldsm_x2t(sB + k * 256 + (((uint32_t)(cn ^ (k & 7))) << 4), bf[ni]);
            }
#pragma unroll
            for (int mi = 0; mi < 4; mi++)
#pragma unroll
                for (int ni = 0; ni < 4; ni++)
                    mma_f16(acc[mi][ni], af[mi], bf[ni]);
        }
    };

    issue(0, 0); CP_COMMIT();
    issue(1, 1); CP_COMMIT();
    issue(2, 2); CP_COMMIT();
    int st = 0;
    for (int t = 0; t < nt; t++) {
        if (t + 3 < nt) {
            CP_WAIT(2);
            __syncthreads();
            issue(t + 3, (st + 3) & 3);
            CP_COMMIT();
        } else {
            CP_WAIT(0);
            __syncthreads();
        }
        compute(st);
        st = (st + 1) & 3;
    }

#pragma unroll
    for (int mi = 0; mi < 4; mi++) {
        const int r0 = row0 + wm * 64 + mi * 16 + g;
#pragma unroll
        for (int ni = 0; ni < 4; ni++) {
            const int cc = col0 + wn * 32 + ni * 8 + 2 * c4;
            *(float2*)(C + (size_t)r0 * ldc + cc) =
                make_float2(acc[mi][ni][0], acc[mi][ni][1]);
            *(float2*)(C + (size_t)(r0 + 8) * ldc + cc) =
                make_float2(acc[mi][ni][2], acc[mi][ni][3]);
        }
    }
}

// ================= weight pack (fp16) =================
__global__ void pack_w(const float* __restrict__ Wq, const float* __restrict__ Wk,
                       const float* __restrict__ Wv, const float* __restrict__ Wg,
                       const float* __restrict__ Wa, const float* __restrict__ Wb,
                       __half* __restrict__ P)
{
    int idx = blockIdx.x * 256 + threadIdx.x;
    int k = idx / 3136;
    int n = (idx - k * 3136) * 4;
    float4 v = make_float4(0.f, 0.f, 0.f, 0.f);
    if      (n < OFF_K)   v = *(const float4*)(Wq + (size_t)k * 2048 + n);
    else if (n < OFF_V)   v = *(const float4*)(Wk + (size_t)k * 2048 + n - OFF_K);
    else if (n < OFF_G)   v = *(const float4*)(Wv + (size_t)k * 4096 + n - OFF_V);
    else if (n < OFF_A)   v = *(const float4*)(Wg + (size_t)k * 4096 + n - OFF_G);
    else if (n < OFF_B2)  v = *(const float4*)(Wa + (size_t)k * 32 + n - OFF_A);
    else if (n < OFF_END) v = *(const float4*)(Wb + (size_t)k * 32 + n - OFF_B2);
    __half* p = P + (size_t)k * NPACK + n;
    *(__half2*)(p + 0) = __floats2half2_rn(v.x, v.y);
    *(__half2*)(p + 2) = __floats2half2_rn(v.z, v.w);
}

// float -> fp16 copy
__global__ void half_copy(const float* __restrict__ src, __half* __restrict__ dst)
{
    int i = (blockIdx.x * 256 + threadIdx.x) * 4;
    float4 v = *(const float4*)(src + i);
    *(__half2*)(dst + i + 0) = __floats2half2_rn(v.x, v.y);
    *(__half2*)(dst + i + 2) = __floats2half2_rn(v.z, v.w);
}

// =====================================================================
// Fused: v-conv+SiLU; q/k conv+SiLU+l2norm+permute; gate/beta (as R12).
// =====================================================================
__global__ void conv_norm(const float* __restrict__ big,
                          const float* __restrict__ cq, const float* __restrict__ ck,
                          const float* __restrict__ cv, const float* __restrict__ dtb,
                          const float* __restrict__ Alg, float* __restrict__ acts,
                          float* __restrict__ egT, float* __restrict__ btT,
                          float* __restrict__ qn, float* __restrict__ kn)
{
    int b = blockIdx.x;
    float4 z = make_float4(0.f, 0.f, 0.f, 0.f);
    if (b < 8192) {
        int gid = b * 256 + threadIdx.x;
        int t = gid >> 10;
        int c = (gid & 1023) << 2;
        const float* wp = cv + c * 4;
        float4 w0 = *(const float4*)(wp + 0), w1 = *(const float4*)(wp + 4);
        float4 w2 = *(const float4*)(wp + 8), w3 = *(const float4*)(wp + 12);
        const float* xp = big + (size_t)t * NPACK + 4096 + c;
        float4 x3 = *(const float4*)xp;
        float4 x2 = (t >= 1) ? *(const float4*)(xp - NPACK)     : z;
        float4 x1 = (t >= 2) ? *(const float4*)(xp - 2 * NPACK) : z;
        float4 x0 = (t >= 3) ? *(const float4*)(xp - 3 * NPACK) : z;
        float4 o;
        o.x = w0.x * x0.x + w0.y * x1.x + w0.z * x2.x + w0.w * x3.x;
        o.y = w1.x * x0.y + w1.y * x1.y + w1.z * x2.y + w1.w * x3.y;
        o.z = w2.x * x0.z + w2.y * x1.z + w2.z * x2.z + w2.w * x3.z;
        o.w = w3.x * x0.w + w3.y * x1.w + w3.z * x2.w + w3.w * x3.w;
        o.x = o.x / (1.f + expf(-o.x)); o.y = o.y / (1.f + expf(-o.y));
        o.z = o.z / (1.f + expf(-o.z)); o.w = o.w / (1.f + expf(-o.w));
        *(float4*)(acts + (size_t)t * 8192 + 4096 + c) = o;
    } else if (b < 16384) {
        int gw   = (b - 8192) * 8 + (threadIdx.x >> 5);
        int lane = threadIdx.x & 31;
        int t     = gw >> 5;
        int rest  = gw & 31;
        int which = rest & 1;
        int hh    = rest >> 1;
        int cl    = lane * 4;
        const float* wp = (which ? ck : cq) + (hh * 128 + cl) * 4;
        float4 w0 = *(const float4*)(wp + 0), w1 = *(const float4*)(wp + 4);
        float4 w2 = *(const float4*)(wp + 8), w3 = *(const float4*)(wp + 12);
        const float* xp = big + (size_t)t * NPACK + which * 2048 + hh * 128 + cl;
        float4 x3 = *(const float4*)xp;
        float4 x2 = (t >= 1) ? *(const float4*)(xp - NPACK)     : z;
        float4 x1 = (t >= 2) ? *(const float4*)(xp - 2 * NPACK) : z;
        float4 x0 = (t >= 3) ? *(const float4*)(xp - 3 * NPACK) : z;
        float v[4];
        v[0] = w0.x * x0.x + w0.y * x1.x + w0.z * x2.x + w0.w * x3.x;
        v[1] = w1.x * x0.y + w1.y * x1.y + w1.z * x2.y + w1.w * x3.y;
        v[2] = w2.x * x0.z + w2.y * x1.z + w2.z * x2.z + w2.w * x3.z;
        v[3] = w3.x * x0.w + w3.y * x1.w + w3.z * x2.w + w3.w * x3.w;
#pragma unroll
        for (int j = 0; j < 4; j++) v[j] = v[j] / (1.f + expf(-v[j]));
        float ss = v[0] * v[0] + v[1] * v[1] + v[2] * v[2] + v[3] * v[3];
#pragma unroll
        for (int off = 16; off; off >>= 1) ss += __shfl_xor_sync(0xffffffffu, ss, off);
        float s = rsqrtf(ss + 1e-6f);
        if (which == 0) s *= 0.08838834764831845f;
        float* dst = (which ? kn : qn) + (size_t)t * 2048 + hh * 128;
#pragma unroll
        for (int j = 0; j < 4; j++) {
            int c = cl + j;
            dst[((c & 15) << 3) + (c >> 4)] = v[j] * s;
        }
    } else {
        int i = (b - 16384) * 256 + threadIdx.x;
        int t = i >> 5, hh = i & 31;
        float x  = big[(size_t)t * NPACK + OFF_A + hh] + dtb[hh];
        float sp = (x <= 20.f) ? log1pf(expf(x)) : x;
        egT[(size_t)hh * T_ + t] = expf(-expf(Alg[hh]) * sp);
        float xb = big[(size_t)t * NPACK + OFF_B2 + hh];
        btT[(size_t)hh * T_ + t] = 1.f / (1.f + expf(-xb));
    }
}

// =====================================================================
// one warp per (pair p, hk): q_2p.k_2p, q_2p+1.k_2p+1, k_2p+1.k_2p,
// q_2p+1.k_2p  (dk-permutation is dot-invariant).
// =====================================================================
__global__ void qk_dot3(const float* __restrict__ qn, const float* __restrict__ kn,
                        float* __restrict__ qkd, float* __restrict__ kkx,
                        float* __restrict__ qkx)
{
    int wid  = (blockIdx.x * 256 + threadIdx.x) >> 5;   // 0..16383
    int lane = threadIdx.x & 31;
    int p = wid >> 4, hk = wid & 15;
    int t = p << 1;
    const float* qs = qn + (size_t)t * 2048 + hk * 128 + lane * 4;
    const float* ks = kn + (size_t)t * 2048 + hk * 128 + lane * 4;
    float4 q0 = *(const float4*)qs;
    float4 k0 = *(const float4*)ks;
    float4 q1 = *(const float4*)(qs + 2048);
    float4 k1 = *(const float4*)(ks + 2048);
    float r0 = q0.x * k0.x + q0.y * k0.y + q0.z * k0.z + q0.w * k0.w;
    float r1 = q1.x * k1.x + q1.y * k1.y + q1.z * k1.z + q1.w * k1.w;
    float r2 = k1.x * k0.x + k1.y * k0.y + k1.z * k0.z + k1.w * k0.w;
    float r3 = q1.x * k0.x + q1.y * k0.y + q1.z * k0.z + q1.w * k0.w;
#pragma unroll
    for (int off = 16; off; off >>= 1) {
        r0 += __shfl_xor_sync(0xffffffffu, r0, off);
        r1 += __shfl_xor_sync(0xffffffffu, r1, off);
        r2 += __shfl_xor_sync(0xffffffffu, r2, off);
        r3 += __shfl_xor_sync(0xffffffffu, r3, off);
    }
    if (lane == 0) {
        qkd[(size_t)hk * T_ + t]     = r0;
        qkd[(size_t)hk * T_ + t + 1] = r1;
        kkx[(size_t)hk * 1024 + p]   = r2;
        qkx[(size_t)hk * 1024 + p]   = r3;
    }
}

// =====================================================================
// Gated delta-rule scan v4: exact 2-step lookahead. All 8 reductions
// for a step-pair run against pair-start S0 in ONE butterfly phase.
// Grid (8 dv-tiles, 32 heads), 128 threads, lane = dkg*2+dvg.
// =====================================================================
__global__ __launch_bounds__(128) void gdn_scan(
    const float* __restrict__ qp, const float* __restrict__ kp,
    const float* __restrict__ acts, const float* __restrict__ egT,
    const float* __restrict__ btT, const float* __restrict__ qkd,
    const float* __restrict__ kkx, const float* __restrict__ qkx,
    float* __restrict__ o)
{
    const int h    = blockIdx.y;
    const int dvt  = blockIdx.x;
    const int hk   = h >> 1;
    const int tid  = threadIdx.x;
    const int w    = tid >> 5;
    const int lane = tid & 31;
    const int dkg  = lane >> 1;
    const int dvg  = lane & 1;

    __shared__ float sq[2][32][128];
    __shared__ float sk[2][32][128];
    __shared__ float sv[2][32][16];
    __shared__ float se[2][32];
    __shared__ float sb[2][32];
    __shared__ float sqk[2][32];
    __shared__ float skk[2][16];
    __shared__ float sqx[2][16];

    auto fill = [&](int buf, int t0) {
#pragma unroll
        for (int it = 0; it < 8; it++) {
            int idx = it * 128 + tid;
            int tt = idx >> 5, f = (idx & 31) << 2;
            cp16(smem_u32(&sq[buf][tt][f]), qp + (size_t)(t0 + tt) * 2048 + hk * 128 + f);
            cp16(smem_u32(&sk[buf][tt][f]), kp + (size_t)(t0 + tt) * 2048 + hk * 128 + f);
        }
        {
            int tt = tid >> 2, f = (tid & 3) << 2;
            cp16(smem_u32(&sv[buf][tt][f]),
                 acts + (size_t)(t0 + tt) * 8192 + 4096 + h * 128 + dvt * 16 + f);
        }
        if (tid < 8)
            cp16(smem_u32(&se[buf][tid << 2]), egT + (size_t)h * T_ + t0 + (tid << 2));
        else if (tid < 16)
            cp16(smem_u32(&sb[buf][(tid - 8) << 2]), btT + (size_t)h * T_ + t0 + ((tid - 8) << 2));
        else if (tid < 24)
            cp16(smem_u32(&sqk[buf][(tid - 16) << 2]), qkd + (size_t)hk * T_ + t0 + ((tid - 16) << 2));
        else if (tid < 28)
            cp16(smem_u32(&skk[buf][(tid - 24) << 2]), kkx + (size_t)hk * 1024 + (t0 >> 1) + ((tid - 24) << 2));
        else if (tid < 32)
            cp16(smem_u32(&sqx[buf][(tid - 28) << 2]), qkx + (size_t)hk * 1024 + (t0 >> 1) + ((tid - 28) << 2));
    };

    u64 S2[4][2];
#pragma unroll
    for (int i = 0; i < 4; i++) { S2[i][0] = 0ull; S2[i][1] = 0ull; }

    fill(0, 0); CP_COMMIT();

    for (int c = 0; c < 64; c++) {
        const int buf = c & 1;
        if (c + 1 < 64) { fill(buf ^ 1, (c + 1) << 5); CP_COMMIT(); CP_WAIT(1); }
        else            { CP_WAIT(0); }
        __syncthreads();
#pragma unroll 1
        for (int pp = 0; pp < 16; pp++) {
            const int tt = pp << 1;
            ulonglong2 a0, a1;
            a0 = *(const ulonglong2*)&sk[buf][tt][dkg << 3];
            a1 = *(const ulonglong2*)&sk[buf][tt][(dkg << 3) + 4];
            u64 kt[4]  = {a0.x, a0.y, a1.x, a1.y};
            a0 = *(const ulonglong2*)&sq[buf][tt][dkg << 3];
            a1 = *(const ulonglong2*)&sq[buf][tt][(dkg << 3) + 4];
            u64 qt[4]  = {a0.x, a0.y, a1.x, a1.y};
            a0 = *(const ulonglong2*)&sk[buf][tt + 1][dkg << 3];
            a1 = *(const ulonglong2*)&sk[buf][tt + 1][(dkg << 3) + 4];
            u64 kt1[4] = {a0.x, a0.y, a1.x, a1.y};
            a0 = *(const ulonglong2*)&sq[buf][tt + 1][dkg << 3];
            a1 = *(const ulonglong2*)&sq[buf][tt + 1][(dkg << 3) + 4];
            u64 qt1[4] = {a0.x, a0.y, a1.x, a1.y};
            float2 v0 = *(const float2*)&sv[buf][tt][(w << 2) + (dvg << 1)];
            float2 v1 = *(const float2*)&sv[buf][tt + 1][(w << 2) + (dvg << 1)];
            float e0 = se[buf][tt], e1 = se[buf][tt + 1];
            float b0 = sb[buf][tt], b1 = sb[buf][tt + 1];
            float qk0 = sqk[buf][tt], qk1 = sqk[buf][tt + 1];
            float kk = skk[buf][pp], qx = sqx[buf][pp];

            u64 kv1a = 0ull, kv1b = 0ull, kv2a = 0ull, kv2b = 0ull;
            u64 oq1a = 0ull, oq1b = 0ull, oq2a = 0ull, oq2b = 0ull;
#pragma unroll
            for (int i = 0; i < 4; i++) {
                kv1a = f2fma(kt[i],  S2[i][0], kv1a);
                kv1b = f2fma(kt[i],  S2[i][1], kv1b);
                kv2a = f2fma(kt1[i], S2[i][0], kv2a);
                kv2b = f2fma(kt1[i], S2[i][1], kv2b);
                oq1a = f2fma(qt[i],  S2[i][0], oq1a);
                oq1b = f2fma(qt[i],  S2[i][1], oq1b);
                oq2a = f2fma(qt1[i], S2[i][0], oq2a);
                oq2b = f2fma(qt1[i], S2[i][1], oq2b);
            }
            float r[8] = {f2hadd(kv1a), f2hadd(kv1b), f2hadd(kv2a), f2hadd(kv2b),
                          f2hadd(oq1a), f2hadd(oq1b), f2hadd(oq2a), f2hadd(oq2b)};
#pragma unroll
            for (int m = 2; m <= 16; m <<= 1) {
#pragma unroll
                for (int j = 0; j < 8; j++)
                    r[j] += __shfl_xor_sync(0xffffffffu, r[j], m);
            }
            // step t
            float d0 = b0 * (v0.x - e0 * r[0]);
            float d1 = b0 * (v0.y - e0 * r[1]);
            // step t+1 (lookahead via cross-dots)
            float dn0 = b1 * (v1.x - e1 * fmaf(kk, d0, e0 * r[2]));
            float dn1 = b1 * (v1.y - e1 * fmaf(kk, d1, e0 * r[3]));

            float ee = e0 * e1, ed0 = e1 * d0, ed1 = e1 * d1;
            u64 ee2 = f2b(ee), ed02 = f2b(ed0), ed12 = f2b(ed1);
            u64 dn02 = f2b(dn0), dn12 = f2b(dn1);
#pragma unroll
            for (int i = 0; i < 4; i++) {
                S2[i][0] = f2fma(S2[i][0], ee2, f2fma(kt1[i], dn02, f2mul(kt[i], ed02)));
                S2[i][1] = f2fma(S2[i][1], ee2, f2fma(kt1[i], dn12, f2mul(kt[i], ed12)));
            }
            if (dkg == 0) {
                float2 o0 = make_float2(fmaf(qk0, d0, e0 * r[4]),
                                        fmaf(qk0, d1, e0 * r[5]));
                float2 o1 = make_float2(fmaf(qk1, dn0, e1 * fmaf(qx, d0, e0 * r[6])),
                                        fmaf(qk1, dn1, e1 * fmaf(qx, d1, e0 * r[7])));
                size_t ob = (size_t)((c << 5) + tt) * 4096 + h * 128
                          + dvt * 16 + (w << 2) + (dvg << 1);
                *(float2*)(o + ob) = o0;
                *(float2*)(o + ob + 4096) = o1;
            }
        }
        __syncthreads();
    }
}

// ============ gated RMSNorm + silu(gate), fp16 output ============
__global__ void gate_norm(const float* __restrict__ o, const float* __restrict__ big,
                          const float* __restrict__ wn, __half* __restrict__ og)
{
    int wid  = (blockIdx.x * blockDim.x + threadIdx.x) >> 5;
    int lane = threadIdx.x & 31;
    int t = wid >> 5;
    int h = wid & 31;
    size_t base = (size_t)t * 4096 + h * 128 + lane * 4;
    float4 x = *(const float4*)(o + base);
    float ss = x.x * x.x + x.y * x.y + x.z * x.z + x.w * x.w;
#pragma unroll
    for (int off = 16; off; off >>= 1) ss += __shfl_xor_sync(0xffffffffu, ss, off);
    float r = rsqrtf(ss * (1.f / 128.f) + 1e-5f);
    float4 gv = *(const float4*)(big + (size_t)t * NPACK + OFF_G + h * 128 + lane * 4);
    float4 wv = *(const float4*)(wn + lane * 4);
    float ox = x.x * r * wv.x * (gv.x / (1.f + expf(-gv.x)));
    float oy = x.y * r * wv.y * (gv.y / (1.f + expf(-gv.y)));
    float oz = x.z * r * wv.z * (gv.z / (1.f + expf(-gv.z)));
    float ow = x.w * r * wv.w * (gv.w / (1.f + expf(-gv.w)));
    *(__half2*)(og + base + 0) = __floats2half2_rn(ox, oy);
    *(__half2*)(og + base + 2) = __floats2half2_rn(oz, ow);
}

// =====================================================================
extern "C" void kernel_launch(void* const* d_in, const int* in_sizes, int n_in,
                              void* d_out, int out_size)
{
    const float* h   = (const float*)d_in[0];
    const float* Wq  = (const float*)d_in[1];
    const float* Wk  = (const float*)d_in[2];
    const float* Wv  = (const float*)d_in[3];
    const float* Wa  = (const float*)d_in[4];
    const float* Wb  = (const float*)d_in[5];
    const float* Wg  = (const float*)d_in[6];
    const float* cq  = (const float*)d_in[7];
    const float* ck  = (const float*)d_in[8];
    const float* cv  = (const float*)d_in[9];
    const float* dtb = (const float*)d_in[10];
    const float* Alg = (const float*)d_in[11];
    const float* onw = (const float*)d_in[12];
    const float* Wo  = (const float*)d_in[13];
    float* out = (float*)d_out;

    float *big, *acts, *egT, *btT, *qn, *kn, *qkd, *kkx, *qkx, *o;
    __half *Wp, *hr, *WoR, *og;
    cudaGetSymbolAddress((void**)&big,  g_big);
    cudaGetSymbolAddress((void**)&Wp,   g_Wp);
    cudaGetSymbolAddress((void**)&hr,   g_hr);
    cudaGetSymbolAddress((void**)&WoR,  g_WoR);
    cudaGetSymbolAddress((void**)&acts, g_acts);
    cudaGetSymbolAddress((void**)&egT,  g_egT);
    cudaGetSymbolAddress((void**)&btT,  g_btT);
    cudaGetSymbolAddress((void**)&qn,   g_qn);
    cudaGetSymbolAddress((void**)&kn,   g_kn);
    cudaGetSymbolAddress((void**)&qkd,  g_qkd);
    cudaGetSymbolAddress((void**)&kkx,  g_kkx);
    cudaGetSymbolAddress((void**)&qkx,  g_qkx);
    cudaGetSymbolAddress((void**)&o,    g_o);
    cudaGetSymbolAddress((void**)&og,   g_og);

    cudaFuncSetAttribute(mma_gemm, cudaFuncAttributeMaxDynamicSharedMemorySize, GEMM_SMEM);

    half_copy<<<(2048 * 2048 / 4) / 256, 256>>>(h, hr);
    pack_w<<<2048 * 3136 / 256, 256>>>(Wq, Wk, Wv, Wg, Wa, Wb, Wp);

    mma_gemm<<<dim3(8, 98), 512, GEMM_SMEM>>>(hr, Wp, big, 2048, NPACK, NPACK);

    conv_norm<<<16640, 256>>>(big, cq, ck, cv, dtb, Alg, acts, egT, btT, qn, kn);
    qk_dot3<<<2048, 256>>>(qn, kn, qkd, kkx, qkx);
    gdn_scan<<<dim3(8, 32), 128>>>(qn, kn, acts, egT, btT, qkd, kkx, qkx, o);
    gate_norm<<<8192, 256>>>(o, big, onw, og);

    half_copy<<<(4096 * 2048 / 4) / 256, 256>>>(Wo, WoR);
    mma_gemm<<<dim3(8, 16), 512, GEMM_SMEM>>>(og, WoR, out, 4096, 2048, 2048);
}